// round 9
// baseline (speedup 1.0000x reference)
#include <cuda_runtime.h>
#include <cuda_bf16.h>
#include <math.h>
#include <cstdint>

// ---------------- problem constants ----------------
#define MROWS   8192        // B*S
#define DMODEL  1024
#define NHEAD   16
#define DHEAD   64
#define SEQ     2048
#define CTXROWS 308         // B*77
#define CTXLEN  77
#define CTXDIM  768
#define FFH     8192
#define FFHALF  4096

// weight buffer offsets (elements) inside g_wh / g_wl
#define OW_Q    0
#define OW_K    (1024*1024)
#define OW_V    (2*1024*1024)
#define OW_O1   (3*1024*1024)
#define OW_Q2   (4*1024*1024)
#define OW_O2   (5*1024*1024)
#define OW_FF1  (6*1024*1024)
#define OW_FF2  (14*1024*1024)
#define W_TOTAL (18*1024*1024)

// ---------------- scratch (static device globals; no runtime alloc) ----------------
__device__ float g_xa[MROWS * DMODEL];
__device__ float g_ctmp1[CTXROWS * DMODEL];
__device__ float g_ctmp2[CTXROWS * DMODEL];
__device__ __nv_bfloat16 g_wh[W_TOTAL];                  // all weights hi ([N,K])
__device__ __nv_bfloat16 g_wl[W_TOTAL];                  // all weights lo
__device__ __nv_bfloat16 g_hh[(size_t)MROWS * FFH];      // FF1 out hi
__device__ __nv_bfloat16 g_hl[(size_t)MROWS * FFH];      // FF1 out lo
__device__ __nv_bfloat16 g_ah[(size_t)MROWS * FFHALF];   // activation hi
__device__ __nv_bfloat16 g_al[(size_t)MROWS * FFHALF];   // activation lo
__device__ __nv_bfloat16 g_qh[MROWS * DMODEL];
__device__ __nv_bfloat16 g_ql[MROWS * DMODEL];
__device__ __nv_bfloat16 g_kh[MROWS * DMODEL];
__device__ __nv_bfloat16 g_kl[MROWS * DMODEL];
__device__ __nv_bfloat16 g_vh[MROWS * DMODEL];
__device__ __nv_bfloat16 g_vl[MROWS * DMODEL];
__device__ __nv_bfloat16 g_oh[MROWS * DMODEL];
__device__ __nv_bfloat16 g_ol[MROWS * DMODEL];

// ---------------- PTX helpers ----------------
__device__ __forceinline__ uint32_t smem_to_u32(const void* p) {
    uint32_t a;
    asm("{ .reg .u64 t; cvta.to.shared.u64 t, %1; cvt.u32.u64 %0, t; }" : "=r"(a) : "l"(p));
    return a;
}
#define CP_ASYNC16(dst, src) \
    asm volatile("cp.async.cg.shared.global [%0], [%1], 16;" :: "r"(dst), "l"(src))
#define CP_COMMIT() asm volatile("cp.async.commit_group;")
#define CP_WAIT0()  asm volatile("cp.async.wait_group 0;")
#define LDSM_X4(r0, r1, r2, r3, addr) \
    asm volatile("ldmatrix.sync.aligned.m8n8.x4.shared.b16 {%0,%1,%2,%3}, [%4];" \
        : "=r"(r0), "=r"(r1), "=r"(r2), "=r"(r3) : "r"(addr))
#define MMA16816(d, a, b0, b1) \
    asm volatile("mma.sync.aligned.m16n8k16.row.col.f32.bf16.bf16.f32 " \
        "{%0,%1,%2,%3}, {%4,%5,%6,%7}, {%8,%9}, {%0,%1,%2,%3};" \
        : "+f"((d)[0]), "+f"((d)[1]), "+f"((d)[2]), "+f"((d)[3]) \
        : "r"((a)[0]), "r"((a)[1]), "r"((a)[2]), "r"((a)[3]), "r"(b0), "r"(b1))

// ---------------- hi/lo split helpers ----------------
__device__ __forceinline__ void split_hilo(float x, __nv_bfloat16& h, __nv_bfloat16& l) {
    h = __float2bfloat16(x);
    l = __float2bfloat16(x - __bfloat162float(h));
}
__device__ __forceinline__ uint32_t pack_bf2(__nv_bfloat16 lo, __nv_bfloat16 hi) {
    __nv_bfloat162 t; t.x = lo; t.y = hi;
    return *(uint32_t*)&t;
}

// ---------------- fused LayerNorm + hi/lo emit ----------------
__global__ __launch_bounds__(256) void ln_hilo_kernel(const float* __restrict__ X,
                                                      const float* __restrict__ gma,
                                                      const float* __restrict__ bta,
                                                      __nv_bfloat16* __restrict__ Ho,
                                                      __nv_bfloat16* __restrict__ Lo) {
    int row = blockIdx.x;
    int tid = threadIdx.x;
    const float4* xr = (const float4*)(X + (size_t)row * DMODEL);
    float4 x4 = xr[tid];
    float s  = x4.x + x4.y + x4.z + x4.w;
    float ss = x4.x*x4.x + x4.y*x4.y + x4.z*x4.z + x4.w*x4.w;
#pragma unroll
    for (int off = 16; off > 0; off >>= 1) {
        s  += __shfl_xor_sync(0xffffffffu, s,  off);
        ss += __shfl_xor_sync(0xffffffffu, ss, off);
    }
    __shared__ float red[16];
    int lane = tid & 31, wid = tid >> 5;
    if (lane == 0) { red[wid] = s; red[8 + wid] = ss; }
    __syncthreads();
    float tot = 0.f, tot2 = 0.f;
#pragma unroll
    for (int i = 0; i < 8; i++) { tot += red[i]; tot2 += red[8 + i]; }
    const float inv = 1.0f / (float)DMODEL;
    float mu  = tot * inv;
    float var = tot2 * inv - mu * mu;
    float rs  = rsqrtf(var + 1e-5f);
    float4 gv = ((const float4*)gma)[tid];
    float4 bv = ((const float4*)bta)[tid];
    float o0 = (x4.x - mu) * rs * gv.x + bv.x;
    float o1 = (x4.y - mu) * rs * gv.y + bv.y;
    float o2 = (x4.z - mu) * rs * gv.z + bv.z;
    float o3 = (x4.w - mu) * rs * gv.w + bv.w;
    union { __nv_bfloat16 b[4]; uint2 u; } ph, pl;
    split_hilo(o0, ph.b[0], pl.b[0]);
    split_hilo(o1, ph.b[1], pl.b[1]);
    split_hilo(o2, ph.b[2], pl.b[2]);
    split_hilo(o3, ph.b[3], pl.b[3]);
    size_t base = (size_t)row * DMODEL + tid * 4;
    *(uint2*)(Ho + base) = ph.u;
    *(uint2*)(Lo + base) = pl.u;
}

// ---------------- elementwise fp32 -> bf16 hi/lo (ctx K/V path) ----------------
__global__ __launch_bounds__(256) void hilo_kernel(const float* __restrict__ X,
                                                   __nv_bfloat16* __restrict__ Ho,
                                                   __nv_bfloat16* __restrict__ Lo) {
    size_t idx = (size_t)blockIdx.x * 256 + threadIdx.x;
    float4 v = ((const float4*)X)[idx];
    union { __nv_bfloat16 b[4]; uint2 u; } ph, pl;
    split_hilo(v.x, ph.b[0], pl.b[0]);
    split_hilo(v.y, ph.b[1], pl.b[1]);
    split_hilo(v.z, ph.b[2], pl.b[2]);
    split_hilo(v.w, ph.b[3], pl.b[3]);
    *(uint2*)(Ho + idx * 4) = ph.u;
    *(uint2*)(Lo + idx * 4) = pl.u;
}

// ---------------- weight convert + transpose: W[K,N] fp32 -> Ht/Lt[N,K] bf16 ----------------
__global__ __launch_bounds__(256) void tconv_kernel(const float* __restrict__ W,
                                                    __nv_bfloat16* __restrict__ Ht,
                                                    __nv_bfloat16* __restrict__ Lt,
                                                    int K, int N) {
    __shared__ float s[32][33];
    int tx = threadIdx.x, ty = threadIdx.y;
    int n0 = blockIdx.x * 32, k0 = blockIdx.y * 32;
#pragma unroll
    for (int i = 0; i < 4; i++)
        s[ty + 8 * i][tx] = W[(size_t)(k0 + ty + 8 * i) * N + n0 + tx];
    __syncthreads();
#pragma unroll
    for (int i = 0; i < 4; i++) {
        int n = ty + 8 * i, k = tx;
        float v = s[k][n];
        __nv_bfloat16 h, l;
        split_hilo(v, h, l);
        size_t off = (size_t)(n0 + n) * K + k0 + k;
        Ht[off] = h;
        Lt[off] = l;
    }
}

// ---------------- bf16x3 GEMM via mma.sync: load-once / MMA-thrice ----------------
// C[M,N] = A @ Bt^T, terms AhBh + AhBl + AlBh accumulated per k-chunk.
// BM=BN=128, BK=32, 256 threads = 8 warps (2M x 4N). Stage = Ah|Al|Bh|Bl = 32KB, 2 stages.
#define GSTAGE 32768
#define GEMM_SMEM (2 * GSTAGE)

__global__ __launch_bounds__(256) void gemm_mma_kernel(const __nv_bfloat16* __restrict__ Ah,
                                                       const __nv_bfloat16* __restrict__ Al,
                                                       const __nv_bfloat16* __restrict__ Bh,
                                                       const __nv_bfloat16* __restrict__ Bl,
                                                       float* __restrict__ C,
                                                       int M, int N, int K,
                                                       const float* __restrict__ bias,
                                                       const float* __restrict__ resid,
                                                       __nv_bfloat16* __restrict__ CH,
                                                       __nv_bfloat16* __restrict__ CL) {
    extern __shared__ char gsm[];
    uint32_t sbase = smem_to_u32(gsm);
    int tid = threadIdx.x;
    int warp = tid >> 5, lane = tid & 31;
    int wm = (warp & 1) * 64, wn = (warp >> 1) * 32;
    int row0 = blockIdx.y * 128, col0 = blockIdx.x * 128;

    const int nk = K / 32;

    float acc[4][4][4];
#pragma unroll
    for (int mi = 0; mi < 4; mi++)
#pragma unroll
        for (int ni = 0; ni < 4; ni++)
#pragma unroll
            for (int e = 0; e < 4; e++) acc[mi][ni][e] = 0.f;

    auto load_stage = [&](int buf, int k0) {
        uint32_t so = sbase + buf * GSTAGE;
#pragma unroll
        for (int i = 0; i < 2; i++) {
            int lci = tid + i * 256;
            int r = lci >> 2, c = lci & 3;
            uint32_t doff = (uint32_t)(r * 64 + ((c ^ ((r >> 1) & 3)) * 16));
            size_t ga = (size_t)(row0 + r) * K + k0 + c * 8;
            size_t gb = (size_t)(col0 + r) * K + k0 + c * 8;
            CP_ASYNC16(so + doff,         Ah + ga);
            CP_ASYNC16(so + 8192 + doff,  Al + ga);
            CP_ASYNC16(so + 16384 + doff, Bh + gb);
            CP_ASYNC16(so + 24576 + doff, Bl + gb);
        }
    };

    load_stage(0, 0);
    CP_COMMIT();

    for (int it = 0; it < nk; it++) {
        int buf = it & 1;
        CP_WAIT0();
        __syncthreads();
        if (it + 1 < nk) {
            load_stage(buf ^ 1, (it + 1) * 32);
            CP_COMMIT();
        }
        uint32_t ah_s = sbase + buf * GSTAGE;
        uint32_t al_s = ah_s + 8192;
        uint32_t bh_s = ah_s + 16384;
        uint32_t bl_s = ah_s + 24576;
#pragma unroll
        for (int kk = 0; kk < 2; kk++) {
            int ar = wm + (lane & 15);
            int cidx = kk * 2 + (lane >> 4);
            uint32_t ahf[4][4], alf[4][4];
#pragma unroll
            for (int mi = 0; mi < 4; mi++) {
                int r = ar + mi * 16;
                uint32_t soff = (uint32_t)(r * 64 + ((cidx ^ ((r >> 1) & 3)) * 16));
                LDSM_X4(ahf[mi][0], ahf[mi][1], ahf[mi][2], ahf[mi][3], ah_s + soff);
                LDSM_X4(alf[mi][0], alf[mi][1], alf[mi][2], alf[mi][3], al_s + soff);
            }
            uint32_t bhf[2][4], blf[2][4];
#pragma unroll
            for (int nb = 0; nb < 2; nb++) {
                int r = wn + nb * 16 + (lane & 15);
                uint32_t soff = (uint32_t)(r * 64 + ((cidx ^ ((r >> 1) & 3)) * 16));
                LDSM_X4(bhf[nb][0], bhf[nb][1], bhf[nb][2], bhf[nb][3], bh_s + soff);
                LDSM_X4(blf[nb][0], blf[nb][1], blf[nb][2], blf[nb][3], bl_s + soff);
            }
#pragma unroll
            for (int mi = 0; mi < 4; mi++)
#pragma unroll
                for (int nb = 0; nb < 2; nb++) {
                    MMA16816(acc[mi][nb * 2 + 0], ahf[mi], bhf[nb][0], bhf[nb][2]);
                    MMA16816(acc[mi][nb * 2 + 1], ahf[mi], bhf[nb][1], bhf[nb][3]);
                    MMA16816(acc[mi][nb * 2 + 0], ahf[mi], blf[nb][0], blf[nb][2]);
                    MMA16816(acc[mi][nb * 2 + 1], ahf[mi], blf[nb][1], blf[nb][3]);
                    MMA16816(acc[mi][nb * 2 + 0], alf[mi], bhf[nb][0], bhf[nb][2]);
                    MMA16816(acc[mi][nb * 2 + 1], alf[mi], bhf[nb][1], bhf[nb][3]);
                }
        }
        __syncthreads();
    }

    // epilogue
    int grow = row0 + wm;
    int gcol = col0 + wn;
#pragma unroll
    for (int mi = 0; mi < 4; mi++)
#pragma unroll
        for (int ni = 0; ni < 4; ni++) {
            int r  = grow + mi * 16 + (lane >> 2);
            int cc = gcol + ni * 8 + (lane & 3) * 2;
            float2 v0 = make_float2(acc[mi][ni][0], acc[mi][ni][1]);
            float2 v1 = make_float2(acc[mi][ni][2], acc[mi][ni][3]);
            if (bias) {
                float2 b2 = *(const float2*)(bias + cc);
                v0.x += b2.x; v0.y += b2.y;
                v1.x += b2.x; v1.y += b2.y;
            }
            if (resid) {
                float2 r0 = *(const float2*)(resid + (size_t)r * N + cc);
                float2 r1 = *(const float2*)(resid + (size_t)(r + 8) * N + cc);
                v0.x += r0.x; v0.y += r0.y;
                v1.x += r1.x; v1.y += r1.y;
            }
            if (CH) {
                __nv_bfloat16 h0, l0, h1, l1;
                split_hilo(v0.x, h0, l0); split_hilo(v0.y, h1, l1);
                *(uint32_t*)(CH + (size_t)r * N + cc) = pack_bf2(h0, h1);
                *(uint32_t*)(CL + (size_t)r * N + cc) = pack_bf2(l0, l1);
                split_hilo(v1.x, h0, l0); split_hilo(v1.y, h1, l1);
                *(uint32_t*)(CH + (size_t)(r + 8) * N + cc) = pack_bf2(h0, h1);
                *(uint32_t*)(CL + (size_t)(r + 8) * N + cc) = pack_bf2(l0, l1);
            } else {
                *(float2*)(C + (size_t)r * N + cc) = v0;
                *(float2*)(C + (size_t)(r + 8) * N + cc) = v1;
            }
        }
}

// ---------------- fp32 GEMM (small ctx projections only) ----------------
__global__ __launch_bounds__(256) void gemm_kernel(const float* __restrict__ A,
                                                   const float* __restrict__ B,
                                                   float* __restrict__ C,
                                                   int M, int N, int K) {
    __shared__ float As[16][128];
    __shared__ float Bs[16][128];
    int tid = threadIdx.x;
    int tx = tid & 15, ty = tid >> 4;
    int row0 = blockIdx.y * 128, col0 = blockIdx.x * 128;
    float acc[8][8];
#pragma unroll
    for (int i = 0; i < 8; i++)
#pragma unroll
        for (int j = 0; j < 8; j++) acc[i][j] = 0.f;

    for (int k0 = 0; k0 < K; k0 += 16) {
#pragma unroll
        for (int i = 0; i < 2; i++) {
            int idx = tid * 2 + i;
            int r = idx >> 2, kc = idx & 3;
            int gr = row0 + r;
            float4 f = make_float4(0.f, 0.f, 0.f, 0.f);
            if (gr < M) f = *(const float4*)(A + (size_t)gr * K + k0 + kc * 4);
            As[kc * 4 + 0][r] = f.x;
            As[kc * 4 + 1][r] = f.y;
            As[kc * 4 + 2][r] = f.z;
            As[kc * 4 + 3][r] = f.w;
        }
#pragma unroll
        for (int i = 0; i < 2; i++) {
            int idx = tid * 2 + i;
            int kb = idx >> 5, nc = idx & 31;
            float4 f = *(const float4*)(B + (size_t)(k0 + kb) * N + col0 + nc * 4);
            *(float4*)&Bs[kb][nc * 4] = f;
        }
        __syncthreads();
#pragma unroll
        for (int kk = 0; kk < 16; kk++) {
            float a[8], bb[8];
            *(float4*)&a[0]  = *(float4*)&As[kk][ty * 8];
            *(float4*)&a[4]  = *(float4*)&As[kk][ty * 8 + 4];
            *(float4*)&bb[0] = *(float4*)&Bs[kk][tx * 4];
            *(float4*)&bb[4] = *(float4*)&Bs[kk][64 + tx * 4];
#pragma unroll
            for (int i = 0; i < 8; i++)
#pragma unroll
                for (int j = 0; j < 8; j++) acc[i][j] += a[i] * bb[j];
        }
        __syncthreads();
    }
#pragma unroll
    for (int i = 0; i < 8; i++) {
        int gr = row0 + ty * 8 + i;
        if (gr >= M) continue;
#pragma unroll
        for (int half = 0; half < 2; half++) {
            int gc = col0 + half * 64 + tx * 4;
            float4 r4;
            r4.x = acc[i][half * 4 + 0];
            r4.y = acc[i][half * 4 + 1];
            r4.z = acc[i][half * 4 + 2];
            r4.w = acc[i][half * 4 + 3];
            *(float4*)(C + (size_t)gr * N + gc) = r4;
        }
    }
}

// ---------------- MMA flash attention ----------------
#define AQ_H 0
#define AQ_L 16384
#define AK_H 32768
#define AK_L 40960
#define AV_H 49152
#define AV_L 57344
#define ATT_SMEM 65536

__device__ __forceinline__ uint32_t att_sw(int r, int c) {
    return (uint32_t)(r * 128 + ((c ^ (r & 7)) << 4));
}

__global__ __launch_bounds__(256) void attn_mma_kernel(
    const __nv_bfloat16* __restrict__ Qh, const __nv_bfloat16* __restrict__ Ql,
    const __nv_bfloat16* __restrict__ Kp_h, const __nv_bfloat16* __restrict__ Kp_l,
    const __nv_bfloat16* __restrict__ Vh, const __nv_bfloat16* __restrict__ Vl,
    __nv_bfloat16* __restrict__ Oh, __nv_bfloat16* __restrict__ Ol,
    int qlen, int kvlen)
{
    extern __shared__ char smc[];
    uint32_t sb = smem_to_u32(smc);
    int b = blockIdx.z, h = blockIdx.y, qt = blockIdx.x;
    int tid = threadIdx.x, warp = tid >> 5, lane = tid & 31;
    int qrow0 = qt * 128;
    size_t qbase  = ((size_t)b * qlen + qrow0) * DMODEL + h * DHEAD;
    size_t kvbase = ((size_t)b * kvlen) * DMODEL + h * DHEAD;

#pragma unroll
    for (int i = 0; i < 4; i++) {
        int idx = tid + i * 256;
        int r = idx >> 3, c = idx & 7;
        uint4 vh4 = *(const uint4*)(Qh + qbase + (size_t)r * DMODEL + c * 8);
        uint4 vl4 = *(const uint4*)(Ql + qbase + (size_t)r * DMODEL + c * 8);
        *(uint4*)(smc + AQ_H + att_sw(r, c)) = vh4;
        *(uint4*)(smc + AQ_L + att_sw(r, c)) = vl4;
    }
    __syncthreads();

    uint32_t qfh[4][4], qfl[4][4];
    {
        int r = warp * 16 + (lane & 15);
#pragma unroll
        for (int kk = 0; kk < 4; kk++) {
            int c = kk * 2 + (lane >> 4);
            LDSM_X4(qfh[kk][0], qfh[kk][1], qfh[kk][2], qfh[kk][3], sb + AQ_H + att_sw(r, c));
            LDSM_X4(qfl[kk][0], qfl[kk][1], qfl[kk][2], qfl[kk][3], sb + AQ_L + att_sw(r, c));
        }
    }

    float m_a = -1e30f, m_b = -1e30f, l_a = 0.f, l_b = 0.f;
    float acc_o[8][4];
#pragma unroll
    for (int t = 0; t < 8; t++)
#pragma unroll
        for (int e = 0; e < 4; e++) acc_o[t][e] = 0.f;

    int ntiles = (kvlen + 63) >> 6;
    for (int kt = 0; kt < ntiles; kt++) {
#pragma unroll
        for (int i = 0; i < 2; i++) {
            int idx = tid + i * 256;
            int r = idx >> 3, c = idx & 7;
            int kr = kt * 64 + r;
            uint4 kh4 = make_uint4(0, 0, 0, 0), kl4 = kh4;
            if (kr < kvlen) {
                kh4 = *(const uint4*)(Kp_h + kvbase + (size_t)kr * DMODEL + c * 8);
                kl4 = *(const uint4*)(Kp_l + kvbase + (size_t)kr * DMODEL + c * 8);
            }
            *(uint4*)(smc + AK_H + att_sw(r, c)) = kh4;
            *(uint4*)(smc + AK_L + att_sw(r, c)) = kl4;
        }
#pragma unroll
        for (int i = 0; i < 4; i++) {
            int idx = tid + i * 256;
            int r = idx >> 4, cg = idx & 15;
            int kr = kt * 64 + r;
            union { uint2 u; __nv_bfloat16 e[4]; } vhu, vlu;
            vhu.u = make_uint2(0, 0); vlu.u = make_uint2(0, 0);
            if (kr < kvlen) {
                vhu.u = *(const uint2*)(Vh + kvbase + (size_t)kr * DMODEL + cg * 4);
                vlu.u = *(const uint2*)(Vl + kvbase + (size_t)kr * DMODEL + cg * 4);
            }
#pragma unroll
            for (int j = 0; j < 4; j++) {
                int d = cg * 4 + j;
                uint32_t off = (uint32_t)(d * 128 + ((((r >> 3) ^ (d & 7))) << 4) + (r & 7) * 2);
                *(__nv_bfloat16*)(smc + AV_H + off) = vhu.e[j];
                *(__nv_bfloat16*)(smc + AV_L + off) = vlu.e[j];
            }
        }
        __syncthreads();

        float s[8][4];
#pragma unroll
        for (int t = 0; t < 8; t++)
#pragma unroll
            for (int e = 0; e < 4; e++) s[t][e] = 0.f;
#pragma unroll
        for (int kk = 0; kk < 4; kk++) {
#pragma unroll
            for (int nq = 0; nq < 4; nq++) {
                int r = nq * 16 + (lane & 15);
                int c = kk * 2 + (lane >> 4);
                uint32_t khf[4], klf[4];
                LDSM_X4(khf[0], khf[1], khf[2], khf[3], sb + AK_H + att_sw(r, c));
                LDSM_X4(klf[0], klf[1], klf[2], klf[3], sb + AK_L + att_sw(r, c));
                MMA16816(s[nq * 2 + 0], qfh[kk], khf[0], khf[2]);
                MMA16816(s[nq * 2 + 1], qfh[kk], khf[1], khf[3]);
                MMA16816(s[nq * 2 + 0], qfh[kk], klf[0], klf[2]);
                MMA16816(s[nq * 2 + 1], qfh[kk], klf[1], klf[3]);
                MMA16816(s[nq * 2 + 0], qfl[kk], khf[0], khf[2]);
                MMA16816(s[nq * 2 + 1], qfl[kk], khf[1], khf[3]);
            }
        }
        bool mtile = (kt == ntiles - 1) && (kvlen & 63);
#pragma unroll
        for (int t = 0; t < 8; t++)
#pragma unroll
            for (int e = 0; e < 4; e++) {
                float vv = s[t][e] * 0.125f;
                if (mtile) {
                    int col = kt * 64 + t * 8 + (lane & 3) * 2 + (e & 1);
                    if (col >= kvlen) vv = -1e30f;
                }
                s[t][e] = vv;
            }
        float mx_a = -1e30f, mx_b = -1e30f;
#pragma unroll
        for (int t = 0; t < 8; t++) {
            mx_a = fmaxf(mx_a, fmaxf(s[t][0], s[t][1]));
            mx_b = fmaxf(mx_b, fmaxf(s[t][2], s[t][3]));
        }
        mx_a = fmaxf(mx_a, __shfl_xor_sync(0xffffffffu, mx_a, 1));
        mx_a = fmaxf(mx_a, __shfl_xor_sync(0xffffffffu, mx_a, 2));
        mx_b = fmaxf(mx_b, __shfl_xor_sync(0xffffffffu, mx_b, 1));
        mx_b = fmaxf(mx_b, __shfl_xor_sync(0xffffffffu, mx_b, 2));
        float mn_a = fmaxf(m_a, mx_a), mn_b = fmaxf(m_b, mx_b);
        float al_a = __expf(m_a - mn_a), al_b = __expf(m_b - mn_b);
        m_a = mn_a; m_b = mn_b;
        float sum_a = 0.f, sum_b = 0.f;
#pragma unroll
        for (int t = 0; t < 8; t++) {
            s[t][0] = __expf(s[t][0] - m_a);
            s[t][1] = __expf(s[t][1] - m_a);
            s[t][2] = __expf(s[t][2] - m_b);
            s[t][3] = __expf(s[t][3] - m_b);
            sum_a += s[t][0] + s[t][1];
            sum_b += s[t][2] + s[t][3];
        }
        sum_a += __shfl_xor_sync(0xffffffffu, sum_a, 1);
        sum_a += __shfl_xor_sync(0xffffffffu, sum_a, 2);
        sum_b += __shfl_xor_sync(0xffffffffu, sum_b, 1);
        sum_b += __shfl_xor_sync(0xffffffffu, sum_b, 2);
        l_a = l_a * al_a + sum_a;
        l_b = l_b * al_b + sum_b;
#pragma unroll
        for (int t = 0; t < 8; t++) {
            acc_o[t][0] *= al_a; acc_o[t][1] *= al_a;
            acc_o[t][2] *= al_b; acc_o[t][3] *= al_b;
        }
#pragma unroll
        for (int kc = 0; kc < 4; kc++) {
            int t0 = kc * 2, t1 = t0 + 1;
            uint32_t pah[4], pal[4];
            {
                __nv_bfloat16 hb, lb, hb2, lb2;
                split_hilo(s[t0][0], hb, lb);  split_hilo(s[t0][1], hb2, lb2);
                pah[0] = pack_bf2(hb, hb2);    pal[0] = pack_bf2(lb, lb2);
                split_hilo(s[t0][2], hb, lb);  split_hilo(s[t0][3], hb2, lb2);
                pah[1] = pack_bf2(hb, hb2);    pal[1] = pack_bf2(lb, lb2);
                split_hilo(s[t1][0], hb, lb);  split_hilo(s[t1][1], hb2, lb2);
                pah[2] = pack_bf2(hb, hb2);    pal[2] = pack_bf2(lb, lb2);
                split_hilo(s[t1][2], hb, lb);  split_hilo(s[t1][3], hb2, lb2);
                pah[3] = pack_bf2(hb, hb2);    pal[3] = pack_bf2(lb, lb2);
            }
#pragma unroll
            for (int nd = 0; nd < 4; nd++) {
                int r = nd * 16 + (lane & 15);
                int c = kc * 2 + (lane >> 4);
                uint32_t vhf[4], vlf[4];
                LDSM_X4(vhf[0], vhf[1], vhf[2], vhf[3], sb + AV_H + att_sw(r, c));
                LDSM_X4(vlf[0], vlf[1], vlf[2], vlf[3], sb + AV_L + att_sw(r, c));
                MMA16816(acc_o[nd * 2 + 0], pah, vhf[0], vhf[2]);
                MMA16816(acc_o[nd * 2 + 1], pah, vhf[1], vhf[3]);
                MMA16816(acc_o[nd * 2 + 0], pah, vlf[0], vlf[2]);
                MMA16816(acc_o[nd * 2 + 1], pah, vlf[1], vlf[3]);
                MMA16816(acc_o[nd * 2 + 0], pal, vhf[0], vhf[2]);
                MMA16816(acc_o[nd * 2 + 1], pal, vhf[1], vhf[3]);
            }
        }
        __syncthreads();
    }

    float inv_a = 1.0f / l_a, inv_b = 1.0f / l_b;
    int row_a = qrow0 + warp * 16 + (lane >> 2);
    size_t ob = ((size_t)b * qlen) * DMODEL + h * DHEAD;
#pragma unroll
    for (int nd = 0; nd < 8; nd++) {
        int d0 = nd * 8 + (lane & 3) * 2;
        float a0 = acc_o[nd][0] * inv_a, a1 = acc_o[nd][1] * inv_a;
        float b0 = acc_o[nd][2] * inv_b, b1 = acc_o[nd][3] * inv_b;
        __nv_bfloat16 h0, l0, h1, l1;
        split_hilo(a0, h0, l0); split_hilo(a1, h1, l1);
        *(uint32_t*)(Oh + ob + (size_t)row_a * DMODEL + d0) = pack_bf2(h0, h1);
        *(uint32_t*)(Ol + ob + (size_t)row_a * DMODEL + d0) = pack_bf2(l0, l1);
        split_hilo(b0, h0, l0); split_hilo(b1, h1, l1);
        *(uint32_t*)(Oh + ob + (size_t)(row_a + 8) * DMODEL + d0) = pack_bf2(h0, h1);
        *(uint32_t*)(Ol + ob + (size_t)(row_a + 8) * DMODEL + d0) = pack_bf2(l0, l1);
    }
}

// ---------------- GeGLU (bf16 hi/lo in) + hi/lo emit ----------------
__global__ __launch_bounds__(256) void geglu_hilo_kernel(const __nv_bfloat16* __restrict__ Hh,
                                                         const __nv_bfloat16* __restrict__ Hl,
                                                         __nv_bfloat16* __restrict__ Ho,
                                                         __nv_bfloat16* __restrict__ Lo) {
    int row = blockIdx.y;
    int c = (blockIdx.x * 256 + threadIdx.x) * 4;
    size_t ubase = (size_t)row * FFH + c;
    size_t gbase = ubase + FFHALF;
    union { uint2 u; __nv_bfloat16 e[4]; } uh, ul, gh, gl;
    uh.u = *(const uint2*)(Hh + ubase);
    ul.u = *(const uint2*)(Hl + ubase);
    gh.u = *(const uint2*)(Hh + gbase);
    gl.u = *(const uint2*)(Hl + gbase);
    const float kc = 0.70710678118654752f;
    union { __nv_bfloat16 b[4]; uint2 uu; } ph, pl;
#pragma unroll
    for (int j = 0; j < 4; j++) {
        float u = __bfloat162float(uh.e[j]) + __bfloat162float(ul.e[j]);
        float g = __bfloat162float(gh.e[j]) + __bfloat162float(gl.e[j]);
        float r = u * (0.5f * g * (1.f + erff(g * kc)));
        split_hilo(r, ph.b[j], pl.b[j]);
    }
    size_t base = (size_t)row * FFHALF + c;
    *(uint2*)(Ho + base) = ph.uu;
    *(uint2*)(Lo + base) = pl.uu;
}

// ---------------- launch ----------------
extern "C" void kernel_launch(void* const* d_in, const int* in_sizes, int n_in,
                              void* d_out, int out_size) {
    const float* x    = (const float*)d_in[0];
    const float* ctx  = (const float*)d_in[1];
    const float* ln1g = (const float*)d_in[2];
    const float* ln1b = (const float*)d_in[3];
    const float* ln2g = (const float*)d_in[4];
    const float* ln2b = (const float*)d_in[5];
    const float* ln3g = (const float*)d_in[6];
    const float* ln3b = (const float*)d_in[7];
    const float* a1wq = (const float*)d_in[8];
    const float* a1wk = (const float*)d_in[9];
    const float* a1wv = (const float*)d_in[10];
    const float* a1wo = (const float*)d_in[11];
    const float* a1bo = (const float*)d_in[12];
    const float* a2wq = (const float*)d_in[13];
    const float* a2wk = (const float*)d_in[14];
    const float* a2wv = (const float*)d_in[15];
    const float* a2wo = (const float*)d_in[16];
    const float* a2bo = (const float*)d_in[17];
    const float* ffw1 = (const float*)d_in[18];
    const float* ffb1 = (const float*)d_in[19];
    const float* ffw2 = (const float*)d_in[20];
    const float* ffb2 = (const float*)d_in[21];
    float* out = (float*)d_out;

    float *xa, *ct1, *ct2;
    __nv_bfloat16 *wh, *wl, *hh, *hl, *ah, *al, *qh, *ql, *kh, *kl, *vh, *vl, *oh, *ol;
    cudaGetSymbolAddress((void**)&xa,  g_xa);
    cudaGetSymbolAddress((void**)&ct1, g_ctmp1);
    cudaGetSymbolAddress((void**)&ct2, g_ctmp2);
    cudaGetSymbolAddress((void**)&wh, g_wh);
    cudaGetSymbolAddress((void**)&wl, g_wl);
    cudaGetSymbolAddress((void**)&hh, g_hh);
    cudaGetSymbolAddress((void**)&hl, g_hl);
    cudaGetSymbolAddress((void**)&ah, g_ah);
    cudaGetSymbolAddress((void**)&al, g_al);
    cudaGetSymbolAddress((void**)&qh, g_qh);
    cudaGetSymbolAddress((void**)&ql, g_ql);
    cudaGetSymbolAddress((void**)&kh, g_kh);
    cudaGetSymbolAddress((void**)&kl, g_kl);
    cudaGetSymbolAddress((void**)&vh, g_vh);
    cudaGetSymbolAddress((void**)&vl, g_vl);
    cudaGetSymbolAddress((void**)&oh, g_oh);
    cudaGetSymbolAddress((void**)&ol, g_ol);

    cudaFuncSetAttribute(attn_mma_kernel, cudaFuncAttributeMaxDynamicSharedMemorySize, ATT_SMEM);
    cudaFuncSetAttribute(gemm_mma_kernel, cudaFuncAttributeMaxDynamicSharedMemorySize, GEMM_SMEM);

    dim3 blk(256);
    dim3 tblk(32, 8);
    dim3 tc1024(DMODEL / 128, MROWS / 128);
    dim3 tcFF1(FFH / 128, MROWS / 128);
    dim3 gemmCtx(DMODEL / 128, (CTXROWS + 127) / 128);
    dim3 attng(SEQ / 128, NHEAD, 4);
    dim3 tg1024(DMODEL / 32, DMODEL / 32);
    dim3 tgFF1(FFH / 32, DMODEL / 32);
    dim3 tgFF2(DMODEL / 32, FFHALF / 32);

    // --- self attention ---
    ln_hilo_kernel<<<MROWS, blk>>>(x, ln1g, ln1b, ah, al);                       // 0
    tconv_kernel<<<tg1024, tblk>>>(a1wq, wh + OW_Q,  wl + OW_Q,  DMODEL, DMODEL); // 1
    tconv_kernel<<<tg1024, tblk>>>(a1wk, wh + OW_K,  wl + OW_K,  DMODEL, DMODEL); // 2
    tconv_kernel<<<tg1024, tblk>>>(a1wv, wh + OW_V,  wl + OW_V,  DMODEL, DMODEL); // 3
    tconv_kernel<<<tg1024, tblk>>>(a1wo, wh + OW_O1, wl + OW_O1, DMODEL, DMODEL); // 4
    gemm_mma_kernel<<<tc1024, blk, GEMM_SMEM>>>(ah, al, wh + OW_Q, wl + OW_Q, nullptr,   // 5 (ncu)
        MROWS, DMODEL, DMODEL, nullptr, nullptr, qh, ql);
    gemm_mma_kernel<<<tc1024, blk, GEMM_SMEM>>>(ah, al, wh + OW_K, wl + OW_K, nullptr,
        MROWS, DMODEL, DMODEL, nullptr, nullptr, kh, kl);
    gemm_mma_kernel<<<tc1024, blk, GEMM_SMEM>>>(ah, al, wh + OW_V, wl + OW_V, nullptr,
        MROWS, DMODEL, DMODEL, nullptr, nullptr, vh, vl);
    attn_mma_kernel<<<attng, blk, ATT_SMEM>>>(qh, ql, kh, kl, vh, vl, oh, ol, SEQ, SEQ);
    gemm_mma_kernel<<<tc1024, blk, GEMM_SMEM>>>(oh, ol, wh + OW_O1, wl + OW_O1, xa,
        MROWS, DMODEL, DMODEL, a1bo, x, nullptr, nullptr);

    // --- cross attention ---
    ln_hilo_kernel<<<MROWS, blk>>>(xa, ln2g, ln2b, ah, al);
    tconv_kernel<<<tg1024, tblk>>>(a2wq, wh + OW_Q2, wl + OW_Q2, DMODEL, DMODEL);
    tconv_kernel<<<tg1024, tblk>>>(a2wo, wh + OW_O2, wl + OW_O2, DMODEL, DMODEL);
    gemm_mma_kernel<<<tc1024, blk, GEMM_SMEM>>>(ah, al, wh + OW_Q2, wl + OW_Q2, nullptr,
        MROWS, DMODEL, DMODEL, nullptr, nullptr, qh, ql);
    gemm_kernel<<<gemmCtx, blk>>>(ctx, a2wk, ct1, CTXROWS, DMODEL, CTXDIM);
    hilo_kernel<<<CTXROWS, blk>>>(ct1, kh, kl);
    gemm_kernel<<<gemmCtx, blk>>>(ctx, a2wv, ct2, CTXROWS, DMODEL, CTXDIM);
    hilo_kernel<<<CTXROWS, blk>>>(ct2, vh, vl);
    attn_mma_kernel<<<attng, blk, ATT_SMEM>>>(qh, ql, kh, kl, vh, vl, oh, ol, SEQ, CTXLEN);
    gemm_mma_kernel<<<tc1024, blk, GEMM_SMEM>>>(oh, ol, wh + OW_O2, wl + OW_O2, xa,
        MROWS, DMODEL, DMODEL, a2bo, xa, nullptr, nullptr);

    // --- GeGLU feed-forward ---
    ln_hilo_kernel<<<MROWS, blk>>>(xa, ln3g, ln3b, ah, al);
    tconv_kernel<<<tgFF1, tblk>>>(ffw1, wh + OW_FF1, wl + OW_FF1, DMODEL, FFH);
    tconv_kernel<<<tgFF2, tblk>>>(ffw2, wh + OW_FF2, wl + OW_FF2, FFHALF, DMODEL);
    gemm_mma_kernel<<<tcFF1, blk, GEMM_SMEM>>>(ah, al, wh + OW_FF1, wl + OW_FF1, nullptr,
        MROWS, FFH, DMODEL, ffb1, nullptr, hh, hl);
    geglu_hilo_kernel<<<dim3(FFHALF / 1024, MROWS), blk>>>(hh, hl, ah, al);
    gemm_mma_kernel<<<tc1024, blk, GEMM_SMEM>>>(ah, al, wh + OW_FF2, wl + OW_FF2, out,
        MROWS, DMODEL, FFHALF, ffb2, xa, nullptr, nullptr);
}

// round 10
// speedup vs baseline: 1.4204x; 1.4204x over previous
#include <cuda_runtime.h>
#include <cuda_bf16.h>
#include <math.h>
#include <cstdint>

// ---------------- problem constants ----------------
#define MROWS   8192        // B*S
#define DMODEL  1024
#define NHEAD   16
#define DHEAD   64
#define SEQ     2048
#define CTXROWS 308         // B*77
#define CTXLEN  77
#define CTXDIM  768
#define FFH     8192
#define FFHALF  4096

// ---------------- scratch (static device globals; no runtime alloc) ----------------
__device__ float g_xa[MROWS * DMODEL];
__device__ float g_h [(size_t)MROWS * FFH];
__device__ float g_ctmp1[CTXROWS * DMODEL];
__device__ float g_ctmp2[CTXROWS * DMODEL];
__device__ __nv_bfloat16 g_ah[(size_t)MROWS * FFHALF];   // activation hi
__device__ __nv_bfloat16 g_al[(size_t)MROWS * FFHALF];   // activation lo
__device__ __nv_bfloat16 g_bh[(size_t)FFH * DMODEL];     // weight hi (transposed [N,K])
__device__ __nv_bfloat16 g_bl[(size_t)FFH * DMODEL];     // weight lo
__device__ __nv_bfloat16 g_qh[MROWS * DMODEL];
__device__ __nv_bfloat16 g_ql[MROWS * DMODEL];
__device__ __nv_bfloat16 g_kh[MROWS * DMODEL];
__device__ __nv_bfloat16 g_kl[MROWS * DMODEL];
__device__ __nv_bfloat16 g_vh[MROWS * DMODEL];
__device__ __nv_bfloat16 g_vl[MROWS * DMODEL];
__device__ __nv_bfloat16 g_oh[MROWS * DMODEL];
__device__ __nv_bfloat16 g_ol[MROWS * DMODEL];

// ---------------- PTX helpers ----------------
__device__ __forceinline__ uint32_t smem_to_u32(const void* p) {
    uint32_t a;
    asm("{ .reg .u64 t; cvta.to.shared.u64 t, %1; cvt.u32.u64 %0, t; }" : "=r"(a) : "l"(p));
    return a;
}
#define CP_ASYNC16(dst, src) \
    asm volatile("cp.async.cg.shared.global [%0], [%1], 16;" :: "r"(dst), "l"(src))
#define CP_COMMIT() asm volatile("cp.async.commit_group;")
#define CP_WAIT0()  asm volatile("cp.async.wait_group 0;")
#define CP_WAIT1()  asm volatile("cp.async.wait_group 1;")
#define LDSM_X4(r0, r1, r2, r3, addr) \
    asm volatile("ldmatrix.sync.aligned.m8n8.x4.shared.b16 {%0,%1,%2,%3}, [%4];" \
        : "=r"(r0), "=r"(r1), "=r"(r2), "=r"(r3) : "r"(addr))
#define MMA16816(d, a, b0, b1) \
    asm volatile("mma.sync.aligned.m16n8k16.row.col.f32.bf16.bf16.f32 " \
        "{%0,%1,%2,%3}, {%4,%5,%6,%7}, {%8,%9}, {%0,%1,%2,%3};" \
        : "+f"((d)[0]), "+f"((d)[1]), "+f"((d)[2]), "+f"((d)[3]) \
        : "r"((a)[0]), "r"((a)[1]), "r"((a)[2]), "r"((a)[3]), "r"(b0), "r"(b1))

// ---------------- hi/lo split helpers ----------------
__device__ __forceinline__ void split_hilo(float x, __nv_bfloat16& h, __nv_bfloat16& l) {
    h = __float2bfloat16(x);
    l = __float2bfloat16(x - __bfloat162float(h));
}
__device__ __forceinline__ uint32_t pack_bf2(__nv_bfloat16 lo, __nv_bfloat16 hi) {
    __nv_bfloat162 t; t.x = lo; t.y = hi;
    return *(uint32_t*)&t;
}

// ---------------- fused LayerNorm + hi/lo emit ----------------
__global__ __launch_bounds__(256) void ln_hilo_kernel(const float* __restrict__ X,
                                                      const float* __restrict__ gma,
                                                      const float* __restrict__ bta,
                                                      __nv_bfloat16* __restrict__ Ho,
                                                      __nv_bfloat16* __restrict__ Lo) {
    int row = blockIdx.x;
    int tid = threadIdx.x;
    const float4* xr = (const float4*)(X + (size_t)row * DMODEL);
    float4 x4 = xr[tid];
    float s  = x4.x + x4.y + x4.z + x4.w;
    float ss = x4.x*x4.x + x4.y*x4.y + x4.z*x4.z + x4.w*x4.w;
#pragma unroll
    for (int off = 16; off > 0; off >>= 1) {
        s  += __shfl_xor_sync(0xffffffffu, s,  off);
        ss += __shfl_xor_sync(0xffffffffu, ss, off);
    }
    __shared__ float red[16];
    int lane = tid & 31, wid = tid >> 5;
    if (lane == 0) { red[wid] = s; red[8 + wid] = ss; }
    __syncthreads();
    float tot = 0.f, tot2 = 0.f;
#pragma unroll
    for (int i = 0; i < 8; i++) { tot += red[i]; tot2 += red[8 + i]; }
    const float inv = 1.0f / (float)DMODEL;
    float mu  = tot * inv;
    float var = tot2 * inv - mu * mu;
    float rs  = rsqrtf(var + 1e-5f);
    float4 gv = ((const float4*)gma)[tid];
    float4 bv = ((const float4*)bta)[tid];
    float o0 = (x4.x - mu) * rs * gv.x + bv.x;
    float o1 = (x4.y - mu) * rs * gv.y + bv.y;
    float o2 = (x4.z - mu) * rs * gv.z + bv.z;
    float o3 = (x4.w - mu) * rs * gv.w + bv.w;
    union { __nv_bfloat16 b[4]; uint2 u; } ph, pl;
    split_hilo(o0, ph.b[0], pl.b[0]);
    split_hilo(o1, ph.b[1], pl.b[1]);
    split_hilo(o2, ph.b[2], pl.b[2]);
    split_hilo(o3, ph.b[3], pl.b[3]);
    size_t base = (size_t)row * DMODEL + tid * 4;
    *(uint2*)(Ho + base) = ph.u;
    *(uint2*)(Lo + base) = pl.u;
}

// ---------------- elementwise fp32 -> bf16 hi/lo (ctx K/V path) ----------------
__global__ __launch_bounds__(256) void hilo_kernel(const float* __restrict__ X,
                                                   __nv_bfloat16* __restrict__ Ho,
                                                   __nv_bfloat16* __restrict__ Lo) {
    size_t idx = (size_t)blockIdx.x * 256 + threadIdx.x;
    float4 v = ((const float4*)X)[idx];
    union { __nv_bfloat16 b[4]; uint2 u; } ph, pl;
    split_hilo(v.x, ph.b[0], pl.b[0]);
    split_hilo(v.y, ph.b[1], pl.b[1]);
    split_hilo(v.z, ph.b[2], pl.b[2]);
    split_hilo(v.w, ph.b[3], pl.b[3]);
    *(uint2*)(Ho + idx * 4) = ph.u;
    *(uint2*)(Lo + idx * 4) = pl.u;
}

// ---------------- weight convert + transpose: W[K,N] fp32 -> Ht/Lt[N,K] bf16 ----------------
__global__ __launch_bounds__(256) void tconv_kernel(const float* __restrict__ W,
                                                    __nv_bfloat16* __restrict__ Ht,
                                                    __nv_bfloat16* __restrict__ Lt,
                                                    int K, int N) {
    __shared__ float s[32][33];
    int tx = threadIdx.x, ty = threadIdx.y;
    int n0 = blockIdx.x * 32, k0 = blockIdx.y * 32;
#pragma unroll
    for (int i = 0; i < 4; i++)
        s[ty + 8 * i][tx] = W[(size_t)(k0 + ty + 8 * i) * N + n0 + tx];
    __syncthreads();
#pragma unroll
    for (int i = 0; i < 4; i++) {
        int n = ty + 8 * i, k = tx;
        float v = s[k][n];
        __nv_bfloat16 h, l;
        split_hilo(v, h, l);
        size_t off = (size_t)(n0 + n) * K + k0 + k;
        Ht[off] = h;
        Lt[off] = l;
    }
}

// ---------------- bf16x3 GEMM via mma.sync (3-pass terms, 3-stage cp.async) ----------------
// C[M,N] = A @ Bt^T, terms AhBh + AhBl + AlBh as three K-passes into one accumulator.
// BM=BN=128, BK=32, 256 threads = 8 warps (2M x 4N). Stage = A|B = 16KB, 3 stages.
#define GSTAGE 16384
#define GEMM_SMEM (3 * GSTAGE)

__global__ __launch_bounds__(256) void gemm_mma_kernel(const __nv_bfloat16* __restrict__ Ah,
                                                       const __nv_bfloat16* __restrict__ Al,
                                                       const __nv_bfloat16* __restrict__ Bh,
                                                       const __nv_bfloat16* __restrict__ Bl,
                                                       float* __restrict__ C,
                                                       int M, int N, int K,
                                                       const float* __restrict__ bias,
                                                       const float* __restrict__ resid,
                                                       __nv_bfloat16* __restrict__ CH,
                                                       __nv_bfloat16* __restrict__ CL) {
    extern __shared__ char gsm[];
    uint32_t sbase = smem_to_u32(gsm);
    int tid = threadIdx.x;
    int warp = tid >> 5, lane = tid & 31;
    int wm = (warp & 1) * 64, wn = (warp >> 1) * 32;
    int row0 = blockIdx.y * 128, col0 = blockIdx.x * 128;

    const __nv_bfloat16* Aterm[3] = { Ah, Ah, Al };
    const __nv_bfloat16* Bterm[3] = { Bh, Bl, Bh };
    const int nk = K / 32;
    const int total = 3 * nk;

    float acc[4][4][4];
#pragma unroll
    for (int mi = 0; mi < 4; mi++)
#pragma unroll
        for (int ni = 0; ni < 4; ni++)
#pragma unroll
            for (int e = 0; e < 4; e++) acc[mi][ni][e] = 0.f;

    // one stage = A tile (8KB) + B tile (8KB); each thread: 2 A-chunks + 2 B-chunks
    auto load_stage = [&](int buf, int idx) {
        int t  = idx / nk;
        int k0 = (idx % nk) * 32;
        const __nv_bfloat16* Ap = Aterm[t];
        const __nv_bfloat16* Bp = Bterm[t];
        uint32_t so = sbase + buf * GSTAGE;
#pragma unroll
        for (int i = 0; i < 2; i++) {
            int lci = tid + i * 256;
            int r = lci >> 2, c = lci & 3;
            uint32_t doff = (uint32_t)(r * 64 + ((c ^ ((r >> 1) & 3)) * 16));
            CP_ASYNC16(so + doff,        Ap + (size_t)(row0 + r) * K + k0 + c * 8);
            CP_ASYNC16(so + 8192 + doff, Bp + (size_t)(col0 + r) * K + k0 + c * 8);
        }
        CP_COMMIT();
    };

    load_stage(0, 0);
    load_stage(1, 1);

    int buf = 0;
    for (int it = 0; it < total; it++) {
        if (it + 1 < total) { CP_WAIT1(); } else { CP_WAIT0(); }
        __syncthreads();
        if (it + 2 < total) {
            int nb3 = buf + 2; if (nb3 >= 3) nb3 -= 3;
            load_stage(nb3, it + 2);
        }
        uint32_t abase = sbase + buf * GSTAGE;
        uint32_t bbase = abase + 8192;
#pragma unroll
        for (int kk = 0; kk < 2; kk++) {
            uint32_t afr[4][4];
#pragma unroll
            for (int mi = 0; mi < 4; mi++) {
                int r = wm + mi * 16 + (lane & 15);
                int c = kk * 2 + (lane >> 4);
                uint32_t addr = abase + r * 64 + (uint32_t)((c ^ ((r >> 1) & 3)) * 16);
                LDSM_X4(afr[mi][0], afr[mi][1], afr[mi][2], afr[mi][3], addr);
            }
            uint32_t bfr[2][4];
#pragma unroll
            for (int nb = 0; nb < 2; nb++) {
                int r = wn + nb * 16 + (lane & 15);
                int c = kk * 2 + (lane >> 4);
                uint32_t addr = bbase + r * 64 + (uint32_t)((c ^ ((r >> 1) & 3)) * 16);
                LDSM_X4(bfr[nb][0], bfr[nb][1], bfr[nb][2], bfr[nb][3], addr);
            }
#pragma unroll
            for (int mi = 0; mi < 4; mi++)
#pragma unroll
                for (int nb = 0; nb < 2; nb++) {
                    MMA16816(acc[mi][nb * 2 + 0], afr[mi], bfr[nb][0], bfr[nb][2]);
                    MMA16816(acc[mi][nb * 2 + 1], afr[mi], bfr[nb][1], bfr[nb][3]);
                }
        }
        buf++; if (buf >= 3) buf -= 3;
    }

    // epilogue
    int grow = row0 + wm;
    int gcol = col0 + wn;
#pragma unroll
    for (int mi = 0; mi < 4; mi++)
#pragma unroll
        for (int ni = 0; ni < 4; ni++) {
            int r  = grow + mi * 16 + (lane >> 2);
            int cc = gcol + ni * 8 + (lane & 3) * 2;
            float2 v0 = make_float2(acc[mi][ni][0], acc[mi][ni][1]);
            float2 v1 = make_float2(acc[mi][ni][2], acc[mi][ni][3]);
            if (bias) {
                float2 b2 = *(const float2*)(bias + cc);
                v0.x += b2.x; v0.y += b2.y;
                v1.x += b2.x; v1.y += b2.y;
            }
            if (resid) {
                float2 r0 = *(const float2*)(resid + (size_t)r * N + cc);
                float2 r1 = *(const float2*)(resid + (size_t)(r + 8) * N + cc);
                v0.x += r0.x; v0.y += r0.y;
                v1.x += r1.x; v1.y += r1.y;
            }
            if (CH) {
                __nv_bfloat16 h0, l0, h1, l1;
                split_hilo(v0.x, h0, l0); split_hilo(v0.y, h1, l1);
                *(uint32_t*)(CH + (size_t)r * N + cc) = pack_bf2(h0, h1);
                *(uint32_t*)(CL + (size_t)r * N + cc) = pack_bf2(l0, l1);
                split_hilo(v1.x, h0, l0); split_hilo(v1.y, h1, l1);
                *(uint32_t*)(CH + (size_t)(r + 8) * N + cc) = pack_bf2(h0, h1);
                *(uint32_t*)(CL + (size_t)(r + 8) * N + cc) = pack_bf2(l0, l1);
            } else {
                *(float2*)(C + (size_t)r * N + cc) = v0;
                *(float2*)(C + (size_t)(r + 8) * N + cc) = v1;
            }
        }
}

// ---------------- fp32 GEMM (small ctx projections only) ----------------
__global__ __launch_bounds__(256) void gemm_kernel(const float* __restrict__ A,
                                                   const float* __restrict__ B,
                                                   float* __restrict__ C,
                                                   int M, int N, int K) {
    __shared__ float As[16][128];
    __shared__ float Bs[16][128];
    int tid = threadIdx.x;
    int tx = tid & 15, ty = tid >> 4;
    int row0 = blockIdx.y * 128, col0 = blockIdx.x * 128;
    float acc[8][8];
#pragma unroll
    for (int i = 0; i < 8; i++)
#pragma unroll
        for (int j = 0; j < 8; j++) acc[i][j] = 0.f;

    for (int k0 = 0; k0 < K; k0 += 16) {
#pragma unroll
        for (int i = 0; i < 2; i++) {
            int idx = tid * 2 + i;
            int r = idx >> 2, kc = idx & 3;
            int gr = row0 + r;
            float4 f = make_float4(0.f, 0.f, 0.f, 0.f);
            if (gr < M) f = *(const float4*)(A + (size_t)gr * K + k0 + kc * 4);
            As[kc * 4 + 0][r] = f.x;
            As[kc * 4 + 1][r] = f.y;
            As[kc * 4 + 2][r] = f.z;
            As[kc * 4 + 3][r] = f.w;
        }
#pragma unroll
        for (int i = 0; i < 2; i++) {
            int idx = tid * 2 + i;
            int kb = idx >> 5, nc = idx & 31;
            float4 f = *(const float4*)(B + (size_t)(k0 + kb) * N + col0 + nc * 4);
            *(float4*)&Bs[kb][nc * 4] = f;
        }
        __syncthreads();
#pragma unroll
        for (int kk = 0; kk < 16; kk++) {
            float a[8], bb[8];
            *(float4*)&a[0]  = *(float4*)&As[kk][ty * 8];
            *(float4*)&a[4]  = *(float4*)&As[kk][ty * 8 + 4];
            *(float4*)&bb[0] = *(float4*)&Bs[kk][tx * 4];
            *(float4*)&bb[4] = *(float4*)&Bs[kk][64 + tx * 4];
#pragma unroll
            for (int i = 0; i < 8; i++)
#pragma unroll
                for (int j = 0; j < 8; j++) acc[i][j] += a[i] * bb[j];
        }
        __syncthreads();
    }
#pragma unroll
    for (int i = 0; i < 8; i++) {
        int gr = row0 + ty * 8 + i;
        if (gr >= M) continue;
#pragma unroll
        for (int half = 0; half < 2; half++) {
            int gc = col0 + half * 64 + tx * 4;
            float4 r4;
            r4.x = acc[i][half * 4 + 0];
            r4.y = acc[i][half * 4 + 1];
            r4.z = acc[i][half * 4 + 2];
            r4.w = acc[i][half * 4 + 3];
            *(float4*)(C + (size_t)gr * N + gc) = r4;
        }
    }
}

// ---------------- MMA flash attention ----------------
#define AQ_H 0
#define AQ_L 16384
#define AK_H 32768
#define AK_L 40960
#define AV_H 49152
#define AV_L 57344
#define ATT_SMEM 65536

__device__ __forceinline__ uint32_t att_sw(int r, int c) {
    return (uint32_t)(r * 128 + ((c ^ (r & 7)) << 4));
}

__global__ __launch_bounds__(256) void attn_mma_kernel(
    const __nv_bfloat16* __restrict__ Qh, const __nv_bfloat16* __restrict__ Ql,
    const __nv_bfloat16* __restrict__ Kp_h, const __nv_bfloat16* __restrict__ Kp_l,
    const __nv_bfloat16* __restrict__ Vh, const __nv_bfloat16* __restrict__ Vl,
    __nv_bfloat16* __restrict__ Oh, __nv_bfloat16* __restrict__ Ol,
    int qlen, int kvlen)
{
    extern __shared__ char smc[];
    uint32_t sb = smem_to_u32(smc);
    int b = blockIdx.z, h = blockIdx.y, qt = blockIdx.x;
    int tid = threadIdx.x, warp = tid >> 5, lane = tid & 31;
    int qrow0 = qt * 128;
    size_t qbase  = ((size_t)b * qlen + qrow0) * DMODEL + h * DHEAD;
    size_t kvbase = ((size_t)b * kvlen) * DMODEL + h * DHEAD;

#pragma unroll
    for (int i = 0; i < 4; i++) {
        int idx = tid + i * 256;
        int r = idx >> 3, c = idx & 7;
        uint4 vh4 = *(const uint4*)(Qh + qbase + (size_t)r * DMODEL + c * 8);
        uint4 vl4 = *(const uint4*)(Ql + qbase + (size_t)r * DMODEL + c * 8);
        *(uint4*)(smc + AQ_H + att_sw(r, c)) = vh4;
        *(uint4*)(smc + AQ_L + att_sw(r, c)) = vl4;
    }
    __syncthreads();

    uint32_t qfh[4][4], qfl[4][4];
    {
        int r = warp * 16 + (lane & 15);
#pragma unroll
        for (int kk = 0; kk < 4; kk++) {
            int c = kk * 2 + (lane >> 4);
            LDSM_X4(qfh[kk][0], qfh[kk][1], qfh[kk][2], qfh[kk][3], sb + AQ_H + att_sw(r, c));
            LDSM_X4(qfl[kk][0], qfl[kk][1], qfl[kk][2], qfl[kk][3], sb + AQ_L + att_sw(r, c));
        }
    }

    float m_a = -1e30f, m_b = -1e30f, l_a = 0.f, l_b = 0.f;
    float acc_o[8][4];
#pragma unroll
    for (int t = 0; t < 8; t++)
#pragma unroll
        for (int e = 0; e < 4; e++) acc_o[t][e] = 0.f;

    int ntiles = (kvlen + 63) >> 6;
    for (int kt = 0; kt < ntiles; kt++) {
#pragma unroll
        for (int i = 0; i < 2; i++) {
            int idx = tid + i * 256;
            int r = idx >> 3, c = idx & 7;
            int kr = kt * 64 + r;
            uint4 kh4 = make_uint4(0, 0, 0, 0), kl4 = kh4;
            if (kr < kvlen) {
                kh4 = *(const uint4*)(Kp_h + kvbase + (size_t)kr * DMODEL + c * 8);
                kl4 = *(const uint4*)(Kp_l + kvbase + (size_t)kr * DMODEL + c * 8);
            }
            *(uint4*)(smc + AK_H + att_sw(r, c)) = kh4;
            *(uint4*)(smc + AK_L + att_sw(r, c)) = kl4;
        }
#pragma unroll
        for (int i = 0; i < 4; i++) {
            int idx = tid + i * 256;
            int r = idx >> 4, cg = idx & 15;
            int kr = kt * 64 + r;
            union { uint2 u; __nv_bfloat16 e[4]; } vhu, vlu;
            vhu.u = make_uint2(0, 0); vlu.u = make_uint2(0, 0);
            if (kr < kvlen) {
                vhu.u = *(const uint2*)(Vh + kvbase + (size_t)kr * DMODEL + cg * 4);
                vlu.u = *(const uint2*)(Vl + kvbase + (size_t)kr * DMODEL + cg * 4);
            }
#pragma unroll
            for (int j = 0; j < 4; j++) {
                int d = cg * 4 + j;
                uint32_t off = (uint32_t)(d * 128 + ((((r >> 3) ^ (d & 7))) << 4) + (r & 7) * 2);
                *(__nv_bfloat16*)(smc + AV_H + off) = vhu.e[j];
                *(__nv_bfloat16*)(smc + AV_L + off) = vlu.e[j];
            }
        }
        __syncthreads();

        float s[8][4];
#pragma unroll
        for (int t = 0; t < 8; t++)
#pragma unroll
            for (int e = 0; e < 4; e++) s[t][e] = 0.f;
#pragma unroll
        for (int kk = 0; kk < 4; kk++) {
#pragma unroll
            for (int nq = 0; nq < 4; nq++) {
                int r = nq * 16 + (lane & 15);
                int c = kk * 2 + (lane >> 4);
                uint32_t khf[4], klf[4];
                LDSM_X4(khf[0], khf[1], khf[2], khf[3], sb + AK_H + att_sw(r, c));
                LDSM_X4(klf[0], klf[1], klf[2], klf[3], sb + AK_L + att_sw(r, c));
                MMA16816(s[nq * 2 + 0], qfh[kk], khf[0], khf[2]);
                MMA16816(s[nq * 2 + 1], qfh[kk], khf[1], khf[3]);
                MMA16816(s[nq * 2 + 0], qfh[kk], klf[0], klf[2]);
                MMA16816(s[nq * 2 + 1], qfh[kk], klf[1], klf[3]);
                MMA16816(s[nq * 2 + 0], qfl[kk], khf[0], khf[2]);
                MMA16816(s[nq * 2 + 1], qfl[kk], khf[1], khf[3]);
            }
        }
        bool mtile = (kt == ntiles - 1) && (kvlen & 63);
#pragma unroll
        for (int t = 0; t < 8; t++)
#pragma unroll
            for (int e = 0; e < 4; e++) {
                float vv = s[t][e] * 0.125f;
                if (mtile) {
                    int col = kt * 64 + t * 8 + (lane & 3) * 2 + (e & 1);
                    if (col >= kvlen) vv = -1e30f;
                }
                s[t][e] = vv;
            }
        float mx_a = -1e30f, mx_b = -1e30f;
#pragma unroll
        for (int t = 0; t < 8; t++) {
            mx_a = fmaxf(mx_a, fmaxf(s[t][0], s[t][1]));
            mx_b = fmaxf(mx_b, fmaxf(s[t][2], s[t][3]));
        }
        mx_a = fmaxf(mx_a, __shfl_xor_sync(0xffffffffu, mx_a, 1));
        mx_a = fmaxf(mx_a, __shfl_xor_sync(0xffffffffu, mx_a, 2));
        mx_b = fmaxf(mx_b, __shfl_xor_sync(0xffffffffu, mx_b, 1));
        mx_b = fmaxf(mx_b, __shfl_xor_sync(0xffffffffu, mx_b, 2));
        float mn_a = fmaxf(m_a, mx_a), mn_b = fmaxf(m_b, mx_b);
        float al_a = __expf(m_a - mn_a), al_b = __expf(m_b - mn_b);
        m_a = mn_a; m_b = mn_b;
        float sum_a = 0.f, sum_b = 0.f;
#pragma unroll
        for (int t = 0; t < 8; t++) {
            s[t][0] = __expf(s[t][0] - m_a);
            s[t][1] = __expf(s[t][1] - m_a);
            s[t][2] = __expf(s[t][2] - m_b);
            s[t][3] = __expf(s[t][3] - m_b);
            sum_a += s[t][0] + s[t][1];
            sum_b += s[t][2] + s[t][3];
        }
        sum_a += __shfl_xor_sync(0xffffffffu, sum_a, 1);
        sum_a += __shfl_xor_sync(0xffffffffu, sum_a, 2);
        sum_b += __shfl_xor_sync(0xffffffffu, sum_b, 1);
        sum_b += __shfl_xor_sync(0xffffffffu, sum_b, 2);
        l_a = l_a * al_a + sum_a;
        l_b = l_b * al_b + sum_b;
#pragma unroll
        for (int t = 0; t < 8; t++) {
            acc_o[t][0] *= al_a; acc_o[t][1] *= al_a;
            acc_o[t][2] *= al_b; acc_o[t][3] *= al_b;
        }
#pragma unroll
        for (int kc = 0; kc < 4; kc++) {
            int t0 = kc * 2, t1 = t0 + 1;
            uint32_t pah[4], pal[4];
            {
                __nv_bfloat16 hb, lb, hb2, lb2;
                split_hilo(s[t0][0], hb, lb);  split_hilo(s[t0][1], hb2, lb2);
                pah[0] = pack_bf2(hb, hb2);    pal[0] = pack_bf2(lb, lb2);
                split_hilo(s[t0][2], hb, lb);  split_hilo(s[t0][3], hb2, lb2);
                pah[1] = pack_bf2(hb, hb2);    pal[1] = pack_bf2(lb, lb2);
                split_hilo(s[t1][0], hb, lb);  split_hilo(s[t1][1], hb2, lb2);
                pah[2] = pack_bf2(hb, hb2);    pal[2] = pack_bf2(lb, lb2);
                split_hilo(s[t1][2], hb, lb);  split_hilo(s[t1][3], hb2, lb2);
                pah[3] = pack_bf2(hb, hb2);    pal[3] = pack_bf2(lb, lb2);
            }
#pragma unroll
            for (int nd = 0; nd < 4; nd++) {
                int r = nd * 16 + (lane & 15);
                int c = kc * 2 + (lane >> 4);
                uint32_t vhf[4], vlf[4];
                LDSM_X4(vhf[0], vhf[1], vhf[2], vhf[3], sb + AV_H + att_sw(r, c));
                LDSM_X4(vlf[0], vlf[1], vlf[2], vlf[3], sb + AV_L + att_sw(r, c));
                MMA16816(acc_o[nd * 2 + 0], pah, vhf[0], vhf[2]);
                MMA16816(acc_o[nd * 2 + 1], pah, vhf[1], vhf[3]);
                MMA16816(acc_o[nd * 2 + 0], pah, vlf[0], vlf[2]);
                MMA16816(acc_o[nd * 2 + 1], pah, vlf[1], vlf[3]);
                MMA16816(acc_o[nd * 2 + 0], pal, vhf[0], vhf[2]);
                MMA16816(acc_o[nd * 2 + 1], pal, vhf[1], vhf[3]);
            }
        }
        __syncthreads();
    }

    float inv_a = 1.0f / l_a, inv_b = 1.0f / l_b;
    int row_a = qrow0 + warp * 16 + (lane >> 2);
    size_t ob = ((size_t)b * qlen) * DMODEL + h * DHEAD;
#pragma unroll
    for (int nd = 0; nd < 8; nd++) {
        int d0 = nd * 8 + (lane & 3) * 2;
        float a0 = acc_o[nd][0] * inv_a, a1 = acc_o[nd][1] * inv_a;
        float b0 = acc_o[nd][2] * inv_b, b1 = acc_o[nd][3] * inv_b;
        __nv_bfloat16 h0, l0, h1, l1;
        split_hilo(a0, h0, l0); split_hilo(a1, h1, l1);
        *(uint32_t*)(Oh + ob + (size_t)row_a * DMODEL + d0) = pack_bf2(h0, h1);
        *(uint32_t*)(Ol + ob + (size_t)row_a * DMODEL + d0) = pack_bf2(l0, l1);
        split_hilo(b0, h0, l0); split_hilo(b1, h1, l1);
        *(uint32_t*)(Oh + ob + (size_t)(row_a + 8) * DMODEL + d0) = pack_bf2(h0, h1);
        *(uint32_t*)(Ol + ob + (size_t)(row_a + 8) * DMODEL + d0) = pack_bf2(l0, l1);
    }
}

// ---------------- GeGLU + hi/lo emit ----------------
__global__ __launch_bounds__(256) void geglu_hilo_kernel(const float* __restrict__ Hb,
                                                         __nv_bfloat16* __restrict__ Ho,
                                                         __nv_bfloat16* __restrict__ Lo) {
    int row = blockIdx.y;
    int c = (blockIdx.x * 256 + threadIdx.x) * 4;
    const float* hr = Hb + (size_t)row * FFH;
    float4 u = *(const float4*)(hr + c);
    float4 g = *(const float4*)(hr + FFHALF + c);
    const float k = 0.70710678118654752f;
    float r0 = u.x * (0.5f * g.x * (1.f + erff(g.x * k)));
    float r1 = u.y * (0.5f * g.y * (1.f + erff(g.y * k)));
    float r2 = u.z * (0.5f * g.z * (1.f + erff(g.z * k)));
    float r3 = u.w * (0.5f * g.w * (1.f + erff(g.w * k)));
    union { __nv_bfloat16 b[4]; uint2 uu; } ph, pl;
    split_hilo(r0, ph.b[0], pl.b[0]);
    split_hilo(r1, ph.b[1], pl.b[1]);
    split_hilo(r2, ph.b[2], pl.b[2]);
    split_hilo(r3, ph.b[3], pl.b[3]);
    size_t base = (size_t)row * FFHALF + c;
    *(uint2*)(Ho + base) = ph.uu;
    *(uint2*)(Lo + base) = pl.uu;
}

// ---------------- launch ----------------
extern "C" void kernel_launch(void* const* d_in, const int* in_sizes, int n_in,
                              void* d_out, int out_size) {
    const float* x    = (const float*)d_in[0];
    const float* ctx  = (const float*)d_in[1];
    const float* ln1g = (const float*)d_in[2];
    const float* ln1b = (const float*)d_in[3];
    const float* ln2g = (const float*)d_in[4];
    const float* ln2b = (const float*)d_in[5];
    const float* ln3g = (const float*)d_in[6];
    const float* ln3b = (const float*)d_in[7];
    const float* a1wq = (const float*)d_in[8];
    const float* a1wk = (const float*)d_in[9];
    const float* a1wv = (const float*)d_in[10];
    const float* a1wo = (const float*)d_in[11];
    const float* a1bo = (const float*)d_in[12];
    const float* a2wq = (const float*)d_in[13];
    const float* a2wk = (const float*)d_in[14];
    const float* a2wv = (const float*)d_in[15];
    const float* a2wo = (const float*)d_in[16];
    const float* a2bo = (const float*)d_in[17];
    const float* ffw1 = (const float*)d_in[18];
    const float* ffb1 = (const float*)d_in[19];
    const float* ffw2 = (const float*)d_in[20];
    const float* ffb2 = (const float*)d_in[21];
    float* out = (float*)d_out;

    float *xa, *hbuf, *ct1, *ct2;
    __nv_bfloat16 *ah, *al, *bh, *bl, *qh, *ql, *kh, *kl, *vh, *vl, *oh, *ol;
    cudaGetSymbolAddress((void**)&xa,   g_xa);
    cudaGetSymbolAddress((void**)&hbuf, g_h);
    cudaGetSymbolAddress((void**)&ct1,  g_ctmp1);
    cudaGetSymbolAddress((void**)&ct2,  g_ctmp2);
    cudaGetSymbolAddress((void**)&ah, g_ah);
    cudaGetSymbolAddress((void**)&al, g_al);
    cudaGetSymbolAddress((void**)&bh, g_bh);
    cudaGetSymbolAddress((void**)&bl, g_bl);
    cudaGetSymbolAddress((void**)&qh, g_qh);
    cudaGetSymbolAddress((void**)&ql, g_ql);
    cudaGetSymbolAddress((void**)&kh, g_kh);
    cudaGetSymbolAddress((void**)&kl, g_kl);
    cudaGetSymbolAddress((void**)&vh, g_vh);
    cudaGetSymbolAddress((void**)&vl, g_vl);
    cudaGetSymbolAddress((void**)&oh, g_oh);
    cudaGetSymbolAddress((void**)&ol, g_ol);

    cudaFuncSetAttribute(attn_mma_kernel, cudaFuncAttributeMaxDynamicSharedMemorySize, ATT_SMEM);
    cudaFuncSetAttribute(gemm_mma_kernel, cudaFuncAttributeMaxDynamicSharedMemorySize, GEMM_SMEM);

    dim3 blk(256);
    dim3 tblk(32, 8);
    dim3 tc1024(DMODEL / 128, MROWS / 128);
    dim3 tcFF1(FFH / 128, MROWS / 128);
    dim3 gemmCtx(DMODEL / 128, (CTXROWS + 127) / 128);
    dim3 attng(SEQ / 128, NHEAD, 4);
    dim3 tg1024(DMODEL / 32, DMODEL / 32);
    dim3 tgFF1(FFH / 32, DMODEL / 32);
    dim3 tgFF2(DMODEL / 32, FFHALF / 32);

    // --- self attention ---
    ln_hilo_kernel<<<MROWS, blk>>>(x, ln1g, ln1b, ah, al);
    tconv_kernel<<<tg1024, tblk>>>(a1wq, bh, bl, DMODEL, DMODEL);
    gemm_mma_kernel<<<tc1024, blk, GEMM_SMEM>>>(ah, al, bh, bl, nullptr, MROWS, DMODEL, DMODEL, nullptr, nullptr, qh, ql);
    tconv_kernel<<<tg1024, tblk>>>(a1wk, bh, bl, DMODEL, DMODEL);
    gemm_mma_kernel<<<tc1024, blk, GEMM_SMEM>>>(ah, al, bh, bl, nullptr, MROWS, DMODEL, DMODEL, nullptr, nullptr, kh, kl);
    tconv_kernel<<<tg1024, tblk>>>(a1wv, bh, bl, DMODEL, DMODEL);
    gemm_mma_kernel<<<tc1024, blk, GEMM_SMEM>>>(ah, al, bh, bl, nullptr, MROWS, DMODEL, DMODEL, nullptr, nullptr, vh, vl);
    attn_mma_kernel<<<attng, blk, ATT_SMEM>>>(qh, ql, kh, kl, vh, vl, oh, ol, SEQ, SEQ);
    tconv_kernel<<<tg1024, tblk>>>(a1wo, bh, bl, DMODEL, DMODEL);
    gemm_mma_kernel<<<tc1024, blk, GEMM_SMEM>>>(oh, ol, bh, bl, xa, MROWS, DMODEL, DMODEL, a1bo, x, nullptr, nullptr);

    // --- cross attention ---
    ln_hilo_kernel<<<MROWS, blk>>>(xa, ln2g, ln2b, ah, al);
    tconv_kernel<<<tg1024, tblk>>>(a2wq, bh, bl, DMODEL, DMODEL);
    gemm_mma_kernel<<<tc1024, blk, GEMM_SMEM>>>(ah, al, bh, bl, nullptr, MROWS, DMODEL, DMODEL, nullptr, nullptr, qh, ql);
    gemm_kernel<<<gemmCtx, blk>>>(ctx, a2wk, ct1, CTXROWS, DMODEL, CTXDIM);
    hilo_kernel<<<CTXROWS, blk>>>(ct1, kh, kl);
    gemm_kernel<<<gemmCtx, blk>>>(ctx, a2wv, ct2, CTXROWS, DMODEL, CTXDIM);
    hilo_kernel<<<CTXROWS, blk>>>(ct2, vh, vl);
    attn_mma_kernel<<<attng, blk, ATT_SMEM>>>(qh, ql, kh, kl, vh, vl, oh, ol, SEQ, CTXLEN);
    tconv_kernel<<<tg1024, tblk>>>(a2wo, bh, bl, DMODEL, DMODEL);
    gemm_mma_kernel<<<tc1024, blk, GEMM_SMEM>>>(oh, ol, bh, bl, xa, MROWS, DMODEL, DMODEL, a2bo, xa, nullptr, nullptr);

    // --- GeGLU feed-forward ---
    ln_hilo_kernel<<<MROWS, blk>>>(xa, ln3g, ln3b, ah, al);
    tconv_kernel<<<tgFF1, tblk>>>(ffw1, bh, bl, DMODEL, FFH);
    gemm_mma_kernel<<<tcFF1, blk, GEMM_SMEM>>>(ah, al, bh, bl, hbuf, MROWS, FFH, DMODEL, ffb1, nullptr, nullptr, nullptr);
    geglu_hilo_kernel<<<dim3(FFHALF / 1024, MROWS), blk>>>(hbuf, ah, al);
    tconv_kernel<<<tgFF2, tblk>>>(ffw2, bh, bl, FFHALF, DMODEL);
    gemm_mma_kernel<<<tc1024, blk, GEMM_SMEM>>>(ah, al, bh, bl, out, MROWS, DMODEL, FFHALF, ffb2, xa, nullptr, nullptr);
}

// round 12
// speedup vs baseline: 1.4374x; 1.0120x over previous
#include <cuda_runtime.h>
#include <cuda_bf16.h>
#include <math.h>
#include <cstdint>

// ---------------- problem constants ----------------
#define MROWS   8192        // B*S
#define DMODEL  1024
#define NHEAD   16
#define DHEAD   64
#define SEQ     2048
#define CTXROWS 308         // B*77
#define CTXLEN  77
#define CTXDIM  768
#define FFH     8192
#define FFHALF  4096
#define QKVN    3072

// weight sub-offsets inside g_bh/g_bl (elements)
#define OW_QKV_Q 0
#define OW_QKV_K (1024*1024)
#define OW_QKV_V (2*1024*1024)
#define OW_O1    (3*1024*1024)

// ---------------- scratch (static device globals; no runtime alloc) ----------------
__device__ float g_xa[MROWS * DMODEL];
__device__ float g_h [(size_t)MROWS * FFH];
__device__ float g_ctmp1[CTXROWS * DMODEL];
__device__ float g_ctmp2[CTXROWS * DMODEL];
__device__ __nv_bfloat16 g_ah[(size_t)MROWS * FFHALF];   // activation hi
__device__ __nv_bfloat16 g_al[(size_t)MROWS * FFHALF];   // activation lo
__device__ __nv_bfloat16 g_bh[(size_t)FFH * DMODEL];     // weights hi ([N,K], region-offset)
__device__ __nv_bfloat16 g_bl[(size_t)FFH * DMODEL];     // weights lo
__device__ __nv_bfloat16 g_qkvh[(size_t)MROWS * QKVN];   // fused QKV hi
__device__ __nv_bfloat16 g_qkvl[(size_t)MROWS * QKVN];   // fused QKV lo
__device__ __nv_bfloat16 g_qh[MROWS * DMODEL];           // cross-attn Q hi
__device__ __nv_bfloat16 g_ql[MROWS * DMODEL];
__device__ __nv_bfloat16 g_kh[MROWS * DMODEL];           // ctx K hi
__device__ __nv_bfloat16 g_kl[MROWS * DMODEL];
__device__ __nv_bfloat16 g_vh[MROWS * DMODEL];           // ctx V hi
__device__ __nv_bfloat16 g_vl[MROWS * DMODEL];
__device__ __nv_bfloat16 g_oh[MROWS * DMODEL];
__device__ __nv_bfloat16 g_ol[MROWS * DMODEL];

// ---------------- PTX helpers ----------------
__device__ __forceinline__ uint32_t smem_to_u32(const void* p) {
    uint32_t a;
    asm("{ .reg .u64 t; cvta.to.shared.u64 t, %1; cvt.u32.u64 %0, t; }" : "=r"(a) : "l"(p));
    return a;
}
#define CP_ASYNC16(dst, src) \
    asm volatile("cp.async.cg.shared.global [%0], [%1], 16;" :: "r"(dst), "l"(src))
#define CP_COMMIT() asm volatile("cp.async.commit_group;")
#define CP_WAIT0()  asm volatile("cp.async.wait_group 0;")
#define CP_WAIT1()  asm volatile("cp.async.wait_group 1;")
#define LDSM_X4(r0, r1, r2, r3, addr) \
    asm volatile("ldmatrix.sync.aligned.m8n8.x4.shared.b16 {%0,%1,%2,%3}, [%4];" \
        : "=r"(r0), "=r"(r1), "=r"(r2), "=r"(r3) : "r"(addr))
#define MMA16816(d, a, b0, b1) \
    asm volatile("mma.sync.aligned.m16n8k16.row.col.f32.bf16.bf16.f32 " \
        "{%0,%1,%2,%3}, {%4,%5,%6,%7}, {%8,%9}, {%0,%1,%2,%3};" \
        : "+f"((d)[0]), "+f"((d)[1]), "+f"((d)[2]), "+f"((d)[3]) \
        : "r"((a)[0]), "r"((a)[1]), "r"((a)[2]), "r"((a)[3]), "r"(b0), "r"(b1))

// ---------------- hi/lo split helpers ----------------
__device__ __forceinline__ void split_hilo(float x, __nv_bfloat16& h, __nv_bfloat16& l) {
    h = __float2bfloat16(x);
    l = __float2bfloat16(x - __bfloat162float(h));
}
__device__ __forceinline__ uint32_t pack_bf2(__nv_bfloat16 lo, __nv_bfloat16 hi) {
    __nv_bfloat162 t; t.x = lo; t.y = hi;
    return *(uint32_t*)&t;
}

// ---------------- fused LayerNorm + hi/lo emit ----------------
__global__ __launch_bounds__(256) void ln_hilo_kernel(const float* __restrict__ X,
                                                      const float* __restrict__ gma,
                                                      const float* __restrict__ bta,
                                                      __nv_bfloat16* __restrict__ Ho,
                                                      __nv_bfloat16* __restrict__ Lo) {
    int row = blockIdx.x;
    int tid = threadIdx.x;
    const float4* xr = (const float4*)(X + (size_t)row * DMODEL);
    float4 x4 = xr[tid];
    float s  = x4.x + x4.y + x4.z + x4.w;
    float ss = x4.x*x4.x + x4.y*x4.y + x4.z*x4.z + x4.w*x4.w;
#pragma unroll
    for (int off = 16; off > 0; off >>= 1) {
        s  += __shfl_xor_sync(0xffffffffu, s,  off);
        ss += __shfl_xor_sync(0xffffffffu, ss, off);
    }
    __shared__ float red[16];
    int lane = tid & 31, wid = tid >> 5;
    if (lane == 0) { red[wid] = s; red[8 + wid] = ss; }
    __syncthreads();
    float tot = 0.f, tot2 = 0.f;
#pragma unroll
    for (int i = 0; i < 8; i++) { tot += red[i]; tot2 += red[8 + i]; }
    const float inv = 1.0f / (float)DMODEL;
    float mu  = tot * inv;
    float var = tot2 * inv - mu * mu;
    float rs  = rsqrtf(var + 1e-5f);
    float4 gv = ((const float4*)gma)[tid];
    float4 bv = ((const float4*)bta)[tid];
    float o0 = (x4.x - mu) * rs * gv.x + bv.x;
    float o1 = (x4.y - mu) * rs * gv.y + bv.y;
    float o2 = (x4.z - mu) * rs * gv.z + bv.z;
    float o3 = (x4.w - mu) * rs * gv.w + bv.w;
    union { __nv_bfloat16 b[4]; uint2 u; } ph, pl;
    split_hilo(o0, ph.b[0], pl.b[0]);
    split_hilo(o1, ph.b[1], pl.b[1]);
    split_hilo(o2, ph.b[2], pl.b[2]);
    split_hilo(o3, ph.b[3], pl.b[3]);
    size_t base = (size_t)row * DMODEL + tid * 4;
    *(uint2*)(Ho + base) = ph.u;
    *(uint2*)(Lo + base) = pl.u;
}

// ---------------- elementwise fp32 -> bf16 hi/lo (ctx K/V path) ----------------
__global__ __launch_bounds__(256) void hilo_kernel(const float* __restrict__ X,
                                                   __nv_bfloat16* __restrict__ Ho,
                                                   __nv_bfloat16* __restrict__ Lo) {
    size_t idx = (size_t)blockIdx.x * 256 + threadIdx.x;
    float4 v = ((const float4*)X)[idx];
    union { __nv_bfloat16 b[4]; uint2 u; } ph, pl;
    split_hilo(v.x, ph.b[0], pl.b[0]);
    split_hilo(v.y, ph.b[1], pl.b[1]);
    split_hilo(v.z, ph.b[2], pl.b[2]);
    split_hilo(v.w, ph.b[3], pl.b[3]);
    *(uint2*)(Ho + idx * 4) = ph.u;
    *(uint2*)(Lo + idx * 4) = pl.u;
}

// ---------------- weight convert + transpose: W[K,N] fp32 -> Ht/Lt[N,K] bf16 ----------------
__global__ __launch_bounds__(256) void tconv_kernel(const float* __restrict__ W,
                                                    __nv_bfloat16* __restrict__ Ht,
                                                    __nv_bfloat16* __restrict__ Lt,
                                                    int K, int N) {
    __shared__ float s[32][33];
    int tx = threadIdx.x, ty = threadIdx.y;
    int n0 = blockIdx.x * 32, k0 = blockIdx.y * 32;
#pragma unroll
    for (int i = 0; i < 4; i++)
        s[ty + 8 * i][tx] = W[(size_t)(k0 + ty + 8 * i) * N + n0 + tx];
    __syncthreads();
#pragma unroll
    for (int i = 0; i < 4; i++) {
        int n = ty + 8 * i, k = tx;
        float v = s[k][n];
        __nv_bfloat16 h, l;
        split_hilo(v, h, l);
        size_t off = (size_t)(n0 + n) * K + k0 + k;
        Ht[off] = h;
        Lt[off] = l;
    }
}

// ---------------- bf16x3 GEMM via mma.sync (3-pass terms, 3-stage cp.async) ----------------
#define GSTAGE 16384
#define GEMM_SMEM (3 * GSTAGE)

__global__ __launch_bounds__(256) void gemm_mma_kernel(const __nv_bfloat16* __restrict__ Ah,
                                                       const __nv_bfloat16* __restrict__ Al,
                                                       const __nv_bfloat16* __restrict__ Bh,
                                                       const __nv_bfloat16* __restrict__ Bl,
                                                       float* __restrict__ C,
                                                       int M, int N, int K,
                                                       const float* __restrict__ bias,
                                                       const float* __restrict__ resid,
                                                       __nv_bfloat16* __restrict__ CH,
                                                       __nv_bfloat16* __restrict__ CL) {
    extern __shared__ char gsm[];
    uint32_t sbase = smem_to_u32(gsm);
    int tid = threadIdx.x;
    int warp = tid >> 5, lane = tid & 31;
    int wm = (warp & 1) * 64, wn = (warp >> 1) * 32;
    int row0 = blockIdx.y * 128, col0 = blockIdx.x * 128;

    const __nv_bfloat16* Aterm[3] = { Ah, Ah, Al };
    const __nv_bfloat16* Bterm[3] = { Bh, Bl, Bh };
    const int nk = K / 32;
    const int total = 3 * nk;

    float acc[4][4][4];
#pragma unroll
    for (int mi = 0; mi < 4; mi++)
#pragma unroll
        for (int ni = 0; ni < 4; ni++)
#pragma unroll
            for (int e = 0; e < 4; e++) acc[mi][ni][e] = 0.f;

    auto load_stage = [&](int buf, int idx) {
        int t  = idx / nk;
        int k0 = (idx % nk) * 32;
        const __nv_bfloat16* Ap = Aterm[t];
        const __nv_bfloat16* Bp = Bterm[t];
        uint32_t so = sbase + buf * GSTAGE;
#pragma unroll
        for (int i = 0; i < 2; i++) {
            int lci = tid + i * 256;
            int r = lci >> 2, c = lci & 3;
            uint32_t doff = (uint32_t)(r * 64 + ((c ^ ((r >> 1) & 3)) * 16));
            CP_ASYNC16(so + doff,        Ap + (size_t)(row0 + r) * K + k0 + c * 8);
            CP_ASYNC16(so + 8192 + doff, Bp + (size_t)(col0 + r) * K + k0 + c * 8);
        }
        CP_COMMIT();
    };

    load_stage(0, 0);
    load_stage(1, 1);

    int buf = 0;
    for (int it = 0; it < total; it++) {
        if (it + 1 < total) { CP_WAIT1(); } else { CP_WAIT0(); }
        __syncthreads();
        if (it + 2 < total) {
            int nb3 = buf + 2; if (nb3 >= 3) nb3 -= 3;
            load_stage(nb3, it + 2);
        }
        uint32_t abase = sbase + buf * GSTAGE;
        uint32_t bbase = abase + 8192;
#pragma unroll
        for (int kk = 0; kk < 2; kk++) {
            uint32_t afr[4][4];
#pragma unroll
            for (int mi = 0; mi < 4; mi++) {
                int r = wm + mi * 16 + (lane & 15);
                int c = kk * 2 + (lane >> 4);
                uint32_t addr = abase + r * 64 + (uint32_t)((c ^ ((r >> 1) & 3)) * 16);
                LDSM_X4(afr[mi][0], afr[mi][1], afr[mi][2], afr[mi][3], addr);
            }
            uint32_t bfr[2][4];
#pragma unroll
            for (int nb = 0; nb < 2; nb++) {
                int r = wn + nb * 16 + (lane & 15);
                int c = kk * 2 + (lane >> 4);
                uint32_t addr = bbase + r * 64 + (uint32_t)((c ^ ((r >> 1) & 3)) * 16);
                LDSM_X4(bfr[nb][0], bfr[nb][1], bfr[nb][2], bfr[nb][3], addr);
            }
#pragma unroll
            for (int mi = 0; mi < 4; mi++)
#pragma unroll
                for (int nb = 0; nb < 2; nb++) {
                    MMA16816(acc[mi][nb * 2 + 0], afr[mi], bfr[nb][0], bfr[nb][2]);
                    MMA16816(acc[mi][nb * 2 + 1], afr[mi], bfr[nb][1], bfr[nb][3]);
                }
        }
        buf++; if (buf >= 3) buf -= 3;
    }

    // epilogue
    int grow = row0 + wm;
    int gcol = col0 + wn;
#pragma unroll
    for (int mi = 0; mi < 4; mi++)
#pragma unroll
        for (int ni = 0; ni < 4; ni++) {
            int r  = grow + mi * 16 + (lane >> 2);
            int cc = gcol + ni * 8 + (lane & 3) * 2;
            float2 v0 = make_float2(acc[mi][ni][0], acc[mi][ni][1]);
            float2 v1 = make_float2(acc[mi][ni][2], acc[mi][ni][3]);
            if (bias) {
                float2 b2 = *(const float2*)(bias + cc);
                v0.x += b2.x; v0.y += b2.y;
                v1.x += b2.x; v1.y += b2.y;
            }
            if (resid) {
                float2 r0 = *(const float2*)(resid + (size_t)r * N + cc);
                float2 r1 = *(const float2*)(resid + (size_t)(r + 8) * N + cc);
                v0.x += r0.x; v0.y += r0.y;
                v1.x += r1.x; v1.y += r1.y;
            }
            if (CH) {
                __nv_bfloat16 h0, l0, h1, l1;
                split_hilo(v0.x, h0, l0); split_hilo(v0.y, h1, l1);
                *(uint32_t*)(CH + (size_t)r * N + cc) = pack_bf2(h0, h1);
                *(uint32_t*)(CL + (size_t)r * N + cc) = pack_bf2(l0, l1);
                split_hilo(v1.x, h0, l0); split_hilo(v1.y, h1, l1);
                *(uint32_t*)(CH + (size_t)(r + 8) * N + cc) = pack_bf2(h0, h1);
                *(uint32_t*)(CL + (size_t)(r + 8) * N + cc) = pack_bf2(l0, l1);
            } else {
                *(float2*)(C + (size_t)r * N + cc) = v0;
                *(float2*)(C + (size_t)(r + 8) * N + cc) = v1;
            }
        }
}

// ---------------- fp32 GEMM (small ctx projections only) ----------------
__global__ __launch_bounds__(256) void gemm_kernel(const float* __restrict__ A,
                                                   const float* __restrict__ B,
                                                   float* __restrict__ C,
                                                   int M, int N, int K) {
    __shared__ float As[16][128];
    __shared__ float Bs[16][128];
    int tid = threadIdx.x;
    int tx = tid & 15, ty = tid >> 4;
    int row0 = blockIdx.y * 128, col0 = blockIdx.x * 128;
    float acc[8][8];
#pragma unroll
    for (int i = 0; i < 8; i++)
#pragma unroll
        for (int j = 0; j < 8; j++) acc[i][j] = 0.f;

    for (int k0 = 0; k0 < K; k0 += 16) {
#pragma unroll
        for (int i = 0; i < 2; i++) {
            int idx = tid * 2 + i;
            int r = idx >> 2, kc = idx & 3;
            int gr = row0 + r;
            float4 f = make_float4(0.f, 0.f, 0.f, 0.f);
            if (gr < M) f = *(const float4*)(A + (size_t)gr * K + k0 + kc * 4);
            As[kc * 4 + 0][r] = f.x;
            As[kc * 4 + 1][r] = f.y;
            As[kc * 4 + 2][r] = f.z;
            As[kc * 4 + 3][r] = f.w;
        }
#pragma unroll
        for (int i = 0; i < 2; i++) {
            int idx = tid * 2 + i;
            int kb = idx >> 5, nc = idx & 31;
            float4 f = *(const float4*)(B + (size_t)(k0 + kb) * N + col0 + nc * 4);
            *(float4*)&Bs[kb][nc * 4] = f;
        }
        __syncthreads();
#pragma unroll
        for (int kk = 0; kk < 16; kk++) {
            float a[8], bb[8];
            *(float4*)&a[0]  = *(float4*)&As[kk][ty * 8];
            *(float4*)&a[4]  = *(float4*)&As[kk][ty * 8 + 4];
            *(float4*)&bb[0] = *(float4*)&Bs[kk][tx * 4];
            *(float4*)&bb[4] = *(float4*)&Bs[kk][64 + tx * 4];
#pragma unroll
            for (int i = 0; i < 8; i++)
#pragma unroll
                for (int j = 0; j < 8; j++) acc[i][j] += a[i] * bb[j];
        }
        __syncthreads();
    }
#pragma unroll
    for (int i = 0; i < 8; i++) {
        int gr = row0 + ty * 8 + i;
        if (gr >= M) continue;
#pragma unroll
        for (int half = 0; half < 2; half++) {
            int gc = col0 + half * 64 + tx * 4;
            float4 r4;
            r4.x = acc[i][half * 4 + 0];
            r4.y = acc[i][half * 4 + 1];
            r4.z = acc[i][half * 4 + 2];
            r4.w = acc[i][half * 4 + 3];
            *(float4*)(C + (size_t)gr * N + gc) = r4;
        }
    }
}

// ---------------- MMA flash attention (strided Q/KV) ----------------
#define AQ_H 0
#define AQ_L 16384
#define AK_H 32768
#define AK_L 40960
#define AV_H 49152
#define AV_L 57344
#define ATT_SMEM 65536

__device__ __forceinline__ uint32_t att_sw(int r, int c) {
    return (uint32_t)(r * 128 + ((c ^ (r & 7)) << 4));
}

__global__ __launch_bounds__(256) void attn_mma_kernel(
    const __nv_bfloat16* __restrict__ Qh, const __nv_bfloat16* __restrict__ Ql,
    const __nv_bfloat16* __restrict__ Kp_h, const __nv_bfloat16* __restrict__ Kp_l,
    const __nv_bfloat16* __restrict__ Vh, const __nv_bfloat16* __restrict__ Vl,
    __nv_bfloat16* __restrict__ Oh, __nv_bfloat16* __restrict__ Ol,
    int qlen, int kvlen, int qstride, int kvstride)
{
    extern __shared__ char smc[];
    uint32_t sb = smem_to_u32(smc);
    int b = blockIdx.z, h = blockIdx.y, qt = blockIdx.x;
    int tid = threadIdx.x, warp = tid >> 5, lane = tid & 31;
    int qrow0 = qt * 128;
    size_t qbase  = ((size_t)b * qlen + qrow0) * qstride + h * DHEAD;
    size_t kvbase = ((size_t)b * kvlen) * kvstride + h * DHEAD;

#pragma unroll
    for (int i = 0; i < 4; i++) {
        int idx = tid + i * 256;
        int r = idx >> 3, c = idx & 7;
        uint4 vh4 = *(const uint4*)(Qh + qbase + (size_t)r * qstride + c * 8);
        uint4 vl4 = *(const uint4*)(Ql + qbase + (size_t)r * qstride + c * 8);
        *(uint4*)(smc + AQ_H + att_sw(r, c)) = vh4;
        *(uint4*)(smc + AQ_L + att_sw(r, c)) = vl4;
    }
    __syncthreads();

    uint32_t qfh[4][4], qfl[4][4];
    {
        int r = warp * 16 + (lane & 15);
#pragma unroll
        for (int kk = 0; kk < 4; kk++) {
            int c = kk * 2 + (lane >> 4);
            LDSM_X4(qfh[kk][0], qfh[kk][1], qfh[kk][2], qfh[kk][3], sb + AQ_H + att_sw(r, c));
            LDSM_X4(qfl[kk][0], qfl[kk][1], qfl[kk][2], qfl[kk][3], sb + AQ_L + att_sw(r, c));
        }
    }

    float m_a = -1e30f, m_b = -1e30f, l_a = 0.f, l_b = 0.f;
    float acc_o[8][4];
#pragma unroll
    for (int t = 0; t < 8; t++)
#pragma unroll
        for (int e = 0; e < 4; e++) acc_o[t][e] = 0.f;

    int ntiles = (kvlen + 63) >> 6;
    for (int kt = 0; kt < ntiles; kt++) {
#pragma unroll
        for (int i = 0; i < 2; i++) {
            int idx = tid + i * 256;
            int r = idx >> 3, c = idx & 7;
            int kr = kt * 64 + r;
            uint4 kh4 = make_uint4(0, 0, 0, 0), kl4 = kh4;
            if (kr < kvlen) {
                kh4 = *(const uint4*)(Kp_h + kvbase + (size_t)kr * kvstride + c * 8);
                kl4 = *(const uint4*)(Kp_l + kvbase + (size_t)kr * kvstride + c * 8);
            }
            *(uint4*)(smc + AK_H + att_sw(r, c)) = kh4;
            *(uint4*)(smc + AK_L + att_sw(r, c)) = kl4;
        }
#pragma unroll
        for (int i = 0; i < 4; i++) {
            int idx = tid + i * 256;
            int r = idx >> 4, cg = idx & 15;
            int kr = kt * 64 + r;
            union { uint2 u; __nv_bfloat16 e[4]; } vhu, vlu;
            vhu.u = make_uint2(0, 0); vlu.u = make_uint2(0, 0);
            if (kr < kvlen) {
                vhu.u = *(const uint2*)(Vh + kvbase + (size_t)kr * kvstride + cg * 4);
                vlu.u = *(const uint2*)(Vl + kvbase + (size_t)kr * kvstride + cg * 4);
            }
#pragma unroll
            for (int j = 0; j < 4; j++) {
                int d = cg * 4 + j;
                uint32_t off = (uint32_t)(d * 128 + ((((r >> 3) ^ (d & 7))) << 4) + (r & 7) * 2);
                *(__nv_bfloat16*)(smc + AV_H + off) = vhu.e[j];
                *(__nv_bfloat16*)(smc + AV_L + off) = vlu.e[j];
            }
        }
        __syncthreads();

        float s[8][4];
#pragma unroll
        for (int t = 0; t < 8; t++)
#pragma unroll
            for (int e = 0; e < 4; e++) s[t][e] = 0.f;
#pragma unroll
        for (int kk = 0; kk < 4; kk++) {
#pragma unroll
            for (int nq = 0; nq < 4; nq++) {
                int r = nq * 16 + (lane & 15);
                int c = kk * 2 + (lane >> 4);
                uint32_t khf[4], klf[4];
                LDSM_X4(khf[0], khf[1], khf[2], khf[3], sb + AK_H + att_sw(r, c));
                LDSM_X4(klf[0], klf[1], klf[2], klf[3], sb + AK_L + att_sw(r, c));
                MMA16816(s[nq * 2 + 0], qfh[kk], khf[0], khf[2]);
                MMA16816(s[nq * 2 + 1], qfh[kk], khf[1], khf[3]);
                MMA16816(s[nq * 2 + 0], qfh[kk], klf[0], klf[2]);
                MMA16816(s[nq * 2 + 1], qfh[kk], klf[1], klf[3]);
                MMA16816(s[nq * 2 + 0], qfl[kk], khf[0], khf[2]);
                MMA16816(s[nq * 2 + 1], qfl[kk], khf[1], khf[3]);
            }
        }
        bool mtile = (kt == ntiles - 1) && (kvlen & 63);
#pragma unroll
        for (int t = 0; t < 8; t++)
#pragma unroll
            for (int e = 0; e < 4; e++) {
                float vv = s[t][e] * 0.125f;
                if (mtile) {
                    int col = kt * 64 + t * 8 + (lane & 3) * 2 + (e & 1);
                    if (col >= kvlen) vv = -1e30f;
                }
                s[t][e] = vv;
            }
        float mx_a = -1e30f, mx_b = -1e30f;
#pragma unroll
        for (int t = 0; t < 8; t++) {
            mx_a = fmaxf(mx_a, fmaxf(s[t][0], s[t][1]));
            mx_b = fmaxf(mx_b, fmaxf(s[t][2], s[t][3]));
        }
        mx_a = fmaxf(mx_a, __shfl_xor_sync(0xffffffffu, mx_a, 1));
        mx_a = fmaxf(mx_a, __shfl_xor_sync(0xffffffffu, mx_a, 2));
        mx_b = fmaxf(mx_b, __shfl_xor_sync(0xffffffffu, mx_b, 1));
        mx_b = fmaxf(mx_b, __shfl_xor_sync(0xffffffffu, mx_b, 2));
        float mn_a = fmaxf(m_a, mx_a), mn_b = fmaxf(m_b, mx_b);
        float al_a = __expf(m_a - mn_a), al_b = __expf(m_b - mn_b);
        m_a = mn_a; m_b = mn_b;
        float sum_a = 0.f, sum_b = 0.f;
#pragma unroll
        for (int t = 0; t < 8; t++) {
            s[t][0] = __expf(s[t][0] - m_a);
            s[t][1] = __expf(s[t][1] - m_a);
            s[t][2] = __expf(s[t][2] - m_b);
            s[t][3] = __expf(s[t][3] - m_b);
            sum_a += s[t][0] + s[t][1];
            sum_b += s[t][2] + s[t][3];
        }
        sum_a += __shfl_xor_sync(0xffffffffu, sum_a, 1);
        sum_a += __shfl_xor_sync(0xffffffffu, sum_a, 2);
        sum_b += __shfl_xor_sync(0xffffffffu, sum_b, 1);
        sum_b += __shfl_xor_sync(0xffffffffu, sum_b, 2);
        l_a = l_a * al_a + sum_a;
        l_b = l_b * al_b + sum_b;
#pragma unroll
        for (int t = 0; t < 8; t++) {
            acc_o[t][0] *= al_a; acc_o[t][1] *= al_a;
            acc_o[t][2] *= al_b; acc_o[t][3] *= al_b;
        }
#pragma unroll
        for (int kc = 0; kc < 4; kc++) {
            int t0 = kc * 2, t1 = t0 + 1;
            uint32_t pah[4], pal[4];
            {
                __nv_bfloat16 hb, lb, hb2, lb2;
                split_hilo(s[t0][0], hb, lb);  split_hilo(s[t0][1], hb2, lb2);
                pah[0] = pack_bf2(hb, hb2);    pal[0] = pack_bf2(lb, lb2);
                split_hilo(s[t0][2], hb, lb);  split_hilo(s[t0][3], hb2, lb2);
                pah[1] = pack_bf2(hb, hb2);    pal[1] = pack_bf2(lb, lb2);
                split_hilo(s[t1][0], hb, lb);  split_hilo(s[t1][1], hb2, lb2);
                pah[2] = pack_bf2(hb, hb2);    pal[2] = pack_bf2(lb, lb2);
                split_hilo(s[t1][2], hb, lb);  split_hilo(s[t1][3], hb2, lb2);
                pah[3] = pack_bf2(hb, hb2);    pal[3] = pack_bf2(lb, lb2);
            }
#pragma unroll
            for (int nd = 0; nd < 4; nd++) {
                int r = nd * 16 + (lane & 15);
                int c = kc * 2 + (lane >> 4);
                uint32_t vhf[4], vlf[4];
                LDSM_X4(vhf[0], vhf[1], vhf[2], vhf[3], sb + AV_H + att_sw(r, c));
                LDSM_X4(vlf[0], vlf[1], vlf[2], vlf[3], sb + AV_L + att_sw(r, c));
                MMA16816(acc_o[nd * 2 + 0], pah, vhf[0], vhf[2]);
                MMA16816(acc_o[nd * 2 + 1], pah, vhf[1], vhf[3]);
                MMA16816(acc_o[nd * 2 + 0], pah, vlf[0], vlf[2]);
                MMA16816(acc_o[nd * 2 + 1], pah, vlf[1], vlf[3]);
                MMA16816(acc_o[nd * 2 + 0], pal, vhf[0], vhf[2]);
                MMA16816(acc_o[nd * 2 + 1], pal, vhf[1], vhf[3]);
            }
        }
        __syncthreads();
    }

    float inv_a = 1.0f / l_a, inv_b = 1.0f / l_b;
    int row_a = qrow0 + warp * 16 + (lane >> 2);
    size_t ob = ((size_t)b * qlen) * DMODEL + h * DHEAD;
#pragma unroll
    for (int nd = 0; nd < 8; nd++) {
        int d0 = nd * 8 + (lane & 3) * 2;
        float a0 = acc_o[nd][0] * inv_a, a1 = acc_o[nd][1] * inv_a;
        float b0 = acc_o[nd][2] * inv_b, b1 = acc_o[nd][3] * inv_b;
        __nv_bfloat16 h0, l0, h1, l1;
        split_hilo(a0, h0, l0); split_hilo(a1, h1, l1);
        *(uint32_t*)(Oh + ob + (size_t)row_a * DMODEL + d0) = pack_bf2(h0, h1);
        *(uint32_t*)(Ol + ob + (size_t)row_a * DMODEL + d0) = pack_bf2(l0, l1);
        split_hilo(b0, h0, l0); split_hilo(b1, h1, l1);
        *(uint32_t*)(Oh + ob + (size_t)(row_a + 8) * DMODEL + d0) = pack_bf2(h0, h1);
        *(uint32_t*)(Ol + ob + (size_t)(row_a + 8) * DMODEL + d0) = pack_bf2(l0, l1);
    }
}

// ---------------- GeGLU + hi/lo emit ----------------
__global__ __launch_bounds__(256) void geglu_hilo_kernel(const float* __restrict__ Hb,
                                                         __nv_bfloat16* __restrict__ Ho,
                                                         __nv_bfloat16* __restrict__ Lo) {
    int row = blockIdx.y;
    int c = (blockIdx.x * 256 + threadIdx.x) * 4;
    const float* hr = Hb + (size_t)row * FFH;
    float4 u = *(const float4*)(hr + c);
    float4 g = *(const float4*)(hr + FFHALF + c);
    const float k = 0.70710678118654752f;
    float r0 = u.x * (0.5f * g.x * (1.f + erff(g.x * k)));
    float r1 = u.y * (0.5f * g.y * (1.f + erff(g.y * k)));
    float r2 = u.z * (0.5f * g.z * (1.f + erff(g.z * k)));
    float r3 = u.w * (0.5f * g.w * (1.f + erff(g.w * k)));
    union { __nv_bfloat16 b[4]; uint2 uu; } ph, pl;
    split_hilo(r0, ph.b[0], pl.b[0]);
    split_hilo(r1, ph.b[1], pl.b[1]);
    split_hilo(r2, ph.b[2], pl.b[2]);
    split_hilo(r3, ph.b[3], pl.b[3]);
    size_t base = (size_t)row * FFHALF + c;
    *(uint2*)(Ho + base) = ph.uu;
    *(uint2*)(Lo + base) = pl.uu;
}

// ---------------- launch ----------------
extern "C" void kernel_launch(void* const* d_in, const int* in_sizes, int n_in,
                              void* d_out, int out_size) {
    const float* x    = (const float*)d_in[0];
    const float* ctx  = (const float*)d_in[1];
    const float* ln1g = (const float*)d_in[2];
    const float* ln1b = (const float*)d_in[3];
    const float* ln2g = (const float*)d_in[4];
    const float* ln2b = (const float*)d_in[5];
    const float* ln3g = (const float*)d_in[6];
    const float* ln3b = (const float*)d_in[7];
    const float* a1wq = (const float*)d_in[8];
    const float* a1wk = (const float*)d_in[9];
    const float* a1wv = (const float*)d_in[10];
    const float* a1wo = (const float*)d_in[11];
    const float* a1bo = (const float*)d_in[12];
    const float* a2wq = (const float*)d_in[13];
    const float* a2wk = (const float*)d_in[14];
    const float* a2wv = (const float*)d_in[15];
    const float* a2wo = (const float*)d_in[16];
    const float* a2bo = (const float*)d_in[17];
    const float* ffw1 = (const float*)d_in[18];
    const float* ffb1 = (const float*)d_in[19];
    const float* ffw2 = (const float*)d_in[20];
    const float* ffb2 = (const float*)d_in[21];
    float* out = (float*)d_out;

    float *xa, *hbuf, *ct1, *ct2;
    __nv_bfloat16 *ah, *al, *bh, *bl, *qkvh, *qkvl, *qh, *ql, *kh, *kl, *vh, *vl, *oh, *ol;
    cudaGetSymbolAddress((void**)&xa,   g_xa);
    cudaGetSymbolAddress((void**)&hbuf, g_h);
    cudaGetSymbolAddress((void**)&ct1,  g_ctmp1);
    cudaGetSymbolAddress((void**)&ct2,  g_ctmp2);
    cudaGetSymbolAddress((void**)&ah, g_ah);
    cudaGetSymbolAddress((void**)&al, g_al);
    cudaGetSymbolAddress((void**)&bh, g_bh);
    cudaGetSymbolAddress((void**)&bl, g_bl);
    cudaGetSymbolAddress((void**)&qkvh, g_qkvh);
    cudaGetSymbolAddress((void**)&qkvl, g_qkvl);
    cudaGetSymbolAddress((void**)&qh, g_qh);
    cudaGetSymbolAddress((void**)&ql, g_ql);
    cudaGetSymbolAddress((void**)&kh, g_kh);
    cudaGetSymbolAddress((void**)&kl, g_kl);
    cudaGetSymbolAddress((void**)&vh, g_vh);
    cudaGetSymbolAddress((void**)&vl, g_vl);
    cudaGetSymbolAddress((void**)&oh, g_oh);
    cudaGetSymbolAddress((void**)&ol, g_ol);

    cudaFuncSetAttribute(attn_mma_kernel, cudaFuncAttributeMaxDynamicSharedMemorySize, ATT_SMEM);
    cudaFuncSetAttribute(gemm_mma_kernel, cudaFuncAttributeMaxDynamicSharedMemorySize, GEMM_SMEM);

    dim3 blk(256);
    dim3 tblk(32, 8);
    dim3 tc1024(DMODEL / 128, MROWS / 128);          // (8, 64)
    dim3 tcQKV(QKVN / 128, MROWS / 128);             // (24, 64)
    dim3 tcFF1(FFH / 128, MROWS / 128);              // (64, 64)
    dim3 gemmCtx(DMODEL / 128, (CTXROWS + 127) / 128);
    dim3 attng(SEQ / 128, NHEAD, 4);
    dim3 tg1024(DMODEL / 32, DMODEL / 32);
    dim3 tgFF1(FFH / 32, DMODEL / 32);
    dim3 tgFF2(DMODEL / 32, FFHALF / 32);

    // --- self attention ---
    ln_hilo_kernel<<<MROWS, blk>>>(x, ln1g, ln1b, ah, al);                              // 0
    tconv_kernel<<<tg1024, tblk>>>(a1wq, bh + OW_QKV_Q, bl + OW_QKV_Q, DMODEL, DMODEL); // 1
    tconv_kernel<<<tg1024, tblk>>>(a1wk, bh + OW_QKV_K, bl + OW_QKV_K, DMODEL, DMODEL); // 2
    tconv_kernel<<<tg1024, tblk>>>(a1wv, bh + OW_QKV_V, bl + OW_QKV_V, DMODEL, DMODEL); // 3
    tconv_kernel<<<tg1024, tblk>>>(a1wo, bh + OW_O1,    bl + OW_O1,    DMODEL, DMODEL); // 4
    gemm_mma_kernel<<<tcQKV, blk, GEMM_SMEM>>>(ah, al, bh, bl, nullptr,                  // 5 (ncu target)
        MROWS, QKVN, DMODEL, nullptr, nullptr, qkvh, qkvl);
    attn_mma_kernel<<<attng, blk, ATT_SMEM>>>(qkvh, qkvl,
        qkvh + DMODEL, qkvl + DMODEL, qkvh + 2 * DMODEL, qkvl + 2 * DMODEL,
        oh, ol, SEQ, SEQ, QKVN, QKVN);
    gemm_mma_kernel<<<tc1024, blk, GEMM_SMEM>>>(oh, ol, bh + OW_O1, bl + OW_O1, xa,
        MROWS, DMODEL, DMODEL, a1bo, x, nullptr, nullptr);

    // --- cross attention ---
    ln_hilo_kernel<<<MROWS, blk>>>(xa, ln2g, ln2b, ah, al);
    tconv_kernel<<<tg1024, tblk>>>(a2wq, bh, bl, DMODEL, DMODEL);
    gemm_mma_kernel<<<tc1024, blk, GEMM_SMEM>>>(ah, al, bh, bl, nullptr,
        MROWS, DMODEL, DMODEL, nullptr, nullptr, qh, ql);
    gemm_kernel<<<gemmCtx, blk>>>(ctx, a2wk, ct1, CTXROWS, DMODEL, CTXDIM);
    hilo_kernel<<<CTXROWS, blk>>>(ct1, kh, kl);
    gemm_kernel<<<gemmCtx, blk>>>(ctx, a2wv, ct2, CTXROWS, DMODEL, CTXDIM);
    hilo_kernel<<<CTXROWS, blk>>>(ct2, vh, vl);
    attn_mma_kernel<<<attng, blk, ATT_SMEM>>>(qh, ql, kh, kl, vh, vl,
        oh, ol, SEQ, CTXLEN, DMODEL, DMODEL);
    tconv_kernel<<<tg1024, tblk>>>(a2wo, bh, bl, DMODEL, DMODEL);
    gemm_mma_kernel<<<tc1024, blk, GEMM_SMEM>>>(oh, ol, bh, bl, xa,
        MROWS, DMODEL, DMODEL, a2bo, xa, nullptr, nullptr);

    // --- GeGLU feed-forward ---
    ln_hilo_kernel<<<MROWS, blk>>>(xa, ln3g, ln3b, ah, al);
    tconv_kernel<<<tgFF1, tblk>>>(ffw1, bh, bl, DMODEL, FFH);
    gemm_mma_kernel<<<tcFF1, blk, GEMM_SMEM>>>(ah, al, bh, bl, hbuf,
        MROWS, FFH, DMODEL, ffb1, nullptr, nullptr, nullptr);
    geglu_hilo_kernel<<<dim3(FFHALF / 1024, MROWS), blk>>>(hbuf, ah, al);
    tconv_kernel<<<tgFF2, tblk>>>(ffw2, bh, bl, FFHALF, DMODEL);
    gemm_mma_kernel<<<tc1024, blk, GEMM_SMEM>>>(ah, al, bh, bl, out,
        MROWS, DMODEL, FFHALF, ffb2, xa, nullptr, nullptr);
}

// round 13
// speedup vs baseline: 1.4767x; 1.0273x over previous
#include <cuda_runtime.h>
#include <cuda_bf16.h>
#include <math.h>
#include <cstdint>

// ---------------- problem constants ----------------
#define MROWS   8192        // B*S
#define DMODEL  1024
#define NHEAD   16
#define DHEAD   64
#define SEQ     2048
#define CTXROWS 308         // B*77
#define CTXLEN  77
#define CTXDIM  768
#define FFH     8192
#define FFHALF  4096
#define QKVN    3072

// weight sub-offsets inside g_bh/g_bl (elements)
#define OW_QKV_Q 0
#define OW_QKV_K (1024*1024)
#define OW_QKV_V (2*1024*1024)
#define OW_O1    (3*1024*1024)

// ---------------- scratch (static device globals; no runtime alloc) ----------------
__device__ float g_xa[MROWS * DMODEL];
__device__ float g_ctmp1[CTXROWS * DMODEL];
__device__ float g_ctmp2[CTXROWS * DMODEL];
__device__ __nv_bfloat16 g_hh[(size_t)MROWS * FFH];      // FF1 out hi
__device__ __nv_bfloat16 g_hl[(size_t)MROWS * FFH];      // FF1 out lo
__device__ __nv_bfloat16 g_ah[(size_t)MROWS * FFHALF];   // activation hi
__device__ __nv_bfloat16 g_al[(size_t)MROWS * FFHALF];   // activation lo
__device__ __nv_bfloat16 g_bh[(size_t)FFH * DMODEL];     // weights hi ([N,K], region-offset)
__device__ __nv_bfloat16 g_bl[(size_t)FFH * DMODEL];     // weights lo
__device__ __nv_bfloat16 g_qkvh[(size_t)MROWS * QKVN];   // fused QKV hi
__device__ __nv_bfloat16 g_qkvl[(size_t)MROWS * QKVN];   // fused QKV lo
__device__ __nv_bfloat16 g_qh[MROWS * DMODEL];           // cross-attn Q hi
__device__ __nv_bfloat16 g_ql[MROWS * DMODEL];
__device__ __nv_bfloat16 g_kh[MROWS * DMODEL];           // ctx K hi
__device__ __nv_bfloat16 g_kl[MROWS * DMODEL];
__device__ __nv_bfloat16 g_vh[MROWS * DMODEL];           // ctx V hi
__device__ __nv_bfloat16 g_vl[MROWS * DMODEL];
__device__ __nv_bfloat16 g_oh[MROWS * DMODEL];
__device__ __nv_bfloat16 g_ol[MROWS * DMODEL];

// ---------------- PTX helpers ----------------
__device__ __forceinline__ uint32_t smem_to_u32(const void* p) {
    uint32_t a;
    asm("{ .reg .u64 t; cvta.to.shared.u64 t, %1; cvt.u32.u64 %0, t; }" : "=r"(a) : "l"(p));
    return a;
}
#define CP_ASYNC16(dst, src) \
    asm volatile("cp.async.cg.shared.global [%0], [%1], 16;" :: "r"(dst), "l"(src))
#define CP_COMMIT() asm volatile("cp.async.commit_group;")
#define CP_WAIT0()  asm volatile("cp.async.wait_group 0;")
#define CP_WAIT1()  asm volatile("cp.async.wait_group 1;")
#define LDSM_X4(r0, r1, r2, r3, addr) \
    asm volatile("ldmatrix.sync.aligned.m8n8.x4.shared.b16 {%0,%1,%2,%3}, [%4];" \
        : "=r"(r0), "=r"(r1), "=r"(r2), "=r"(r3) : "r"(addr))
#define LDSM_X4_TRANS(r0, r1, r2, r3, addr) \
    asm volatile("ldmatrix.sync.aligned.m8n8.x4.trans.shared.b16 {%0,%1,%2,%3}, [%4];" \
        : "=r"(r0), "=r"(r1), "=r"(r2), "=r"(r3) : "r"(addr))
#define MMA16816(d, a, b0, b1) \
    asm volatile("mma.sync.aligned.m16n8k16.row.col.f32.bf16.bf16.f32 " \
        "{%0,%1,%2,%3}, {%4,%5,%6,%7}, {%8,%9}, {%0,%1,%2,%3};" \
        : "+f"((d)[0]), "+f"((d)[1]), "+f"((d)[2]), "+f"((d)[3]) \
        : "r"((a)[0]), "r"((a)[1]), "r"((a)[2]), "r"((a)[3]), "r"(b0), "r"(b1))

// ---------------- hi/lo split helpers ----------------
__device__ __forceinline__ void split_hilo(float x, __nv_bfloat16& h, __nv_bfloat16& l) {
    h = __float2bfloat16(x);
    l = __float2bfloat16(x - __bfloat162float(h));
}
__device__ __forceinline__ uint32_t pack_bf2(__nv_bfloat16 lo, __nv_bfloat16 hi) {
    __nv_bfloat162 t; t.x = lo; t.y = hi;
    return *(uint32_t*)&t;
}

// ---------------- fused LayerNorm + hi/lo emit ----------------
__global__ __launch_bounds__(256) void ln_hilo_kernel(const float* __restrict__ X,
                                                      const float* __restrict__ gma,
                                                      const float* __restrict__ bta,
                                                      __nv_bfloat16* __restrict__ Ho,
                                                      __nv_bfloat16* __restrict__ Lo) {
    int row = blockIdx.x;
    int tid = threadIdx.x;
    const float4* xr = (const float4*)(X + (size_t)row * DMODEL);
    float4 x4 = xr[tid];
    float s  = x4.x + x4.y + x4.z + x4.w;
    float ss = x4.x*x4.x + x4.y*x4.y + x4.z*x4.z + x4.w*x4.w;
#pragma unroll
    for (int off = 16; off > 0; off >>= 1) {
        s  += __shfl_xor_sync(0xffffffffu, s,  off);
        ss += __shfl_xor_sync(0xffffffffu, ss, off);
    }
    __shared__ float red[16];
    int lane = tid & 31, wid = tid >> 5;
    if (lane == 0) { red[wid] = s; red[8 + wid] = ss; }
    __syncthreads();
    float tot = 0.f, tot2 = 0.f;
#pragma unroll
    for (int i = 0; i < 8; i++) { tot += red[i]; tot2 += red[8 + i]; }
    const float inv = 1.0f / (float)DMODEL;
    float mu  = tot * inv;
    float var = tot2 * inv - mu * mu;
    float rs  = rsqrtf(var + 1e-5f);
    float4 gv = ((const float4*)gma)[tid];
    float4 bv = ((const float4*)bta)[tid];
    float o0 = (x4.x - mu) * rs * gv.x + bv.x;
    float o1 = (x4.y - mu) * rs * gv.y + bv.y;
    float o2 = (x4.z - mu) * rs * gv.z + bv.z;
    float o3 = (x4.w - mu) * rs * gv.w + bv.w;
    union { __nv_bfloat16 b[4]; uint2 u; } ph, pl;
    split_hilo(o0, ph.b[0], pl.b[0]);
    split_hilo(o1, ph.b[1], pl.b[1]);
    split_hilo(o2, ph.b[2], pl.b[2]);
    split_hilo(o3, ph.b[3], pl.b[3]);
    size_t base = (size_t)row * DMODEL + tid * 4;
    *(uint2*)(Ho + base) = ph.u;
    *(uint2*)(Lo + base) = pl.u;
}

// ---------------- elementwise fp32 -> bf16 hi/lo (ctx K/V path) ----------------
__global__ __launch_bounds__(256) void hilo_kernel(const float* __restrict__ X,
                                                   __nv_bfloat16* __restrict__ Ho,
                                                   __nv_bfloat16* __restrict__ Lo) {
    size_t idx = (size_t)blockIdx.x * 256 + threadIdx.x;
    float4 v = ((const float4*)X)[idx];
    union { __nv_bfloat16 b[4]; uint2 u; } ph, pl;
    split_hilo(v.x, ph.b[0], pl.b[0]);
    split_hilo(v.y, ph.b[1], pl.b[1]);
    split_hilo(v.z, ph.b[2], pl.b[2]);
    split_hilo(v.w, ph.b[3], pl.b[3]);
    *(uint2*)(Ho + idx * 4) = ph.u;
    *(uint2*)(Lo + idx * 4) = pl.u;
}

// ---------------- weight convert + transpose: W[K,N] fp32 -> Ht/Lt[N,K] bf16 ----------------
__global__ __launch_bounds__(256) void tconv_kernel(const float* __restrict__ W,
                                                    __nv_bfloat16* __restrict__ Ht,
                                                    __nv_bfloat16* __restrict__ Lt,
                                                    int K, int N) {
    __shared__ float s[32][33];
    int tx = threadIdx.x, ty = threadIdx.y;
    int n0 = blockIdx.x * 32, k0 = blockIdx.y * 32;
#pragma unroll
    for (int i = 0; i < 4; i++)
        s[ty + 8 * i][tx] = W[(size_t)(k0 + ty + 8 * i) * N + n0 + tx];
    __syncthreads();
#pragma unroll
    for (int i = 0; i < 4; i++) {
        int n = ty + 8 * i, k = tx;
        float v = s[k][n];
        __nv_bfloat16 h, l;
        split_hilo(v, h, l);
        size_t off = (size_t)(n0 + n) * K + k0 + k;
        Ht[off] = h;
        Lt[off] = l;
    }
}

// ---------------- bf16x3 GEMM via mma.sync (3-pass terms, 3-stage cp.async) ----------------
#define GSTAGE 16384
#define GEMM_SMEM (3 * GSTAGE)

__global__ __launch_bounds__(256) void gemm_mma_kernel(const __nv_bfloat16* __restrict__ Ah,
                                                       const __nv_bfloat16* __restrict__ Al,
                                                       const __nv_bfloat16* __restrict__ Bh,
                                                       const __nv_bfloat16* __restrict__ Bl,
                                                       float* __restrict__ C,
                                                       int M, int N, int K,
                                                       const float* __restrict__ bias,
                                                       const float* __restrict__ resid,
                                                       __nv_bfloat16* __restrict__ CH,
                                                       __nv_bfloat16* __restrict__ CL) {
    extern __shared__ char gsm[];
    uint32_t sbase = smem_to_u32(gsm);
    int tid = threadIdx.x;
    int warp = tid >> 5, lane = tid & 31;
    int wm = (warp & 1) * 64, wn = (warp >> 1) * 32;
    int row0 = blockIdx.y * 128, col0 = blockIdx.x * 128;

    const __nv_bfloat16* Aterm[3] = { Ah, Ah, Al };
    const __nv_bfloat16* Bterm[3] = { Bh, Bl, Bh };
    const int nk = K / 32;
    const int total = 3 * nk;

    float acc[4][4][4];
#pragma unroll
    for (int mi = 0; mi < 4; mi++)
#pragma unroll
        for (int ni = 0; ni < 4; ni++)
#pragma unroll
            for (int e = 0; e < 4; e++) acc[mi][ni][e] = 0.f;

    auto load_stage = [&](int buf, int idx) {
        int t  = idx / nk;
        int k0 = (idx % nk) * 32;
        const __nv_bfloat16* Ap = Aterm[t];
        const __nv_bfloat16* Bp = Bterm[t];
        uint32_t so = sbase + buf * GSTAGE;
#pragma unroll
        for (int i = 0; i < 2; i++) {
            int lci = tid + i * 256;
            int r = lci >> 2, c = lci & 3;
            uint32_t doff = (uint32_t)(r * 64 + ((c ^ ((r >> 1) & 3)) * 16));
            CP_ASYNC16(so + doff,        Ap + (size_t)(row0 + r) * K + k0 + c * 8);
            CP_ASYNC16(so + 8192 + doff, Bp + (size_t)(col0 + r) * K + k0 + c * 8);
        }
        CP_COMMIT();
    };

    load_stage(0, 0);
    load_stage(1, 1);

    int buf = 0;
    for (int it = 0; it < total; it++) {
        if (it + 1 < total) { CP_WAIT1(); } else { CP_WAIT0(); }
        __syncthreads();
        if (it + 2 < total) {
            int nb3 = buf + 2; if (nb3 >= 3) nb3 -= 3;
            load_stage(nb3, it + 2);
        }
        uint32_t abase = sbase + buf * GSTAGE;
        uint32_t bbase = abase + 8192;
#pragma unroll
        for (int kk = 0; kk < 2; kk++) {
            uint32_t afr[4][4];
#pragma unroll
            for (int mi = 0; mi < 4; mi++) {
                int r = wm + mi * 16 + (lane & 15);
                int c = kk * 2 + (lane >> 4);
                uint32_t addr = abase + r * 64 + (uint32_t)((c ^ ((r >> 1) & 3)) * 16);
                LDSM_X4(afr[mi][0], afr[mi][1], afr[mi][2], afr[mi][3], addr);
            }
            uint32_t bfr[2][4];
#pragma unroll
            for (int nb = 0; nb < 2; nb++) {
                int r = wn + nb * 16 + (lane & 15);
                int c = kk * 2 + (lane >> 4);
                uint32_t addr = bbase + r * 64 + (uint32_t)((c ^ ((r >> 1) & 3)) * 16);
                LDSM_X4(bfr[nb][0], bfr[nb][1], bfr[nb][2], bfr[nb][3], addr);
            }
#pragma unroll
            for (int mi = 0; mi < 4; mi++)
#pragma unroll
                for (int nb = 0; nb < 2; nb++) {
                    MMA16816(acc[mi][nb * 2 + 0], afr[mi], bfr[nb][0], bfr[nb][2]);
                    MMA16816(acc[mi][nb * 2 + 1], afr[mi], bfr[nb][1], bfr[nb][3]);
                }
        }
        buf++; if (buf >= 3) buf -= 3;
    }

    // epilogue
    int grow = row0 + wm;
    int gcol = col0 + wn;
#pragma unroll
    for (int mi = 0; mi < 4; mi++)
#pragma unroll
        for (int ni = 0; ni < 4; ni++) {
            int r  = grow + mi * 16 + (lane >> 2);
            int cc = gcol + ni * 8 + (lane & 3) * 2;
            float2 v0 = make_float2(acc[mi][ni][0], acc[mi][ni][1]);
            float2 v1 = make_float2(acc[mi][ni][2], acc[mi][ni][3]);
            if (bias) {
                float2 b2 = *(const float2*)(bias + cc);
                v0.x += b2.x; v0.y += b2.y;
                v1.x += b2.x; v1.y += b2.y;
            }
            if (resid) {
                float2 r0 = *(const float2*)(resid + (size_t)r * N + cc);
                float2 r1 = *(const float2*)(resid + (size_t)(r + 8) * N + cc);
                v0.x += r0.x; v0.y += r0.y;
                v1.x += r1.x; v1.y += r1.y;
            }
            if (CH) {
                __nv_bfloat16 h0, l0, h1, l1;
                split_hilo(v0.x, h0, l0); split_hilo(v0.y, h1, l1);
                *(uint32_t*)(CH + (size_t)r * N + cc) = pack_bf2(h0, h1);
                *(uint32_t*)(CL + (size_t)r * N + cc) = pack_bf2(l0, l1);
                split_hilo(v1.x, h0, l0); split_hilo(v1.y, h1, l1);
                *(uint32_t*)(CH + (size_t)(r + 8) * N + cc) = pack_bf2(h0, h1);
                *(uint32_t*)(CL + (size_t)(r + 8) * N + cc) = pack_bf2(l0, l1);
            } else {
                *(float2*)(C + (size_t)r * N + cc) = v0;
                *(float2*)(C + (size_t)(r + 8) * N + cc) = v1;
            }
        }
}

// ---------------- fp32 GEMM (small ctx projections only) ----------------
__global__ __launch_bounds__(256) void gemm_kernel(const float* __restrict__ A,
                                                   const float* __restrict__ B,
                                                   float* __restrict__ C,
                                                   int M, int N, int K) {
    __shared__ float As[16][128];
    __shared__ float Bs[16][128];
    int tid = threadIdx.x;
    int tx = tid & 15, ty = tid >> 4;
    int row0 = blockIdx.y * 128, col0 = blockIdx.x * 128;
    float acc[8][8];
#pragma unroll
    for (int i = 0; i < 8; i++)
#pragma unroll
        for (int j = 0; j < 8; j++) acc[i][j] = 0.f;

    for (int k0 = 0; k0 < K; k0 += 16) {
#pragma unroll
        for (int i = 0; i < 2; i++) {
            int idx = tid * 2 + i;
            int r = idx >> 2, kc = idx & 3;
            int gr = row0 + r;
            float4 f = make_float4(0.f, 0.f, 0.f, 0.f);
            if (gr < M) f = *(const float4*)(A + (size_t)gr * K + k0 + kc * 4);
            As[kc * 4 + 0][r] = f.x;
            As[kc * 4 + 1][r] = f.y;
            As[kc * 4 + 2][r] = f.z;
            As[kc * 4 + 3][r] = f.w;
        }
#pragma unroll
        for (int i = 0; i < 2; i++) {
            int idx = tid * 2 + i;
            int kb = idx >> 5, nc = idx & 31;
            float4 f = *(const float4*)(B + (size_t)(k0 + kb) * N + col0 + nc * 4);
            *(float4*)&Bs[kb][nc * 4] = f;
        }
        __syncthreads();
#pragma unroll
        for (int kk = 0; kk < 16; kk++) {
            float a[8], bb[8];
            *(float4*)&a[0]  = *(float4*)&As[kk][ty * 8];
            *(float4*)&a[4]  = *(float4*)&As[kk][ty * 8 + 4];
            *(float4*)&bb[0] = *(float4*)&Bs[kk][tx * 4];
            *(float4*)&bb[4] = *(float4*)&Bs[kk][64 + tx * 4];
#pragma unroll
            for (int i = 0; i < 8; i++)
#pragma unroll
                for (int j = 0; j < 8; j++) acc[i][j] += a[i] * bb[j];
        }
        __syncthreads();
    }
#pragma unroll
    for (int i = 0; i < 8; i++) {
        int gr = row0 + ty * 8 + i;
        if (gr >= M) continue;
#pragma unroll
        for (int half = 0; half < 2; half++) {
            int gc = col0 + half * 64 + tx * 4;
            float4 r4;
            r4.x = acc[i][half * 4 + 0];
            r4.y = acc[i][half * 4 + 1];
            r4.z = acc[i][half * 4 + 2];
            r4.w = acc[i][half * 4 + 3];
            *(float4*)(C + (size_t)gr * N + gc) = r4;
        }
    }
}

// ---------------- MMA flash attention (strided Q/KV, ldmatrix.trans for V) ----------------
#define AQ_H 0
#define AQ_L 16384
#define AK_H 32768
#define AK_L 40960
#define AV_H 49152
#define AV_L 57344
#define ATT_SMEM 65536

__device__ __forceinline__ uint32_t att_sw(int r, int c) {
    return (uint32_t)(r * 128 + ((c ^ (r & 7)) << 4));
}

__global__ __launch_bounds__(256) void attn_mma_kernel(
    const __nv_bfloat16* __restrict__ Qh, const __nv_bfloat16* __restrict__ Ql,
    const __nv_bfloat16* __restrict__ Kp_h, const __nv_bfloat16* __restrict__ Kp_l,
    const __nv_bfloat16* __restrict__ Vh, const __nv_bfloat16* __restrict__ Vl,
    __nv_bfloat16* __restrict__ Oh, __nv_bfloat16* __restrict__ Ol,
    int qlen, int kvlen, int qstride, int kvstride)
{
    extern __shared__ char smc[];
    uint32_t sb = smem_to_u32(smc);
    int b = blockIdx.z, h = blockIdx.y, qt = blockIdx.x;
    int tid = threadIdx.x, warp = tid >> 5, lane = tid & 31;
    int qrow0 = qt * 128;
    size_t qbase  = ((size_t)b * qlen + qrow0) * qstride + h * DHEAD;
    size_t kvbase = ((size_t)b * kvlen) * kvstride + h * DHEAD;

#pragma unroll
    for (int i = 0; i < 4; i++) {
        int idx = tid + i * 256;
        int r = idx >> 3, c = idx & 7;
        uint4 vh4 = *(const uint4*)(Qh + qbase + (size_t)r * qstride + c * 8);
        uint4 vl4 = *(const uint4*)(Ql + qbase + (size_t)r * qstride + c * 8);
        *(uint4*)(smc + AQ_H + att_sw(r, c)) = vh4;
        *(uint4*)(smc + AQ_L + att_sw(r, c)) = vl4;
    }
    __syncthreads();

    uint32_t qfh[4][4], qfl[4][4];
    {
        int r = warp * 16 + (lane & 15);
#pragma unroll
        for (int kk = 0; kk < 4; kk++) {
            int c = kk * 2 + (lane >> 4);
            LDSM_X4(qfh[kk][0], qfh[kk][1], qfh[kk][2], qfh[kk][3], sb + AQ_H + att_sw(r, c));
            LDSM_X4(qfl[kk][0], qfl[kk][1], qfl[kk][2], qfl[kk][3], sb + AQ_L + att_sw(r, c));
        }
    }

    float m_a = -1e30f, m_b = -1e30f, l_a = 0.f, l_b = 0.f;
    float acc_o[8][4];
#pragma unroll
    for (int t = 0; t < 8; t++)
#pragma unroll
        for (int e = 0; e < 4; e++) acc_o[t][e] = 0.f;

    int ntiles = (kvlen + 63) >> 6;
    for (int kt = 0; kt < ntiles; kt++) {
        // K and V tiles both row-major [kv][d], vectorized + swizzled, zero-padded
#pragma unroll
        for (int i = 0; i < 2; i++) {
            int idx = tid + i * 256;
            int r = idx >> 3, c = idx & 7;
            int kr = kt * 64 + r;
            uint4 kh4 = make_uint4(0, 0, 0, 0), kl4 = kh4, vh4 = kh4, vl4 = kh4;
            if (kr < kvlen) {
                size_t off = kvbase + (size_t)kr * kvstride + c * 8;
                kh4 = *(const uint4*)(Kp_h + off);
                kl4 = *(const uint4*)(Kp_l + off);
                vh4 = *(const uint4*)(Vh + off);
                vl4 = *(const uint4*)(Vl + off);
            }
            uint32_t sw = att_sw(r, c);
            *(uint4*)(smc + AK_H + sw) = kh4;
            *(uint4*)(smc + AK_L + sw) = kl4;
            *(uint4*)(smc + AV_H + sw) = vh4;
            *(uint4*)(smc + AV_L + sw) = vl4;
        }
        __syncthreads();

        float s[8][4];
#pragma unroll
        for (int t = 0; t < 8; t++)
#pragma unroll
            for (int e = 0; e < 4; e++) s[t][e] = 0.f;
#pragma unroll
        for (int kk = 0; kk < 4; kk++) {
#pragma unroll
            for (int nq = 0; nq < 4; nq++) {
                int r = nq * 16 + (lane & 15);
                int c = kk * 2 + (lane >> 4);
                uint32_t khf[4], klf[4];
                LDSM_X4(khf[0], khf[1], khf[2], khf[3], sb + AK_H + att_sw(r, c));
                LDSM_X4(klf[0], klf[1], klf[2], klf[3], sb + AK_L + att_sw(r, c));
                MMA16816(s[nq * 2 + 0], qfh[kk], khf[0], khf[2]);
                MMA16816(s[nq * 2 + 1], qfh[kk], khf[1], khf[3]);
                MMA16816(s[nq * 2 + 0], qfh[kk], klf[0], klf[2]);
                MMA16816(s[nq * 2 + 1], qfh[kk], klf[1], klf[3]);
                MMA16816(s[nq * 2 + 0], qfl[kk], khf[0], khf[2]);
                MMA16816(s[nq * 2 + 1], qfl[kk], khf[1], khf[3]);
            }
        }
        bool mtile = (kt == ntiles - 1) && (kvlen & 63);
#pragma unroll
        for (int t = 0; t < 8; t++)
#pragma unroll
            for (int e = 0; e < 4; e++) {
                float vv = s[t][e] * 0.125f;
                if (mtile) {
                    int col = kt * 64 + t * 8 + (lane & 3) * 2 + (e & 1);
                    if (col >= kvlen) vv = -1e30f;
                }
                s[t][e] = vv;
            }
        float mx_a = -1e30f, mx_b = -1e30f;
#pragma unroll
        for (int t = 0; t < 8; t++) {
            mx_a = fmaxf(mx_a, fmaxf(s[t][0], s[t][1]));
            mx_b = fmaxf(mx_b, fmaxf(s[t][2], s[t][3]));
        }
        mx_a = fmaxf(mx_a, __shfl_xor_sync(0xffffffffu, mx_a, 1));
        mx_a = fmaxf(mx_a, __shfl_xor_sync(0xffffffffu, mx_a, 2));
        mx_b = fmaxf(mx_b, __shfl_xor_sync(0xffffffffu, mx_b, 1));
        mx_b = fmaxf(mx_b, __shfl_xor_sync(0xffffffffu, mx_b, 2));
        float mn_a = fmaxf(m_a, mx_a), mn_b = fmaxf(m_b, mx_b);
        float al_a = __expf(m_a - mn_a), al_b = __expf(m_b - mn_b);
        m_a = mn_a; m_b = mn_b;
        float sum_a = 0.f, sum_b = 0.f;
#pragma unroll
        for (int t = 0; t < 8; t++) {
            s[t][0] = __expf(s[t][0] - m_a);
            s[t][1] = __expf(s[t][1] - m_a);
            s[t][2] = __expf(s[t][2] - m_b);
            s[t][3] = __expf(s[t][3] - m_b);
            sum_a += s[t][0] + s[t][1];
            sum_b += s[t][2] + s[t][3];
        }
        sum_a += __shfl_xor_sync(0xffffffffu, sum_a, 1);
        sum_a += __shfl_xor_sync(0xffffffffu, sum_a, 2);
        sum_b += __shfl_xor_sync(0xffffffffu, sum_b, 1);
        sum_b += __shfl_xor_sync(0xffffffffu, sum_b, 2);
        l_a = l_a * al_a + sum_a;
        l_b = l_b * al_b + sum_b;
#pragma unroll
        for (int t = 0; t < 8; t++) {
            acc_o[t][0] *= al_a; acc_o[t][1] *= al_a;
            acc_o[t][2] *= al_b; acc_o[t][3] *= al_b;
        }
        // PV: B fragments via ldmatrix.trans on row-major [kv][d] V tile
#pragma unroll
        for (int kc = 0; kc < 4; kc++) {
            int t0 = kc * 2, t1 = t0 + 1;
            uint32_t pah[4], pal[4];
            {
                __nv_bfloat16 hb, lb, hb2, lb2;
                split_hilo(s[t0][0], hb, lb);  split_hilo(s[t0][1], hb2, lb2);
                pah[0] = pack_bf2(hb, hb2);    pal[0] = pack_bf2(lb, lb2);
                split_hilo(s[t0][2], hb, lb);  split_hilo(s[t0][3], hb2, lb2);
                pah[1] = pack_bf2(hb, hb2);    pal[1] = pack_bf2(lb, lb2);
                split_hilo(s[t1][0], hb, lb);  split_hilo(s[t1][1], hb2, lb2);
                pah[2] = pack_bf2(hb, hb2);    pal[2] = pack_bf2(lb, lb2);
                split_hilo(s[t1][2], hb, lb);  split_hilo(s[t1][3], hb2, lb2);
                pah[3] = pack_bf2(hb, hb2);    pal[3] = pack_bf2(lb, lb2);
            }
#pragma unroll
            for (int nd = 0; nd < 4; nd++) {
                int r = kc * 16 + (lane & 15);
                int c = nd * 2 + (lane >> 4);
                uint32_t addr = sb + att_sw(r, c);
                uint32_t vhf[4], vlf[4];
                LDSM_X4_TRANS(vhf[0], vhf[1], vhf[2], vhf[3], addr + AV_H);
                LDSM_X4_TRANS(vlf[0], vlf[1], vlf[2], vlf[3], addr + AV_L);
                MMA16816(acc_o[nd * 2 + 0], pah, vhf[0], vhf[1]);
                MMA16816(acc_o[nd * 2 + 1], pah, vhf[2], vhf[3]);
                MMA16816(acc_o[nd * 2 + 0], pah, vlf[0], vlf[1]);
                MMA16816(acc_o[nd * 2 + 1], pah, vlf[2], vlf[3]);
                MMA16816(acc_o[nd * 2 + 0], pal, vhf[0], vhf[1]);
                MMA16816(acc_o[nd * 2 + 1], pal, vhf[2], vhf[3]);
            }
        }
        __syncthreads();
    }

    float inv_a = 1.0f / l_a, inv_b = 1.0f / l_b;
    int row_a = qrow0 + warp * 16 + (lane >> 2);
    size_t ob = ((size_t)b * qlen) * DMODEL + h * DHEAD;
#pragma unroll
    for (int nd = 0; nd < 8; nd++) {
        int d0 = nd * 8 + (lane & 3) * 2;
        float a0 = acc_o[nd][0] * inv_a, a1 = acc_o[nd][1] * inv_a;
        float b0 = acc_o[nd][2] * inv_b, b1 = acc_o[nd][3] * inv_b;
        __nv_bfloat16 h0, l0, h1, l1;
        split_hilo(a0, h0, l0); split_hilo(a1, h1, l1);
        *(uint32_t*)(Oh + ob + (size_t)row_a * DMODEL + d0) = pack_bf2(h0, h1);
        *(uint32_t*)(Ol + ob + (size_t)row_a * DMODEL + d0) = pack_bf2(l0, l1);
        split_hilo(b0, h0, l0); split_hilo(b1, h1, l1);
        *(uint32_t*)(Oh + ob + (size_t)(row_a + 8) * DMODEL + d0) = pack_bf2(h0, h1);
        *(uint32_t*)(Ol + ob + (size_t)(row_a + 8) * DMODEL + d0) = pack_bf2(l0, l1);
    }
}

// ---------------- GeGLU (bf16 hi/lo in) + hi/lo emit ----------------
__global__ __launch_bounds__(256) void geglu_hilo_kernel(const __nv_bfloat16* __restrict__ Hh,
                                                         const __nv_bfloat16* __restrict__ Hl,
                                                         __nv_bfloat16* __restrict__ Ho,
                                                         __nv_bfloat16* __restrict__ Lo) {
    int row = blockIdx.y;
    int c = (blockIdx.x * 256 + threadIdx.x) * 4;
    size_t ubase = (size_t)row * FFH + c;
    size_t gbase = ubase + FFHALF;
    union { uint2 u; __nv_bfloat16 e[4]; } uh, ul, gh, gl;
    uh.u = *(const uint2*)(Hh + ubase);
    ul.u = *(const uint2*)(Hl + ubase);
    gh.u = *(const uint2*)(Hh + gbase);
    gl.u = *(const uint2*)(Hl + gbase);
    const float kc = 0.70710678118654752f;
    union { __nv_bfloat16 b[4]; uint2 uu; } ph, pl;
#pragma unroll
    for (int j = 0; j < 4; j++) {
        float u = __bfloat162float(uh.e[j]) + __bfloat162float(ul.e[j]);
        float g = __bfloat162float(gh.e[j]) + __bfloat162float(gl.e[j]);
        float r = u * (0.5f * g * (1.f + erff(g * kc)));
        split_hilo(r, ph.b[j], pl.b[j]);
    }
    size_t base = (size_t)row * FFHALF + c;
    *(uint2*)(Ho + base) = ph.uu;
    *(uint2*)(Lo + base) = pl.uu;
}

// ---------------- launch ----------------
extern "C" void kernel_launch(void* const* d_in, const int* in_sizes, int n_in,
                              void* d_out, int out_size) {
    const float* x    = (const float*)d_in[0];
    const float* ctx  = (const float*)d_in[1];
    const float* ln1g = (const float*)d_in[2];
    const float* ln1b = (const float*)d_in[3];
    const float* ln2g = (const float*)d_in[4];
    const float* ln2b = (const float*)d_in[5];
    const float* ln3g = (const float*)d_in[6];
    const float* ln3b = (const float*)d_in[7];
    const float* a1wq = (const float*)d_in[8];
    const float* a1wk = (const float*)d_in[9];
    const float* a1wv = (const float*)d_in[10];
    const float* a1wo = (const float*)d_in[11];
    const float* a1bo = (const float*)d_in[12];
    const float* a2wq = (const float*)d_in[13];
    const float* a2wk = (const float*)d_in[14];
    const float* a2wv = (const float*)d_in[15];
    const float* a2wo = (const float*)d_in[16];
    const float* a2bo = (const float*)d_in[17];
    const float* ffw1 = (const float*)d_in[18];
    const float* ffb1 = (const float*)d_in[19];
    const float* ffw2 = (const float*)d_in[20];
    const float* ffb2 = (const float*)d_in[21];
    float* out = (float*)d_out;

    float *xa, *ct1, *ct2;
    __nv_bfloat16 *hh, *hl, *ah, *al, *bh, *bl, *qkvh, *qkvl, *qh, *ql, *kh, *kl, *vh, *vl, *oh, *ol;
    cudaGetSymbolAddress((void**)&xa,   g_xa);
    cudaGetSymbolAddress((void**)&ct1,  g_ctmp1);
    cudaGetSymbolAddress((void**)&ct2,  g_ctmp2);
    cudaGetSymbolAddress((void**)&hh, g_hh);
    cudaGetSymbolAddress((void**)&hl, g_hl);
    cudaGetSymbolAddress((void**)&ah, g_ah);
    cudaGetSymbolAddress((void**)&al, g_al);
    cudaGetSymbolAddress((void**)&bh, g_bh);
    cudaGetSymbolAddress((void**)&bl, g_bl);
    cudaGetSymbolAddress((void**)&qkvh, g_qkvh);
    cudaGetSymbolAddress((void**)&qkvl, g_qkvl);
    cudaGetSymbolAddress((void**)&qh, g_qh);
    cudaGetSymbolAddress((void**)&ql, g_ql);
    cudaGetSymbolAddress((void**)&kh, g_kh);
    cudaGetSymbolAddress((void**)&kl, g_kl);
    cudaGetSymbolAddress((void**)&vh, g_vh);
    cudaGetSymbolAddress((void**)&vl, g_vl);
    cudaGetSymbolAddress((void**)&oh, g_oh);
    cudaGetSymbolAddress((void**)&ol, g_ol);

    cudaFuncSetAttribute(attn_mma_kernel, cudaFuncAttributeMaxDynamicSharedMemorySize, ATT_SMEM);
    cudaFuncSetAttribute(gemm_mma_kernel, cudaFuncAttributeMaxDynamicSharedMemorySize, GEMM_SMEM);

    dim3 blk(256);
    dim3 tblk(32, 8);
    dim3 tc1024(DMODEL / 128, MROWS / 128);          // (8, 64)
    dim3 tcQKV(QKVN / 128, MROWS / 128);             // (24, 64)
    dim3 tcFF1(FFH / 128, MROWS / 128);              // (64, 64)
    dim3 gemmCtx(DMODEL / 128, (CTXROWS + 127) / 128);
    dim3 attng(SEQ / 128, NHEAD, 4);
    dim3 tg1024(DMODEL / 32, DMODEL / 32);
    dim3 tgFF1(FFH / 32, DMODEL / 32);
    dim3 tgFF2(DMODEL / 32, FFHALF / 32);

    // --- self attention ---
    ln_hilo_kernel<<<MROWS, blk>>>(x, ln1g, ln1b, ah, al);
    tconv_kernel<<<tg1024, tblk>>>(a1wq, bh + OW_QKV_Q, bl + OW_QKV_Q, DMODEL, DMODEL);
    tconv_kernel<<<tg1024, tblk>>>(a1wk, bh + OW_QKV_K, bl + OW_QKV_K, DMODEL, DMODEL);
    tconv_kernel<<<tg1024, tblk>>>(a1wv, bh + OW_QKV_V, bl + OW_QKV_V, DMODEL, DMODEL);
    tconv_kernel<<<tg1024, tblk>>>(a1wo, bh + OW_O1,    bl + OW_O1,    DMODEL, DMODEL);
    gemm_mma_kernel<<<tcQKV, blk, GEMM_SMEM>>>(ah, al, bh, bl, nullptr,
        MROWS, QKVN, DMODEL, nullptr, nullptr, qkvh, qkvl);
    attn_mma_kernel<<<attng, blk, ATT_SMEM>>>(qkvh, qkvl,
        qkvh + DMODEL, qkvl + DMODEL, qkvh + 2 * DMODEL, qkvl + 2 * DMODEL,
        oh, ol, SEQ, SEQ, QKVN, QKVN);
    gemm_mma_kernel<<<tc1024, blk, GEMM_SMEM>>>(oh, ol, bh + OW_O1, bl + OW_O1, xa,
        MROWS, DMODEL, DMODEL, a1bo, x, nullptr, nullptr);

    // --- cross attention ---
    ln_hilo_kernel<<<MROWS, blk>>>(xa, ln2g, ln2b, ah, al);
    tconv_kernel<<<tg1024, tblk>>>(a2wq, bh, bl, DMODEL, DMODEL);
    gemm_mma_kernel<<<tc1024, blk, GEMM_SMEM>>>(ah, al, bh, bl, nullptr,
        MROWS, DMODEL, DMODEL, nullptr, nullptr, qh, ql);
    gemm_kernel<<<gemmCtx, blk>>>(ctx, a2wk, ct1, CTXROWS, DMODEL, CTXDIM);
    hilo_kernel<<<CTXROWS, blk>>>(ct1, kh, kl);
    gemm_kernel<<<gemmCtx, blk>>>(ctx, a2wv, ct2, CTXROWS, DMODEL, CTXDIM);
    hilo_kernel<<<CTXROWS, blk>>>(ct2, vh, vl);
    attn_mma_kernel<<<attng, blk, ATT_SMEM>>>(qh, ql, kh, kl, vh, vl,
        oh, ol, SEQ, CTXLEN, DMODEL, DMODEL);
    tconv_kernel<<<tg1024, tblk>>>(a2wo, bh, bl, DMODEL, DMODEL);
    gemm_mma_kernel<<<tc1024, blk, GEMM_SMEM>>>(oh, ol, bh, bl, xa,
        MROWS, DMODEL, DMODEL, a2bo, xa, nullptr, nullptr);

    // --- GeGLU feed-forward ---
    ln_hilo_kernel<<<MROWS, blk>>>(xa, ln3g, ln3b, ah, al);
    tconv_kernel<<<tgFF1, tblk>>>(ffw1, bh, bl, DMODEL, FFH);
    gemm_mma_kernel<<<tcFF1, blk, GEMM_SMEM>>>(ah, al, bh, bl, nullptr,
        MROWS, FFH, DMODEL, ffb1, nullptr, hh, hl);
    geglu_hilo_kernel<<<dim3(FFHALF / 1024, MROWS), blk>>>(hh, hl, ah, al);
    tconv_kernel<<<tgFF2, tblk>>>(ffw2, bh, bl, FFHALF, DMODEL);
    gemm_mma_kernel<<<tc1024, blk, GEMM_SMEM>>>(ah, al, bh, bl, out,
        MROWS, DMODEL, FFHALF, ffb2, xa, nullptr, nullptr);
}

// round 15
// speedup vs baseline: 1.5731x; 1.0653x over previous
#include <cuda_runtime.h>
#include <cuda_bf16.h>
#include <math.h>
#include <cstdint>

// ---------------- problem constants ----------------
#define MROWS   8192        // B*S
#define DMODEL  1024
#define NHEAD   16
#define DHEAD   64
#define SEQ     2048
#define CTXROWS 308         // B*77
#define CTXLEN  77
#define CTXDIM  768
#define FFH     8192
#define FFHALF  4096
#define QKVN    3072

// weight sub-offsets inside g_bh/g_bl (elements)
#define OW_QKV_Q 0
#define OW_QKV_K (1024*1024)
#define OW_QKV_V (2*1024*1024)
#define OW_O1    (3*1024*1024)

// ---------------- scratch (static device globals; no runtime alloc) ----------------
__device__ float g_xa[MROWS * DMODEL];
__device__ float g_ctmp1[CTXROWS * DMODEL];
__device__ float g_ctmp2[CTXROWS * DMODEL];
__device__ __nv_bfloat16 g_hh[(size_t)MROWS * FFH];      // FF1 out hi
__device__ __nv_bfloat16 g_hl[(size_t)MROWS * FFH];      // FF1 out lo
__device__ __nv_bfloat16 g_ah[(size_t)MROWS * FFHALF];   // activation hi
__device__ __nv_bfloat16 g_al[(size_t)MROWS * FFHALF];   // activation lo
__device__ __nv_bfloat16 g_bh[(size_t)FFH * DMODEL];     // weights hi ([N,K], region-offset)
__device__ __nv_bfloat16 g_bl[(size_t)FFH * DMODEL];     // weights lo
__device__ __nv_bfloat16 g_qkvh[(size_t)MROWS * QKVN];   // fused QKV hi
__device__ __nv_bfloat16 g_qkvl[(size_t)MROWS * QKVN];   // fused QKV lo
__device__ __nv_bfloat16 g_qh[MROWS * DMODEL];           // cross-attn Q hi
__device__ __nv_bfloat16 g_ql[MROWS * DMODEL];
__device__ __nv_bfloat16 g_kh[MROWS * DMODEL];           // ctx K hi
__device__ __nv_bfloat16 g_kl[MROWS * DMODEL];
__device__ __nv_bfloat16 g_vh[MROWS * DMODEL];           // ctx V hi
__device__ __nv_bfloat16 g_vl[MROWS * DMODEL];
__device__ __nv_bfloat16 g_oh[MROWS * DMODEL];
__device__ __nv_bfloat16 g_ol[MROWS * DMODEL];

// ---------------- PTX helpers ----------------
__device__ __forceinline__ uint32_t smem_to_u32(const void* p) {
    uint32_t a;
    asm("{ .reg .u64 t; cvta.to.shared.u64 t, %1; cvt.u32.u64 %0, t; }" : "=r"(a) : "l"(p));
    return a;
}
#define CP_ASYNC16(dst, src) \
    asm volatile("cp.async.cg.shared.global [%0], [%1], 16;" :: "r"(dst), "l"(src))
#define CP_COMMIT() asm volatile("cp.async.commit_group;")
#define CP_WAIT0()  asm volatile("cp.async.wait_group 0;")
#define CP_WAIT1()  asm volatile("cp.async.wait_group 1;")
#define LDSM_X4(r0, r1, r2, r3, addr) \
    asm volatile("ldmatrix.sync.aligned.m8n8.x4.shared.b16 {%0,%1,%2,%3}, [%4];" \
        : "=r"(r0), "=r"(r1), "=r"(r2), "=r"(r3) : "r"(addr))
#define LDSM_X4_TRANS(r0, r1, r2, r3, addr) \
    asm volatile("ldmatrix.sync.aligned.m8n8.x4.trans.shared.b16 {%0,%1,%2,%3}, [%4];" \
        : "=r"(r0), "=r"(r1), "=r"(r2), "=r"(r3) : "r"(addr))
#define MMA16816(d, a, b0, b1) \
    asm volatile("mma.sync.aligned.m16n8k16.row.col.f32.bf16.bf16.f32 " \
        "{%0,%1,%2,%3}, {%4,%5,%6,%7}, {%8,%9}, {%0,%1,%2,%3};" \
        : "+f"((d)[0]), "+f"((d)[1]), "+f"((d)[2]), "+f"((d)[3]) \
        : "r"((a)[0]), "r"((a)[1]), "r"((a)[2]), "r"((a)[3]), "r"(b0), "r"(b1))

// 128-byte-row swizzle: chunk c (16B) stored at c ^ (r & 7)
__device__ __forceinline__ uint32_t att_sw(int r, int c) {
    return (uint32_t)(r * 128 + ((c ^ (r & 7)) << 4));
}

// ---------------- hi/lo split helpers ----------------
__device__ __forceinline__ void split_hilo(float x, __nv_bfloat16& h, __nv_bfloat16& l) {
    h = __float2bfloat16(x);
    l = __float2bfloat16(x - __bfloat162float(h));
}
__device__ __forceinline__ uint32_t pack_bf2(__nv_bfloat16 lo, __nv_bfloat16 hi) {
    __nv_bfloat162 t; t.x = lo; t.y = hi;
    return *(uint32_t*)&t;
}

// ---------------- fused LayerNorm + hi/lo emit ----------------
__global__ __launch_bounds__(256) void ln_hilo_kernel(const float* __restrict__ X,
                                                      const float* __restrict__ gma,
                                                      const float* __restrict__ bta,
                                                      __nv_bfloat16* __restrict__ Ho,
                                                      __nv_bfloat16* __restrict__ Lo) {
    int row = blockIdx.x;
    int tid = threadIdx.x;
    const float4* xr = (const float4*)(X + (size_t)row * DMODEL);
    float4 x4 = xr[tid];
    float s  = x4.x + x4.y + x4.z + x4.w;
    float ss = x4.x*x4.x + x4.y*x4.y + x4.z*x4.z + x4.w*x4.w;
#pragma unroll
    for (int off = 16; off > 0; off >>= 1) {
        s  += __shfl_xor_sync(0xffffffffu, s,  off);
        ss += __shfl_xor_sync(0xffffffffu, ss, off);
    }
    __shared__ float red[16];
    int lane = tid & 31, wid = tid >> 5;
    if (lane == 0) { red[wid] = s; red[8 + wid] = ss; }
    __syncthreads();
    float tot = 0.f, tot2 = 0.f;
#pragma unroll
    for (int i = 0; i < 8; i++) { tot += red[i]; tot2 += red[8 + i]; }
    const float inv = 1.0f / (float)DMODEL;
    float mu  = tot * inv;
    float var = tot2 * inv - mu * mu;
    float rs  = rsqrtf(var + 1e-5f);
    float4 gv = ((const float4*)gma)[tid];
    float4 bv = ((const float4*)bta)[tid];
    float o0 = (x4.x - mu) * rs * gv.x + bv.x;
    float o1 = (x4.y - mu) * rs * gv.y + bv.y;
    float o2 = (x4.z - mu) * rs * gv.z + bv.z;
    float o3 = (x4.w - mu) * rs * gv.w + bv.w;
    union { __nv_bfloat16 b[4]; uint2 u; } ph, pl;
    split_hilo(o0, ph.b[0], pl.b[0]);
    split_hilo(o1, ph.b[1], pl.b[1]);
    split_hilo(o2, ph.b[2], pl.b[2]);
    split_hilo(o3, ph.b[3], pl.b[3]);
    size_t base = (size_t)row * DMODEL + tid * 4;
    *(uint2*)(Ho + base) = ph.u;
    *(uint2*)(Lo + base) = pl.u;
}

// ---------------- elementwise fp32 -> bf16 hi/lo (ctx K/V path) ----------------
__global__ __launch_bounds__(256) void hilo_kernel(const float* __restrict__ X,
                                                   __nv_bfloat16* __restrict__ Ho,
                                                   __nv_bfloat16* __restrict__ Lo) {
    size_t idx = (size_t)blockIdx.x * 256 + threadIdx.x;
    float4 v = ((const float4*)X)[idx];
    union { __nv_bfloat16 b[4]; uint2 u; } ph, pl;
    split_hilo(v.x, ph.b[0], pl.b[0]);
    split_hilo(v.y, ph.b[1], pl.b[1]);
    split_hilo(v.z, ph.b[2], pl.b[2]);
    split_hilo(v.w, ph.b[3], pl.b[3]);
    *(uint2*)(Ho + idx * 4) = ph.u;
    *(uint2*)(Lo + idx * 4) = pl.u;
}

// ---------------- weight convert + transpose: W[K,N] fp32 -> Ht/Lt[N,K] bf16 ----------------
__global__ __launch_bounds__(256) void tconv_kernel(const float* __restrict__ W,
                                                    __nv_bfloat16* __restrict__ Ht,
                                                    __nv_bfloat16* __restrict__ Lt,
                                                    int K, int N) {
    __shared__ float s[32][33];
    int tx = threadIdx.x, ty = threadIdx.y;
    int n0 = blockIdx.x * 32, k0 = blockIdx.y * 32;
#pragma unroll
    for (int i = 0; i < 4; i++)
        s[ty + 8 * i][tx] = W[(size_t)(k0 + ty + 8 * i) * N + n0 + tx];
    __syncthreads();
#pragma unroll
    for (int i = 0; i < 4; i++) {
        int n = ty + 8 * i, k = tx;
        float v = s[k][n];
        __nv_bfloat16 h, l;
        split_hilo(v, h, l);
        size_t off = (size_t)(n0 + n) * K + k0 + k;
        Ht[off] = h;
        Lt[off] = l;
    }
}

// ---------------- bf16x3 GEMM via mma.sync (3-pass terms, BK=64, 3-stage cp.async) ----------------
// Stage = A(16KB) | B(16KB) = 32KB, 128B rows, c ^ (r&7) swizzle.
#define GSTAGE 32768
#define GEMM_SMEM (3 * GSTAGE)

__global__ __launch_bounds__(256) void gemm_mma_kernel(const __nv_bfloat16* __restrict__ Ah,
                                                       const __nv_bfloat16* __restrict__ Al,
                                                       const __nv_bfloat16* __restrict__ Bh,
                                                       const __nv_bfloat16* __restrict__ Bl,
                                                       float* __restrict__ C,
                                                       int M, int N, int K,
                                                       const float* __restrict__ bias,
                                                       const float* __restrict__ resid,
                                                       __nv_bfloat16* __restrict__ CH,
                                                       __nv_bfloat16* __restrict__ CL) {
    extern __shared__ char gsm[];
    uint32_t sbase = smem_to_u32(gsm);
    int tid = threadIdx.x;
    int warp = tid >> 5, lane = tid & 31;
    int wm = (warp & 1) * 64, wn = (warp >> 1) * 32;
    int row0 = blockIdx.y * 128, col0 = blockIdx.x * 128;

    const __nv_bfloat16* Aterm[3] = { Ah, Ah, Al };
    const __nv_bfloat16* Bterm[3] = { Bh, Bl, Bh };
    const int nk = K / 64;
    const int total = 3 * nk;

    float acc[4][4][4];
#pragma unroll
    for (int mi = 0; mi < 4; mi++)
#pragma unroll
        for (int ni = 0; ni < 4; ni++)
#pragma unroll
            for (int e = 0; e < 4; e++) acc[mi][ni][e] = 0.f;

    // one stage = A tile (16KB) + B tile (16KB); each thread: 4 A-chunks + 4 B-chunks
    auto load_stage = [&](int buf, int idx) {
        int t  = idx / nk;
        int k0 = (idx % nk) * 64;
        const __nv_bfloat16* Ap = Aterm[t];
        const __nv_bfloat16* Bp = Bterm[t];
        uint32_t so = sbase + buf * GSTAGE;
#pragma unroll
        for (int i = 0; i < 4; i++) {
            int lci = tid + i * 256;
            int r = lci >> 3, c = lci & 7;
            uint32_t doff = att_sw(r, c);
            CP_ASYNC16(so + doff,         Ap + (size_t)(row0 + r) * K + k0 + c * 8);
            CP_ASYNC16(so + 16384 + doff, Bp + (size_t)(col0 + r) * K + k0 + c * 8);
        }
        CP_COMMIT();
    };

    load_stage(0, 0);
    load_stage(1, 1);

    int buf = 0;
    for (int it = 0; it < total; it++) {
        if (it + 1 < total) { CP_WAIT1(); } else { CP_WAIT0(); }
        __syncthreads();
        if (it + 2 < total) {
            int nb3 = buf + 2; if (nb3 >= 3) nb3 -= 3;
            load_stage(nb3, it + 2);
        }
        uint32_t abase = sbase + buf * GSTAGE;
        uint32_t bbase = abase + 16384;
#pragma unroll
        for (int kk = 0; kk < 4; kk++) {
            int cidx = kk * 2 + (lane >> 4);
            uint32_t afr[4][4];
#pragma unroll
            for (int mi = 0; mi < 4; mi++) {
                int r = wm + mi * 16 + (lane & 15);
                LDSM_X4(afr[mi][0], afr[mi][1], afr[mi][2], afr[mi][3], abase + att_sw(r, cidx));
            }
            uint32_t bfr[2][4];
#pragma unroll
            for (int nb = 0; nb < 2; nb++) {
                int r = wn + nb * 16 + (lane & 15);
                LDSM_X4(bfr[nb][0], bfr[nb][1], bfr[nb][2], bfr[nb][3], bbase + att_sw(r, cidx));
            }
#pragma unroll
            for (int mi = 0; mi < 4; mi++)
#pragma unroll
                for (int nb = 0; nb < 2; nb++) {
                    MMA16816(acc[mi][nb * 2 + 0], afr[mi], bfr[nb][0], bfr[nb][2]);
                    MMA16816(acc[mi][nb * 2 + 1], afr[mi], bfr[nb][1], bfr[nb][3]);
                }
        }
        buf++; if (buf >= 3) buf -= 3;
    }

    // epilogue
    int grow = row0 + wm;
    int gcol = col0 + wn;
#pragma unroll
    for (int mi = 0; mi < 4; mi++)
#pragma unroll
        for (int ni = 0; ni < 4; ni++) {
            int r  = grow + mi * 16 + (lane >> 2);
            int cc = gcol + ni * 8 + (lane & 3) * 2;
            float2 v0 = make_float2(acc[mi][ni][0], acc[mi][ni][1]);
            float2 v1 = make_float2(acc[mi][ni][2], acc[mi][ni][3]);
            if (bias) {
                float2 b2 = *(const float2*)(bias + cc);
                v0.x += b2.x; v0.y += b2.y;
                v1.x += b2.x; v1.y += b2.y;
            }
            if (resid) {
                float2 r0 = *(const float2*)(resid + (size_t)r * N + cc);
                float2 r1 = *(const float2*)(resid + (size_t)(r + 8) * N + cc);
                v0.x += r0.x; v0.y += r0.y;
                v1.x += r1.x; v1.y += r1.y;
            }
            if (CH) {
                __nv_bfloat16 h0, l0, h1, l1;
                split_hilo(v0.x, h0, l0); split_hilo(v0.y, h1, l1);
                *(uint32_t*)(CH + (size_t)r * N + cc) = pack_bf2(h0, h1);
                *(uint32_t*)(CL + (size_t)r * N + cc) = pack_bf2(l0, l1);
                split_hilo(v1.x, h0, l0); split_hilo(v1.y, h1, l1);
                *(uint32_t*)(CH + (size_t)(r + 8) * N + cc) = pack_bf2(h0, h1);
                *(uint32_t*)(CL + (size_t)(r + 8) * N + cc) = pack_bf2(l0, l1);
            } else {
                *(float2*)(C + (size_t)r * N + cc) = v0;
                *(float2*)(C + (size_t)(r + 8) * N + cc) = v1;
            }
        }
}

// ---------------- fp32 GEMM (small ctx projections only) ----------------
__global__ __launch_bounds__(256) void gemm_kernel(const float* __restrict__ A,
                                                   const float* __restrict__ B,
                                                   float* __restrict__ C,
                                                   int M, int N, int K) {
    __shared__ float As[16][128];
    __shared__ float Bs[16][128];
    int tid = threadIdx.x;
    int tx = tid & 15, ty = tid >> 4;
    int row0 = blockIdx.y * 128, col0 = blockIdx.x * 128;
    float acc[8][8];
#pragma unroll
    for (int i = 0; i < 8; i++)
#pragma unroll
        for (int j = 0; j < 8; j++) acc[i][j] = 0.f;

    for (int k0 = 0; k0 < K; k0 += 16) {
#pragma unroll
        for (int i = 0; i < 2; i++) {
            int idx = tid * 2 + i;
            int r = idx >> 2, kc = idx & 3;
            int gr = row0 + r;
            float4 f = make_float4(0.f, 0.f, 0.f, 0.f);
            if (gr < M) f = *(const float4*)(A + (size_t)gr * K + k0 + kc * 4);
            As[kc * 4 + 0][r] = f.x;
            As[kc * 4 + 1][r] = f.y;
            As[kc * 4 + 2][r] = f.z;
            As[kc * 4 + 3][r] = f.w;
        }
#pragma unroll
        for (int i = 0; i < 2; i++) {
            int idx = tid * 2 + i;
            int kb = idx >> 5, nc = idx & 31;
            float4 f = *(const float4*)(B + (size_t)(k0 + kb) * N + col0 + nc * 4);
            *(float4*)&Bs[kb][nc * 4] = f;
        }
        __syncthreads();
#pragma unroll
        for (int kk = 0; kk < 16; kk++) {
            float a[8], bb[8];
            *(float4*)&a[0]  = *(float4*)&As[kk][ty * 8];
            *(float4*)&a[4]  = *(float4*)&As[kk][ty * 8 + 4];
            *(float4*)&bb[0] = *(float4*)&Bs[kk][tx * 4];
            *(float4*)&bb[4] = *(float4*)&Bs[kk][64 + tx * 4];
#pragma unroll
            for (int i = 0; i < 8; i++)
#pragma unroll
                for (int j = 0; j < 8; j++) acc[i][j] += a[i] * bb[j];
        }
        __syncthreads();
    }
#pragma unroll
    for (int i = 0; i < 8; i++) {
        int gr = row0 + ty * 8 + i;
        if (gr >= M) continue;
#pragma unroll
        for (int half = 0; half < 2; half++) {
            int gc = col0 + half * 64 + tx * 4;
            float4 r4;
            r4.x = acc[i][half * 4 + 0];
            r4.y = acc[i][half * 4 + 1];
            r4.z = acc[i][half * 4 + 2];
            r4.w = acc[i][half * 4 + 3];
            *(float4*)(C + (size_t)gr * N + gc) = r4;
        }
    }
}

// ---------------- MMA flash attention (strided Q/KV, ldmatrix.trans for V) ----------------
#define AQ_H 0
#define AQ_L 16384
#define AK_H 32768
#define AK_L 40960
#define AV_H 49152
#define AV_L 57344
#define ATT_SMEM 65536

__global__ __launch_bounds__(256) void attn_mma_kernel(
    const __nv_bfloat16* __restrict__ Qh, const __nv_bfloat16* __restrict__ Ql,
    const __nv_bfloat16* __restrict__ Kp_h, const __nv_bfloat16* __restrict__ Kp_l,
    const __nv_bfloat16* __restrict__ Vh, const __nv_bfloat16* __restrict__ Vl,
    __nv_bfloat16* __restrict__ Oh, __nv_bfloat16* __restrict__ Ol,
    int qlen, int kvlen, int qstride, int kvstride)
{
    extern __shared__ char smc[];
    uint32_t sb = smem_to_u32(smc);
    int b = blockIdx.z, h = blockIdx.y, qt = blockIdx.x;
    int tid = threadIdx.x, warp = tid >> 5, lane = tid & 31;
    int qrow0 = qt * 128;
    size_t qbase  = ((size_t)b * qlen + qrow0) * qstride + h * DHEAD;
    size_t kvbase = ((size_t)b * kvlen) * kvstride + h * DHEAD;

#pragma unroll
    for (int i = 0; i < 4; i++) {
        int idx = tid + i * 256;
        int r = idx >> 3, c = idx & 7;
        uint4 vh4 = *(const uint4*)(Qh + qbase + (size_t)r * qstride + c * 8);
        uint4 vl4 = *(const uint4*)(Ql + qbase + (size_t)r * qstride + c * 8);
        *(uint4*)(smc + AQ_H + att_sw(r, c)) = vh4;
        *(uint4*)(smc + AQ_L + att_sw(r, c)) = vl4;
    }
    __syncthreads();

    uint32_t qfh[4][4], qfl[4][4];
    {
        int r = warp * 16 + (lane & 15);
#pragma unroll
        for (int kk = 0; kk < 4; kk++) {
            int c = kk * 2 + (lane >> 4);
            LDSM_X4(qfh[kk][0], qfh[kk][1], qfh[kk][2], qfh[kk][3], sb + AQ_H + att_sw(r, c));
            LDSM_X4(qfl[kk][0], qfl[kk][1], qfl[kk][2], qfl[kk][3], sb + AQ_L + att_sw(r, c));
        }
    }

    float m_a = -1e30f, m_b = -1e30f, l_a = 0.f, l_b = 0.f;
    float acc_o[8][4];
#pragma unroll
    for (int t = 0; t < 8; t++)
#pragma unroll
        for (int e = 0; e < 4; e++) acc_o[t][e] = 0.f;

    int ntiles = (kvlen + 63) >> 6;
    for (int kt = 0; kt < ntiles; kt++) {
#pragma unroll
        for (int i = 0; i < 2; i++) {
            int idx = tid + i * 256;
            int r = idx >> 3, c = idx & 7;
            int kr = kt * 64 + r;
            uint4 kh4 = make_uint4(0, 0, 0, 0), kl4 = kh4, vh4 = kh4, vl4 = kh4;
            if (kr < kvlen) {
                size_t off = kvbase + (size_t)kr * kvstride + c * 8;
                kh4 = *(const uint4*)(Kp_h + off);
                kl4 = *(const uint4*)(Kp_l + off);
                vh4 = *(const uint4*)(Vh + off);
                vl4 = *(const uint4*)(Vl + off);
            }
            uint32_t sw = att_sw(r, c);
            *(uint4*)(smc + AK_H + sw) = kh4;
            *(uint4*)(smc + AK_L + sw) = kl4;
            *(uint4*)(smc + AV_H + sw) = vh4;
            *(uint4*)(smc + AV_L + sw) = vl4;
        }
        __syncthreads();

        float s[8][4];
#pragma unroll
        for (int t = 0; t < 8; t++)
#pragma unroll
            for (int e = 0; e < 4; e++) s[t][e] = 0.f;
#pragma unroll
        for (int kk = 0; kk < 4; kk++) {
#pragma unroll
            for (int nq = 0; nq < 4; nq++) {
                int r = nq * 16 + (lane & 15);
                int c = kk * 2 + (lane >> 4);
                uint32_t khf[4], klf[4];
                LDSM_X4(khf[0], khf[1], khf[2], khf[3], sb + AK_H + att_sw(r, c));
                LDSM_X4(klf[0], klf[1], klf[2], klf[3], sb + AK_L + att_sw(r, c));
                MMA16816(s[nq * 2 + 0], qfh[kk], khf[0], khf[2]);
                MMA16816(s[nq * 2 + 1], qfh[kk], khf[1], khf[3]);
                MMA16816(s[nq * 2 + 0], qfh[kk], klf[0], klf[2]);
                MMA16816(s[nq * 2 + 1], qfh[kk], klf[1], klf[3]);
                MMA16816(s[nq * 2 + 0], qfl[kk], khf[0], khf[2]);
                MMA16816(s[nq * 2 + 1], qfl[kk], khf[1], khf[3]);
            }
        }
        bool mtile = (kt == ntiles - 1) && (kvlen & 63);
#pragma unroll
        for (int t = 0; t < 8; t++)
#pragma unroll
            for (int e = 0; e < 4; e++) {
                float vv = s[t][e] * 0.125f;
                if (mtile) {
                    int col = kt * 64 + t * 8 + (lane & 3) * 2 + (e & 1);
                    if (col >= kvlen) vv = -1e30f;
                }
                s[t][e] = vv;
            }
        float mx_a = -1e30f, mx_b = -1e30f;
#pragma unroll
        for (int t = 0; t < 8; t++) {
            mx_a = fmaxf(mx_a, fmaxf(s[t][0], s[t][1]));
            mx_b = fmaxf(mx_b, fmaxf(s[t][2], s[t][3]));
        }
        mx_a = fmaxf(mx_a, __shfl_xor_sync(0xffffffffu, mx_a, 1));
        mx_a = fmaxf(mx_a, __shfl_xor_sync(0xffffffffu, mx_a, 2));
        mx_b = fmaxf(mx_b, __shfl_xor_sync(0xffffffffu, mx_b, 1));
        mx_b = fmaxf(mx_b, __shfl_xor_sync(0xffffffffu, mx_b, 2));
        float mn_a = fmaxf(m_a, mx_a), mn_b = fmaxf(m_b, mx_b);
        float al_a = __expf(m_a - mn_a), al_b = __expf(m_b - mn_b);
        m_a = mn_a; m_b = mn_b;
        float sum_a = 0.f, sum_b = 0.f;
#pragma unroll
        for (int t = 0; t < 8; t++) {
            s[t][0] = __expf(s[t][0] - m_a);
            s[t][1] = __expf(s[t][1] - m_a);
            s[t][2] = __expf(s[t][2] - m_b);
            s[t][3] = __expf(s[t][3] - m_b);
            sum_a += s[t][0] + s[t][1];
            sum_b += s[t][2] + s[t][3];
        }
        sum_a += __shfl_xor_sync(0xffffffffu, sum_a, 1);
        sum_a += __shfl_xor_sync(0xffffffffu, sum_a, 2);
        sum_b += __shfl_xor_sync(0xffffffffu, sum_b, 1);
        sum_b += __shfl_xor_sync(0xffffffffu, sum_b, 2);
        l_a = l_a * al_a + sum_a;
        l_b = l_b * al_b + sum_b;
#pragma unroll
        for (int t = 0; t < 8; t++) {
            acc_o[t][0] *= al_a; acc_o[t][1] *= al_a;
            acc_o[t][2] *= al_b; acc_o[t][3] *= al_b;
        }
#pragma unroll
        for (int kc = 0; kc < 4; kc++) {
            int t0 = kc * 2, t1 = t0 + 1;
            uint32_t pah[4], pal[4];
            {
                __nv_bfloat16 hb, lb, hb2, lb2;
                split_hilo(s[t0][0], hb, lb);  split_hilo(s[t0][1], hb2, lb2);
                pah[0] = pack_bf2(hb, hb2);    pal[0] = pack_bf2(lb, lb2);
                split_hilo(s[t0][2], hb, lb);  split_hilo(s[t0][3], hb2, lb2);
                pah[1] = pack_bf2(hb, hb2);    pal[1] = pack_bf2(lb, lb2);
                split_hilo(s[t1][0], hb, lb);  split_hilo(s[t1][1], hb2, lb2);
                pah[2] = pack_bf2(hb, hb2);    pal[2] = pack_bf2(lb, lb2);
                split_hilo(s[t1][2], hb, lb);  split_hilo(s[t1][3], hb2, lb2);
                pah[3] = pack_bf2(hb, hb2);    pal[3] = pack_bf2(lb, lb2);
            }
#pragma unroll
            for (int nd = 0; nd < 4; nd++) {
                int r = kc * 16 + (lane & 15);
                int c = nd * 2 + (lane >> 4);
                uint32_t addr = sb + att_sw(r, c);
                uint32_t vhf[4], vlf[4];
                LDSM_X4_TRANS(vhf[0], vhf[1], vhf[2], vhf[3], addr + AV_H);
                LDSM_X4_TRANS(vlf[0], vlf[1], vlf[2], vlf[3], addr + AV_L);
                MMA16816(acc_o[nd * 2 + 0], pah, vhf[0], vhf[1]);
                MMA16816(acc_o[nd * 2 + 1], pah, vhf[2], vhf[3]);
                MMA16816(acc_o[nd * 2 + 0], pah, vlf[0], vlf[1]);
                MMA16816(acc_o[nd * 2 + 1], pah, vlf[2], vlf[3]);
                MMA16816(acc_o[nd * 2 + 0], pal, vhf[0], vhf[1]);
                MMA16816(acc_o[nd * 2 + 1], pal, vhf[2], vhf[3]);
            }
        }
        __syncthreads();
    }

    float inv_a = 1.0f / l_a, inv_b = 1.0f / l_b;
    int row_a = qrow0 + warp * 16 + (lane >> 2);
    size_t ob = ((size_t)b * qlen) * DMODEL + h * DHEAD;
#pragma unroll
    for (int nd = 0; nd < 8; nd++) {
        int d0 = nd * 8 + (lane & 3) * 2;
        float a0 = acc_o[nd][0] * inv_a, a1 = acc_o[nd][1] * inv_a;
        float b0 = acc_o[nd][2] * inv_b, b1 = acc_o[nd][3] * inv_b;
        __nv_bfloat16 h0, l0, h1, l1;
        split_hilo(a0, h0, l0); split_hilo(a1, h1, l1);
        *(uint32_t*)(Oh + ob + (size_t)row_a * DMODEL + d0) = pack_bf2(h0, h1);
        *(uint32_t*)(Ol + ob + (size_t)row_a * DMODEL + d0) = pack_bf2(l0, l1);
        split_hilo(b0, h0, l0); split_hilo(b1, h1, l1);
        *(uint32_t*)(Oh + ob + (size_t)(row_a + 8) * DMODEL + d0) = pack_bf2(h0, h1);
        *(uint32_t*)(Ol + ob + (size_t)(row_a + 8) * DMODEL + d0) = pack_bf2(l0, l1);
    }
}

// ---------------- GeGLU (bf16 hi/lo in) + hi/lo emit ----------------
__global__ __launch_bounds__(256) void geglu_hilo_kernel(const __nv_bfloat16* __restrict__ Hh,
                                                         const __nv_bfloat16* __restrict__ Hl,
                                                         __nv_bfloat16* __restrict__ Ho,
                                                         __nv_bfloat16* __restrict__ Lo) {
    int row = blockIdx.y;
    int c = (blockIdx.x * 256 + threadIdx.x) * 4;
    size_t ubase = (size_t)row * FFH + c;
    size_t gbase = ubase + FFHALF;
    union { uint2 u; __nv_bfloat16 e[4]; } uh, ul, gh, gl;
    uh.u = *(const uint2*)(Hh + ubase);
    ul.u = *(const uint2*)(Hl + ubase);
    gh.u = *(const uint2*)(Hh + gbase);
    gl.u = *(const uint2*)(Hl + gbase);
    const float kc = 0.70710678118654752f;
    union { __nv_bfloat16 b[4]; uint2 uu; } ph, pl;
#pragma unroll
    for (int j = 0; j < 4; j++) {
        float u = __bfloat162float(uh.e[j]) + __bfloat162float(ul.e[j]);
        float g = __bfloat162float(gh.e[j]) + __bfloat162float(gl.e[j]);
        float r = u * (0.5f * g * (1.f + erff(g * kc)));
        split_hilo(r, ph.b[j], pl.b[j]);
    }
    size_t base = (size_t)row * FFHALF + c;
    *(uint2*)(Ho + base) = ph.uu;
    *(uint2*)(Lo + base) = pl.uu;
}

// ---------------- launch ----------------
extern "C" void kernel_launch(void* const* d_in, const int* in_sizes, int n_in,
                              void* d_out, int out_size) {
    const float* x    = (const float*)d_in[0];
    const float* ctx  = (const float*)d_in[1];
    const float* ln1g = (const float*)d_in[2];
    const float* ln1b = (const float*)d_in[3];
    const float* ln2g = (const float*)d_in[4];
    const float* ln2b = (const float*)d_in[5];
    const float* ln3g = (const float*)d_in[6];
    const float* ln3b = (const float*)d_in[7];
    const float* a1wq = (const float*)d_in[8];
    const float* a1wk = (const float*)d_in[9];
    const float* a1wv = (const float*)d_in[10];
    const float* a1wo = (const float*)d_in[11];
    const float* a1bo = (const float*)d_in[12];
    const float* a2wq = (const float*)d_in[13];
    const float* a2wk = (const float*)d_in[14];
    const float* a2wv = (const float*)d_in[15];
    const float* a2wo = (const float*)d_in[16];
    const float* a2bo = (const float*)d_in[17];
    const float* ffw1 = (const float*)d_in[18];
    const float* ffb1 = (const float*)d_in[19];
    const float* ffw2 = (const float*)d_in[20];
    const float* ffb2 = (const float*)d_in[21];
    float* out = (float*)d_out;

    float *xa, *ct1, *ct2;
    __nv_bfloat16 *hh, *hl, *ah, *al, *bh, *bl, *qkvh, *qkvl, *qh, *ql, *kh, *kl, *vh, *vl, *oh, *ol;
    cudaGetSymbolAddress((void**)&xa,   g_xa);
    cudaGetSymbolAddress((void**)&ct1,  g_ctmp1);
    cudaGetSymbolAddress((void**)&ct2,  g_ctmp2);
    cudaGetSymbolAddress((void**)&hh, g_hh);
    cudaGetSymbolAddress((void**)&hl, g_hl);
    cudaGetSymbolAddress((void**)&ah, g_ah);
    cudaGetSymbolAddress((void**)&al, g_al);
    cudaGetSymbolAddress((void**)&bh, g_bh);
    cudaGetSymbolAddress((void**)&bl, g_bl);
    cudaGetSymbolAddress((void**)&qkvh, g_qkvh);
    cudaGetSymbolAddress((void**)&qkvl, g_qkvl);
    cudaGetSymbolAddress((void**)&qh, g_qh);
    cudaGetSymbolAddress((void**)&ql, g_ql);
    cudaGetSymbolAddress((void**)&kh, g_kh);
    cudaGetSymbolAddress((void**)&kl, g_kl);
    cudaGetSymbolAddress((void**)&vh, g_vh);
    cudaGetSymbolAddress((void**)&vl, g_vl);
    cudaGetSymbolAddress((void**)&oh, g_oh);
    cudaGetSymbolAddress((void**)&ol, g_ol);

    cudaFuncSetAttribute(attn_mma_kernel, cudaFuncAttributeMaxDynamicSharedMemorySize, ATT_SMEM);
    cudaFuncSetAttribute(gemm_mma_kernel, cudaFuncAttributeMaxDynamicSharedMemorySize, GEMM_SMEM);

    dim3 blk(256);
    dim3 tblk(32, 8);
    dim3 tc1024(DMODEL / 128, MROWS / 128);          // (8, 64)
    dim3 tcQKV(QKVN / 128, MROWS / 128);             // (24, 64)
    dim3 tcFF1(FFH / 128, MROWS / 128);              // (64, 64)
    dim3 gemmCtx(DMODEL / 128, (CTXROWS + 127) / 128);
    dim3 attng(SEQ / 128, NHEAD, 4);
    dim3 tg1024(DMODEL / 32, DMODEL / 32);
    dim3 tgFF1(FFH / 32, DMODEL / 32);
    dim3 tgFF2(DMODEL / 32, FFHALF / 32);

    // --- self attention ---
    // launch order puts the fused QKV GEMM at 0-indexed position 4 (5th launch) for ncu -s 5
    ln_hilo_kernel<<<MROWS, blk>>>(x, ln1g, ln1b, ah, al);                              // 0
    tconv_kernel<<<tg1024, tblk>>>(a1wq, bh + OW_QKV_Q, bl + OW_QKV_Q, DMODEL, DMODEL); // 1
    tconv_kernel<<<tg1024, tblk>>>(a1wk, bh + OW_QKV_K, bl + OW_QKV_K, DMODEL, DMODEL); // 2
    tconv_kernel<<<tg1024, tblk>>>(a1wv, bh + OW_QKV_V, bl + OW_QKV_V, DMODEL, DMODEL); // 3
    gemm_mma_kernel<<<tcQKV, blk, GEMM_SMEM>>>(ah, al, bh, bl, nullptr,                  // 4 (ncu)
        MROWS, QKVN, DMODEL, nullptr, nullptr, qkvh, qkvl);
    tconv_kernel<<<tg1024, tblk>>>(a1wo, bh + OW_O1, bl + OW_O1, DMODEL, DMODEL);        // 5
    attn_mma_kernel<<<attng, blk, ATT_SMEM>>>(qkvh, qkvl,
        qkvh + DMODEL, qkvl + DMODEL, qkvh + 2 * DMODEL, qkvl + 2 * DMODEL,
        oh, ol, SEQ, SEQ, QKVN, QKVN);
    gemm_mma_kernel<<<tc1024, blk, GEMM_SMEM>>>(oh, ol, bh + OW_O1, bl + OW_O1, xa,
        MROWS, DMODEL, DMODEL, a1bo, x, nullptr, nullptr);

    // --- cross attention ---
    ln_hilo_kernel<<<MROWS, blk>>>(xa, ln2g, ln2b, ah, al);
    tconv_kernel<<<tg1024, tblk>>>(a2wq, bh, bl, DMODEL, DMODEL);
    gemm_mma_kernel<<<tc1024, blk, GEMM_SMEM>>>(ah, al, bh, bl, nullptr,
        MROWS, DMODEL, DMODEL, nullptr, nullptr, qh, ql);
    gemm_kernel<<<gemmCtx, blk>>>(ctx, a2wk, ct1, CTXROWS, DMODEL, CTXDIM);
    hilo_kernel<<<CTXROWS, blk>>>(ct1, kh, kl);
    gemm_kernel<<<gemmCtx, blk>>>(ctx, a2wv, ct2, CTXROWS, DMODEL, CTXDIM);
    hilo_kernel<<<CTXROWS, blk>>>(ct2, vh, vl);
    attn_mma_kernel<<<attng, blk, ATT_SMEM>>>(qh, ql, kh, kl, vh, vl,
        oh, ol, SEQ, CTXLEN, DMODEL, DMODEL);
    tconv_kernel<<<tg1024, tblk>>>(a2wo, bh, bl, DMODEL, DMODEL);
    gemm_mma_kernel<<<tc1024, blk, GEMM_SMEM>>>(oh, ol, bh, bl, xa,
        MROWS, DMODEL, DMODEL, a2bo, xa, nullptr, nullptr);

    // --- GeGLU feed-forward ---
    ln_hilo_kernel<<<MROWS, blk>>>(xa, ln3g, ln3b, ah, al);
    tconv_kernel<<<tgFF1, tblk>>>(ffw1, bh, bl, DMODEL, FFH);
    gemm_mma_kernel<<<tcFF1, blk, GEMM_SMEM>>>(ah, al, bh, bl, nullptr,
        MROWS, FFH, DMODEL, ffb1, nullptr, hh, hl);
    geglu_hilo_kernel<<<dim3(FFHALF / 1024, MROWS), blk>>>(hh, hl, ah, al);
    tconv_kernel<<<tgFF2, tblk>>>(ffw2, bh, bl, FFHALF, DMODEL);
    gemm_mma_kernel<<<tc1024, blk, GEMM_SMEM>>>(ah, al, bh, bl, out,
        MROWS, DMODEL, FFHALF, ffb2, xa, nullptr, nullptr);
}

// round 16
// speedup vs baseline: 1.6804x; 1.0682x over previous
#include <cuda_runtime.h>
#include <cuda_bf16.h>
#include <math.h>
#include <cstdint>

// ---------------- problem constants ----------------
#define MROWS   8192        // B*S
#define DMODEL  1024
#define NHEAD   16
#define DHEAD   64
#define SEQ     2048
#define CTXROWS 308         // B*77
#define CTXLEN  77
#define CTXDIM  768
#define FFH     8192
#define FFHALF  4096
#define QKVN    3072

// weight sub-offsets inside g_bh/g_bl (elements)
#define OW_QKV_Q 0
#define OW_QKV_K (1024*1024)
#define OW_QKV_V (2*1024*1024)
#define OW_O1    (3*1024*1024)

// ---------------- scratch (static device globals; no runtime alloc) ----------------
__device__ float g_xa[MROWS * DMODEL];
__device__ float g_ctmp1[CTXROWS * DMODEL];
__device__ float g_ctmp2[CTXROWS * DMODEL];
__device__ __nv_bfloat16 g_hh[(size_t)MROWS * FFH];      // FF1 out hi
__device__ __nv_bfloat16 g_hl[(size_t)MROWS * FFH];      // FF1 out lo
__device__ __nv_bfloat16 g_ah[(size_t)MROWS * FFHALF];   // activation hi
__device__ __nv_bfloat16 g_al[(size_t)MROWS * FFHALF];   // activation lo
__device__ __nv_bfloat16 g_bh[(size_t)FFH * DMODEL];     // weights hi ([N,K], region-offset)
__device__ __nv_bfloat16 g_bl[(size_t)FFH * DMODEL];     // weights lo
__device__ __nv_bfloat16 g_qkvh[(size_t)MROWS * QKVN];   // fused QKV hi
__device__ __nv_bfloat16 g_qkvl[(size_t)MROWS * QKVN];   // fused QKV lo
__device__ __nv_bfloat16 g_qh[MROWS * DMODEL];           // cross-attn Q hi
__device__ __nv_bfloat16 g_ql[MROWS * DMODEL];
__device__ __nv_bfloat16 g_kh[MROWS * DMODEL];           // ctx K hi
__device__ __nv_bfloat16 g_kl[MROWS * DMODEL];
__device__ __nv_bfloat16 g_vh[MROWS * DMODEL];           // ctx V hi
__device__ __nv_bfloat16 g_vl[MROWS * DMODEL];
__device__ __nv_bfloat16 g_oh[MROWS * DMODEL];
__device__ __nv_bfloat16 g_ol[MROWS * DMODEL];

// ---------------- PTX helpers ----------------
__device__ __forceinline__ uint32_t smem_to_u32(const void* p) {
    uint32_t a;
    asm("{ .reg .u64 t; cvta.to.shared.u64 t, %1; cvt.u32.u64 %0, t; }" : "=r"(a) : "l"(p));
    return a;
}
#define CP_ASYNC16(dst, src) \
    asm volatile("cp.async.cg.shared.global [%0], [%1], 16;" :: "r"(dst), "l"(src))
#define CP_ASYNC16Z(dst, src, sbytes) \
    asm volatile("cp.async.cg.shared.global [%0], [%1], 16, %2;" :: "r"(dst), "l"(src), "r"(sbytes))
#define CP_COMMIT() asm volatile("cp.async.commit_group;")
#define CP_WAIT0()  asm volatile("cp.async.wait_group 0;")
#define CP_WAIT1()  asm volatile("cp.async.wait_group 1;")
#define LDSM_X4(r0, r1, r2, r3, addr) \
    asm volatile("ldmatrix.sync.aligned.m8n8.x4.shared.b16 {%0,%1,%2,%3}, [%4];" \
        : "=r"(r0), "=r"(r1), "=r"(r2), "=r"(r3) : "r"(addr))
#define LDSM_X4_TRANS(r0, r1, r2, r3, addr) \
    asm volatile("ldmatrix.sync.aligned.m8n8.x4.trans.shared.b16 {%0,%1,%2,%3}, [%4];" \
        : "=r"(r0), "=r"(r1), "=r"(r2), "=r"(r3) : "r"(addr))
#define MMA16816(d, a, b0, b1) \
    asm volatile("mma.sync.aligned.m16n8k16.row.col.f32.bf16.bf16.f32 " \
        "{%0,%1,%2,%3}, {%4,%5,%6,%7}, {%8,%9}, {%0,%1,%2,%3};" \
        : "+f"((d)[0]), "+f"((d)[1]), "+f"((d)[2]), "+f"((d)[3]) \
        : "r"((a)[0]), "r"((a)[1]), "r"((a)[2]), "r"((a)[3]), "r"(b0), "r"(b1))

// 128-byte-row swizzle: chunk c (16B) stored at c ^ (r & 7)
__device__ __forceinline__ uint32_t att_sw(int r, int c) {
    return (uint32_t)(r * 128 + ((c ^ (r & 7)) << 4));
}

// ---------------- hi/lo split helpers ----------------
__device__ __forceinline__ void split_hilo(float x, __nv_bfloat16& h, __nv_bfloat16& l) {
    h = __float2bfloat16(x);
    l = __float2bfloat16(x - __bfloat162float(h));
}
__device__ __forceinline__ uint32_t pack_bf2(__nv_bfloat16 lo, __nv_bfloat16 hi) {
    __nv_bfloat162 t; t.x = lo; t.y = hi;
    return *(uint32_t*)&t;
}

// ---------------- fused LayerNorm + hi/lo emit ----------------
__global__ __launch_bounds__(256) void ln_hilo_kernel(const float* __restrict__ X,
                                                      const float* __restrict__ gma,
                                                      const float* __restrict__ bta,
                                                      __nv_bfloat16* __restrict__ Ho,
                                                      __nv_bfloat16* __restrict__ Lo) {
    int row = blockIdx.x;
    int tid = threadIdx.x;
    const float4* xr = (const float4*)(X + (size_t)row * DMODEL);
    float4 x4 = xr[tid];
    float s  = x4.x + x4.y + x4.z + x4.w;
    float ss = x4.x*x4.x + x4.y*x4.y + x4.z*x4.z + x4.w*x4.w;
#pragma unroll
    for (int off = 16; off > 0; off >>= 1) {
        s  += __shfl_xor_sync(0xffffffffu, s,  off);
        ss += __shfl_xor_sync(0xffffffffu, ss, off);
    }
    __shared__ float red[16];
    int lane = tid & 31, wid = tid >> 5;
    if (lane == 0) { red[wid] = s; red[8 + wid] = ss; }
    __syncthreads();
    float tot = 0.f, tot2 = 0.f;
#pragma unroll
    for (int i = 0; i < 8; i++) { tot += red[i]; tot2 += red[8 + i]; }
    const float inv = 1.0f / (float)DMODEL;
    float mu  = tot * inv;
    float var = tot2 * inv - mu * mu;
    float rs  = rsqrtf(var + 1e-5f);
    float4 gv = ((const float4*)gma)[tid];
    float4 bv = ((const float4*)bta)[tid];
    float o0 = (x4.x - mu) * rs * gv.x + bv.x;
    float o1 = (x4.y - mu) * rs * gv.y + bv.y;
    float o2 = (x4.z - mu) * rs * gv.z + bv.z;
    float o3 = (x4.w - mu) * rs * gv.w + bv.w;
    union { __nv_bfloat16 b[4]; uint2 u; } ph, pl;
    split_hilo(o0, ph.b[0], pl.b[0]);
    split_hilo(o1, ph.b[1], pl.b[1]);
    split_hilo(o2, ph.b[2], pl.b[2]);
    split_hilo(o3, ph.b[3], pl.b[3]);
    size_t base = (size_t)row * DMODEL + tid * 4;
    *(uint2*)(Ho + base) = ph.u;
    *(uint2*)(Lo + base) = pl.u;
}

// ---------------- elementwise fp32 -> bf16 hi/lo (ctx K/V path) ----------------
__global__ __launch_bounds__(256) void hilo_kernel(const float* __restrict__ X,
                                                   __nv_bfloat16* __restrict__ Ho,
                                                   __nv_bfloat16* __restrict__ Lo) {
    size_t idx = (size_t)blockIdx.x * 256 + threadIdx.x;
    float4 v = ((const float4*)X)[idx];
    union { __nv_bfloat16 b[4]; uint2 u; } ph, pl;
    split_hilo(v.x, ph.b[0], pl.b[0]);
    split_hilo(v.y, ph.b[1], pl.b[1]);
    split_hilo(v.z, ph.b[2], pl.b[2]);
    split_hilo(v.w, ph.b[3], pl.b[3]);
    *(uint2*)(Ho + idx * 4) = ph.u;
    *(uint2*)(Lo + idx * 4) = pl.u;
}

// ---------------- weight convert + transpose: W[K,N] fp32 -> Ht/Lt[N,K] bf16 ----------------
__global__ __launch_bounds__(256) void tconv_kernel(const float* __restrict__ W,
                                                    __nv_bfloat16* __restrict__ Ht,
                                                    __nv_bfloat16* __restrict__ Lt,
                                                    int K, int N) {
    __shared__ float s[32][33];
    int tx = threadIdx.x, ty = threadIdx.y;
    int n0 = blockIdx.x * 32, k0 = blockIdx.y * 32;
#pragma unroll
    for (int i = 0; i < 4; i++)
        s[ty + 8 * i][tx] = W[(size_t)(k0 + ty + 8 * i) * N + n0 + tx];
    __syncthreads();
#pragma unroll
    for (int i = 0; i < 4; i++) {
        int n = ty + 8 * i, k = tx;
        float v = s[k][n];
        __nv_bfloat16 h, l;
        split_hilo(v, h, l);
        size_t off = (size_t)(n0 + n) * K + k0 + k;
        Ht[off] = h;
        Lt[off] = l;
    }
}

// ---------------- bf16x3 GEMM via mma.sync (3-pass terms, BK=64, 3-stage cp.async) ----------------
// Stage = A(16KB) | B(16KB) = 32KB, 128B rows, c ^ (r&7) swizzle.
#define GSTAGE 32768
#define GEMM_SMEM (3 * GSTAGE)

__global__ __launch_bounds__(256) void gemm_mma_kernel(const __nv_bfloat16* __restrict__ Ah,
                                                       const __nv_bfloat16* __restrict__ Al,
                                                       const __nv_bfloat16* __restrict__ Bh,
                                                       const __nv_bfloat16* __restrict__ Bl,
                                                       float* __restrict__ C,
                                                       int M, int N, int K,
                                                       const float* __restrict__ bias,
                                                       const float* __restrict__ resid,
                                                       __nv_bfloat16* __restrict__ CH,
                                                       __nv_bfloat16* __restrict__ CL) {
    extern __shared__ char gsm[];
    uint32_t sbase = smem_to_u32(gsm);
    int tid = threadIdx.x;
    int warp = tid >> 5, lane = tid & 31;
    int wm = (warp & 1) * 64, wn = (warp >> 1) * 32;
    int row0 = blockIdx.y * 128, col0 = blockIdx.x * 128;

    const __nv_bfloat16* Aterm[3] = { Ah, Ah, Al };
    const __nv_bfloat16* Bterm[3] = { Bh, Bl, Bh };
    const int nk = K / 64;
    const int total = 3 * nk;

    float acc[4][4][4];
#pragma unroll
    for (int mi = 0; mi < 4; mi++)
#pragma unroll
        for (int ni = 0; ni < 4; ni++)
#pragma unroll
            for (int e = 0; e < 4; e++) acc[mi][ni][e] = 0.f;

    auto load_stage = [&](int buf, int idx) {
        int t  = idx / nk;
        int k0 = (idx % nk) * 64;
        const __nv_bfloat16* Ap = Aterm[t];
        const __nv_bfloat16* Bp = Bterm[t];
        uint32_t so = sbase + buf * GSTAGE;
#pragma unroll
        for (int i = 0; i < 4; i++) {
            int lci = tid + i * 256;
            int r = lci >> 3, c = lci & 7;
            uint32_t doff = att_sw(r, c);
            CP_ASYNC16(so + doff,         Ap + (size_t)(row0 + r) * K + k0 + c * 8);
            CP_ASYNC16(so + 16384 + doff, Bp + (size_t)(col0 + r) * K + k0 + c * 8);
        }
        CP_COMMIT();
    };

    load_stage(0, 0);
    load_stage(1, 1);

    int buf = 0;
    for (int it = 0; it < total; it++) {
        if (it + 1 < total) { CP_WAIT1(); } else { CP_WAIT0(); }
        __syncthreads();
        if (it + 2 < total) {
            int nb3 = buf + 2; if (nb3 >= 3) nb3 -= 3;
            load_stage(nb3, it + 2);
        }
        uint32_t abase = sbase + buf * GSTAGE;
        uint32_t bbase = abase + 16384;
#pragma unroll
        for (int kk = 0; kk < 4; kk++) {
            int cidx = kk * 2 + (lane >> 4);
            uint32_t afr[4][4];
#pragma unroll
            for (int mi = 0; mi < 4; mi++) {
                int r = wm + mi * 16 + (lane & 15);
                LDSM_X4(afr[mi][0], afr[mi][1], afr[mi][2], afr[mi][3], abase + att_sw(r, cidx));
            }
            uint32_t bfr[2][4];
#pragma unroll
            for (int nb = 0; nb < 2; nb++) {
                int r = wn + nb * 16 + (lane & 15);
                LDSM_X4(bfr[nb][0], bfr[nb][1], bfr[nb][2], bfr[nb][3], bbase + att_sw(r, cidx));
            }
#pragma unroll
            for (int mi = 0; mi < 4; mi++)
#pragma unroll
                for (int nb = 0; nb < 2; nb++) {
                    MMA16816(acc[mi][nb * 2 + 0], afr[mi], bfr[nb][0], bfr[nb][2]);
                    MMA16816(acc[mi][nb * 2 + 1], afr[mi], bfr[nb][1], bfr[nb][3]);
                }
        }
        buf++; if (buf >= 3) buf -= 3;
    }

    // epilogue
    int grow = row0 + wm;
    int gcol = col0 + wn;
#pragma unroll
    for (int mi = 0; mi < 4; mi++)
#pragma unroll
        for (int ni = 0; ni < 4; ni++) {
            int r  = grow + mi * 16 + (lane >> 2);
            int cc = gcol + ni * 8 + (lane & 3) * 2;
            float2 v0 = make_float2(acc[mi][ni][0], acc[mi][ni][1]);
            float2 v1 = make_float2(acc[mi][ni][2], acc[mi][ni][3]);
            if (bias) {
                float2 b2 = *(const float2*)(bias + cc);
                v0.x += b2.x; v0.y += b2.y;
                v1.x += b2.x; v1.y += b2.y;
            }
            if (resid) {
                float2 r0 = *(const float2*)(resid + (size_t)r * N + cc);
                float2 r1 = *(const float2*)(resid + (size_t)(r + 8) * N + cc);
                v0.x += r0.x; v0.y += r0.y;
                v1.x += r1.x; v1.y += r1.y;
            }
            if (CH) {
                __nv_bfloat16 h0, l0, h1, l1;
                split_hilo(v0.x, h0, l0); split_hilo(v0.y, h1, l1);
                *(uint32_t*)(CH + (size_t)r * N + cc) = pack_bf2(h0, h1);
                *(uint32_t*)(CL + (size_t)r * N + cc) = pack_bf2(l0, l1);
                split_hilo(v1.x, h0, l0); split_hilo(v1.y, h1, l1);
                *(uint32_t*)(CH + (size_t)(r + 8) * N + cc) = pack_bf2(h0, h1);
                *(uint32_t*)(CL + (size_t)(r + 8) * N + cc) = pack_bf2(l0, l1);
            } else {
                *(float2*)(C + (size_t)r * N + cc) = v0;
                *(float2*)(C + (size_t)(r + 8) * N + cc) = v1;
            }
        }
}

// ---------------- fp32 GEMM (small ctx projections only) ----------------
__global__ __launch_bounds__(256) void gemm_kernel(const float* __restrict__ A,
                                                   const float* __restrict__ B,
                                                   float* __restrict__ C,
                                                   int M, int N, int K) {
    __shared__ float As[16][128];
    __shared__ float Bs[16][128];
    int tid = threadIdx.x;
    int tx = tid & 15, ty = tid >> 4;
    int row0 = blockIdx.y * 128, col0 = blockIdx.x * 128;
    float acc[8][8];
#pragma unroll
    for (int i = 0; i < 8; i++)
#pragma unroll
        for (int j = 0; j < 8; j++) acc[i][j] = 0.f;

    for (int k0 = 0; k0 < K; k0 += 16) {
#pragma unroll
        for (int i = 0; i < 2; i++) {
            int idx = tid * 2 + i;
            int r = idx >> 2, kc = idx & 3;
            int gr = row0 + r;
            float4 f = make_float4(0.f, 0.f, 0.f, 0.f);
            if (gr < M) f = *(const float4*)(A + (size_t)gr * K + k0 + kc * 4);
            As[kc * 4 + 0][r] = f.x;
            As[kc * 4 + 1][r] = f.y;
            As[kc * 4 + 2][r] = f.z;
            As[kc * 4 + 3][r] = f.w;
        }
#pragma unroll
        for (int i = 0; i < 2; i++) {
            int idx = tid * 2 + i;
            int kb = idx >> 5, nc = idx & 31;
            float4 f = *(const float4*)(B + (size_t)(k0 + kb) * N + col0 + nc * 4);
            *(float4*)&Bs[kb][nc * 4] = f;
        }
        __syncthreads();
#pragma unroll
        for (int kk = 0; kk < 16; kk++) {
            float a[8], bb[8];
            *(float4*)&a[0]  = *(float4*)&As[kk][ty * 8];
            *(float4*)&a[4]  = *(float4*)&As[kk][ty * 8 + 4];
            *(float4*)&bb[0] = *(float4*)&Bs[kk][tx * 4];
            *(float4*)&bb[4] = *(float4*)&Bs[kk][64 + tx * 4];
#pragma unroll
            for (int i = 0; i < 8; i++)
#pragma unroll
                for (int j = 0; j < 8; j++) acc[i][j] += a[i] * bb[j];
        }
        __syncthreads();
    }
#pragma unroll
    for (int i = 0; i < 8; i++) {
        int gr = row0 + ty * 8 + i;
        if (gr >= M) continue;
#pragma unroll
        for (int half = 0; half < 2; half++) {
            int gc = col0 + half * 64 + tx * 4;
            float4 r4;
            r4.x = acc[i][half * 4 + 0];
            r4.y = acc[i][half * 4 + 1];
            r4.z = acc[i][half * 4 + 2];
            r4.w = acc[i][half * 4 + 3];
            *(float4*)(C + (size_t)gr * N + gc) = r4;
        }
    }
}

// ---------------- MMA flash attention (cp.async double-buffered KV) ----------------
// smem: Q tile 32KB (reused as KV stage B after fragment caching) + KV stage A 32KB = 64KB.
// KV stage layout: Kh(8KB) | Kl(8KB) | Vh(8KB) | Vl(8KB)
#define ATT_SMEM 65536

__global__ __launch_bounds__(256) void attn_mma_kernel(
    const __nv_bfloat16* __restrict__ Qh, const __nv_bfloat16* __restrict__ Ql,
    const __nv_bfloat16* __restrict__ Kp_h, const __nv_bfloat16* __restrict__ Kp_l,
    const __nv_bfloat16* __restrict__ Vh, const __nv_bfloat16* __restrict__ Vl,
    __nv_bfloat16* __restrict__ Oh, __nv_bfloat16* __restrict__ Ol,
    int qlen, int kvlen, int qstride, int kvstride)
{
    extern __shared__ char smc[];
    uint32_t sb = smem_to_u32(smc);
    int b = blockIdx.z, h = blockIdx.y, qt = blockIdx.x;
    int tid = threadIdx.x, warp = tid >> 5, lane = tid & 31;
    int qrow0 = qt * 128;
    size_t qbase  = ((size_t)b * qlen + qrow0) * qstride + h * DHEAD;
    size_t kvbase = ((size_t)b * kvlen) * kvstride + h * DHEAD;

    // Q tile into smem region [0, 32KB)
#pragma unroll
    for (int i = 0; i < 4; i++) {
        int idx = tid + i * 256;
        int r = idx >> 3, c = idx & 7;
        uint4 vh4 = *(const uint4*)(Qh + qbase + (size_t)r * qstride + c * 8);
        uint4 vl4 = *(const uint4*)(Ql + qbase + (size_t)r * qstride + c * 8);
        *(uint4*)(smc + att_sw(r, c)) = vh4;
        *(uint4*)(smc + 16384 + att_sw(r, c)) = vl4;
    }
    __syncthreads();

    // KV stage loader (zfill handles kv tail)
    auto load_kv = [&](uint32_t stoff, int kt) {
        uint32_t so = sb + stoff;
#pragma unroll
        for (int i = 0; i < 2; i++) {
            int idx = tid + i * 256;
            int r = idx >> 3, c = idx & 7;
            int kr = kt * 64 + r;
            int ok = (kr < kvlen);
            uint32_t sb16 = ok ? 16u : 0u;
            size_t off = kvbase + (size_t)(ok ? kr : 0) * kvstride + c * 8;
            uint32_t sw = att_sw(r, c);
            CP_ASYNC16Z(so + sw,         Kp_h + off, sb16);
            CP_ASYNC16Z(so + 8192 + sw,  Kp_l + off, sb16);
            CP_ASYNC16Z(so + 16384 + sw, Vh + off,   sb16);
            CP_ASYNC16Z(so + 24576 + sw, Vl + off,   sb16);
        }
        CP_COMMIT();
    };

    // first KV tile into stage at 32KB (doesn't overlap Q)
    load_kv(32768, 0);

    // cache Q fragments, freeing the Q region for use as stage B
    uint32_t qfh[4][4], qfl[4][4];
    {
        int r = warp * 16 + (lane & 15);
#pragma unroll
        for (int kk = 0; kk < 4; kk++) {
            int c = kk * 2 + (lane >> 4);
            LDSM_X4(qfh[kk][0], qfh[kk][1], qfh[kk][2], qfh[kk][3], sb + att_sw(r, c));
            LDSM_X4(qfl[kk][0], qfl[kk][1], qfl[kk][2], qfl[kk][3], sb + 16384 + att_sw(r, c));
        }
    }
    __syncthreads();   // all warps done reading Q before stage B (offset 0) can be written

    float m_a = -1e30f, m_b = -1e30f, l_a = 0.f, l_b = 0.f;
    float acc_o[8][4];
#pragma unroll
    for (int t = 0; t < 8; t++)
#pragma unroll
        for (int e = 0; e < 4; e++) acc_o[t][e] = 0.f;

    int ntiles = (kvlen + 63) >> 6;
    for (int kt = 0; kt < ntiles; kt++) {
        uint32_t stoff = (kt & 1) ? 0u : 32768u;       // kt=0 -> 32KB, kt=1 -> 0, ...
        if (kt + 1 < ntiles) {
            load_kv((kt & 1) ? 32768u : 0u, kt + 1);
            CP_WAIT1();
        } else {
            CP_WAIT0();
        }
        __syncthreads();

        uint32_t kh_s = sb + stoff;
        uint32_t kl_s = kh_s + 8192;
        uint32_t vh_s = kh_s + 16384;
        uint32_t vl_s = kh_s + 24576;

        float s[8][4];
#pragma unroll
        for (int t = 0; t < 8; t++)
#pragma unroll
            for (int e = 0; e < 4; e++) s[t][e] = 0.f;
#pragma unroll
        for (int kk = 0; kk < 4; kk++) {
#pragma unroll
            for (int nq = 0; nq < 4; nq++) {
                int r = nq * 16 + (lane & 15);
                int c = kk * 2 + (lane >> 4);
                uint32_t khf[4], klf[4];
                LDSM_X4(khf[0], khf[1], khf[2], khf[3], kh_s + att_sw(r, c));
                LDSM_X4(klf[0], klf[1], klf[2], klf[3], kl_s + att_sw(r, c));
                MMA16816(s[nq * 2 + 0], qfh[kk], khf[0], khf[2]);
                MMA16816(s[nq * 2 + 1], qfh[kk], khf[1], khf[3]);
                MMA16816(s[nq * 2 + 0], qfh[kk], klf[0], klf[2]);
                MMA16816(s[nq * 2 + 1], qfh[kk], klf[1], klf[3]);
                MMA16816(s[nq * 2 + 0], qfl[kk], khf[0], khf[2]);
                MMA16816(s[nq * 2 + 1], qfl[kk], khf[1], khf[3]);
            }
        }
        bool mtile = (kt == ntiles - 1) && (kvlen & 63);
#pragma unroll
        for (int t = 0; t < 8; t++)
#pragma unroll
            for (int e = 0; e < 4; e++) {
                float vv = s[t][e] * 0.125f;
                if (mtile) {
                    int col = kt * 64 + t * 8 + (lane & 3) * 2 + (e & 1);
                    if (col >= kvlen) vv = -1e30f;
                }
                s[t][e] = vv;
            }
        float mx_a = -1e30f, mx_b = -1e30f;
#pragma unroll
        for (int t = 0; t < 8; t++) {
            mx_a = fmaxf(mx_a, fmaxf(s[t][0], s[t][1]));
            mx_b = fmaxf(mx_b, fmaxf(s[t][2], s[t][3]));
        }
        mx_a = fmaxf(mx_a, __shfl_xor_sync(0xffffffffu, mx_a, 1));
        mx_a = fmaxf(mx_a, __shfl_xor_sync(0xffffffffu, mx_a, 2));
        mx_b = fmaxf(mx_b, __shfl_xor_sync(0xffffffffu, mx_b, 1));
        mx_b = fmaxf(mx_b, __shfl_xor_sync(0xffffffffu, mx_b, 2));
        float mn_a = fmaxf(m_a, mx_a), mn_b = fmaxf(m_b, mx_b);
        float al_a = __expf(m_a - mn_a), al_b = __expf(m_b - mn_b);
        m_a = mn_a; m_b = mn_b;
        float sum_a = 0.f, sum_b = 0.f;
#pragma unroll
        for (int t = 0; t < 8; t++) {
            s[t][0] = __expf(s[t][0] - m_a);
            s[t][1] = __expf(s[t][1] - m_a);
            s[t][2] = __expf(s[t][2] - m_b);
            s[t][3] = __expf(s[t][3] - m_b);
            sum_a += s[t][0] + s[t][1];
            sum_b += s[t][2] + s[t][3];
        }
        sum_a += __shfl_xor_sync(0xffffffffu, sum_a, 1);
        sum_a += __shfl_xor_sync(0xffffffffu, sum_a, 2);
        sum_b += __shfl_xor_sync(0xffffffffu, sum_b, 1);
        sum_b += __shfl_xor_sync(0xffffffffu, sum_b, 2);
        l_a = l_a * al_a + sum_a;
        l_b = l_b * al_b + sum_b;
#pragma unroll
        for (int t = 0; t < 8; t++) {
            acc_o[t][0] *= al_a; acc_o[t][1] *= al_a;
            acc_o[t][2] *= al_b; acc_o[t][3] *= al_b;
        }
#pragma unroll
        for (int kc = 0; kc < 4; kc++) {
            int t0 = kc * 2, t1 = t0 + 1;
            uint32_t pah[4], pal[4];
            {
                __nv_bfloat16 hb, lb, hb2, lb2;
                split_hilo(s[t0][0], hb, lb);  split_hilo(s[t0][1], hb2, lb2);
                pah[0] = pack_bf2(hb, hb2);    pal[0] = pack_bf2(lb, lb2);
                split_hilo(s[t0][2], hb, lb);  split_hilo(s[t0][3], hb2, lb2);
                pah[1] = pack_bf2(hb, hb2);    pal[1] = pack_bf2(lb, lb2);
                split_hilo(s[t1][0], hb, lb);  split_hilo(s[t1][1], hb2, lb2);
                pah[2] = pack_bf2(hb, hb2);    pal[2] = pack_bf2(lb, lb2);
                split_hilo(s[t1][2], hb, lb);  split_hilo(s[t1][3], hb2, lb2);
                pah[3] = pack_bf2(hb, hb2);    pal[3] = pack_bf2(lb, lb2);
            }
#pragma unroll
            for (int nd = 0; nd < 4; nd++) {
                int r = kc * 16 + (lane & 15);
                int c = nd * 2 + (lane >> 4);
                uint32_t vhf[4], vlf[4];
                LDSM_X4_TRANS(vhf[0], vhf[1], vhf[2], vhf[3], vh_s + att_sw(r, c));
                LDSM_X4_TRANS(vlf[0], vlf[1], vlf[2], vlf[3], vl_s + att_sw(r, c));
                MMA16816(acc_o[nd * 2 + 0], pah, vhf[0], vhf[1]);
                MMA16816(acc_o[nd * 2 + 1], pah, vhf[2], vhf[3]);
                MMA16816(acc_o[nd * 2 + 0], pah, vlf[0], vlf[1]);
                MMA16816(acc_o[nd * 2 + 1], pah, vlf[2], vlf[3]);
                MMA16816(acc_o[nd * 2 + 0], pal, vhf[0], vhf[1]);
                MMA16816(acc_o[nd * 2 + 1], pal, vhf[2], vhf[3]);
            }
        }
        __syncthreads();
    }

    float inv_a = 1.0f / l_a, inv_b = 1.0f / l_b;
    int row_a = qrow0 + warp * 16 + (lane >> 2);
    size_t ob = ((size_t)b * qlen) * DMODEL + h * DHEAD;
#pragma unroll
    for (int nd = 0; nd < 8; nd++) {
        int d0 = nd * 8 + (lane & 3) * 2;
        float a0 = acc_o[nd][0] * inv_a, a1 = acc_o[nd][1] * inv_a;
        float b0 = acc_o[nd][2] * inv_b, b1 = acc_o[nd][3] * inv_b;
        __nv_bfloat16 h0, l0, h1, l1;
        split_hilo(a0, h0, l0); split_hilo(a1, h1, l1);
        *(uint32_t*)(Oh + ob + (size_t)row_a * DMODEL + d0) = pack_bf2(h0, h1);
        *(uint32_t*)(Ol + ob + (size_t)row_a * DMODEL + d0) = pack_bf2(l0, l1);
        split_hilo(b0, h0, l0); split_hilo(b1, h1, l1);
        *(uint32_t*)(Oh + ob + (size_t)(row_a + 8) * DMODEL + d0) = pack_bf2(h0, h1);
        *(uint32_t*)(Ol + ob + (size_t)(row_a + 8) * DMODEL + d0) = pack_bf2(l0, l1);
    }
}

// ---------------- GeGLU (bf16 hi/lo in) + hi/lo emit ----------------
__global__ __launch_bounds__(256) void geglu_hilo_kernel(const __nv_bfloat16* __restrict__ Hh,
                                                         const __nv_bfloat16* __restrict__ Hl,
                                                         __nv_bfloat16* __restrict__ Ho,
                                                         __nv_bfloat16* __restrict__ Lo) {
    int row = blockIdx.y;
    int c = (blockIdx.x * 256 + threadIdx.x) * 4;
    size_t ubase = (size_t)row * FFH + c;
    size_t gbase = ubase + FFHALF;
    union { uint2 u; __nv_bfloat16 e[4]; } uh, ul, gh, gl;
    uh.u = *(const uint2*)(Hh + ubase);
    ul.u = *(const uint2*)(Hl + ubase);
    gh.u = *(const uint2*)(Hh + gbase);
    gl.u = *(const uint2*)(Hl + gbase);
    const float kc = 0.70710678118654752f;
    union { __nv_bfloat16 b[4]; uint2 uu; } ph, pl;
#pragma unroll
    for (int j = 0; j < 4; j++) {
        float u = __bfloat162float(uh.e[j]) + __bfloat162float(ul.e[j]);
        float g = __bfloat162float(gh.e[j]) + __bfloat162float(gl.e[j]);
        float r = u * (0.5f * g * (1.f + erff(g * kc)));
        split_hilo(r, ph.b[j], pl.b[j]);
    }
    size_t base = (size_t)row * FFHALF + c;
    *(uint2*)(Ho + base) = ph.uu;
    *(uint2*)(Lo + base) = pl.uu;
}

// ---------------- launch ----------------
extern "C" void kernel_launch(void* const* d_in, const int* in_sizes, int n_in,
                              void* d_out, int out_size) {
    const float* x    = (const float*)d_in[0];
    const float* ctx  = (const float*)d_in[1];
    const float* ln1g = (const float*)d_in[2];
    const float* ln1b = (const float*)d_in[3];
    const float* ln2g = (const float*)d_in[4];
    const float* ln2b = (const float*)d_in[5];
    const float* ln3g = (const float*)d_in[6];
    const float* ln3b = (const float*)d_in[7];
    const float* a1wq = (const float*)d_in[8];
    const float* a1wk = (const float*)d_in[9];
    const float* a1wv = (const float*)d_in[10];
    const float* a1wo = (const float*)d_in[11];
    const float* a1bo = (const float*)d_in[12];
    const float* a2wq = (const float*)d_in[13];
    const float* a2wk = (const float*)d_in[14];
    const float* a2wv = (const float*)d_in[15];
    const float* a2wo = (const float*)d_in[16];
    const float* a2bo = (const float*)d_in[17];
    const float* ffw1 = (const float*)d_in[18];
    const float* ffb1 = (const float*)d_in[19];
    const float* ffw2 = (const float*)d_in[20];
    const float* ffb2 = (const float*)d_in[21];
    float* out = (float*)d_out;

    float *xa, *ct1, *ct2;
    __nv_bfloat16 *hh, *hl, *ah, *al, *bh, *bl, *qkvh, *qkvl, *qh, *ql, *kh, *kl, *vh, *vl, *oh, *ol;
    cudaGetSymbolAddress((void**)&xa,   g_xa);
    cudaGetSymbolAddress((void**)&ct1,  g_ctmp1);
    cudaGetSymbolAddress((void**)&ct2,  g_ctmp2);
    cudaGetSymbolAddress((void**)&hh, g_hh);
    cudaGetSymbolAddress((void**)&hl, g_hl);
    cudaGetSymbolAddress((void**)&ah, g_ah);
    cudaGetSymbolAddress((void**)&al, g_al);
    cudaGetSymbolAddress((void**)&bh, g_bh);
    cudaGetSymbolAddress((void**)&bl, g_bl);
    cudaGetSymbolAddress((void**)&qkvh, g_qkvh);
    cudaGetSymbolAddress((void**)&qkvl, g_qkvl);
    cudaGetSymbolAddress((void**)&qh, g_qh);
    cudaGetSymbolAddress((void**)&ql, g_ql);
    cudaGetSymbolAddress((void**)&kh, g_kh);
    cudaGetSymbolAddress((void**)&kl, g_kl);
    cudaGetSymbolAddress((void**)&vh, g_vh);
    cudaGetSymbolAddress((void**)&vl, g_vl);
    cudaGetSymbolAddress((void**)&oh, g_oh);
    cudaGetSymbolAddress((void**)&ol, g_ol);

    cudaFuncSetAttribute(attn_mma_kernel, cudaFuncAttributeMaxDynamicSharedMemorySize, ATT_SMEM);
    cudaFuncSetAttribute(gemm_mma_kernel, cudaFuncAttributeMaxDynamicSharedMemorySize, GEMM_SMEM);

    dim3 blk(256);
    dim3 tblk(32, 8);
    dim3 tc1024(DMODEL / 128, MROWS / 128);          // (8, 64)
    dim3 tcQKV(QKVN / 128, MROWS / 128);             // (24, 64)
    dim3 tcFF1(FFH / 128, MROWS / 128);              // (64, 64)
    dim3 gemmCtx(DMODEL / 128, (CTXROWS + 127) / 128);
    dim3 attng(SEQ / 128, NHEAD, 4);
    dim3 tg1024(DMODEL / 32, DMODEL / 32);
    dim3 tgFF1(FFH / 32, DMODEL / 32);
    dim3 tgFF2(DMODEL / 32, FFHALF / 32);

    // --- self attention ---
    ln_hilo_kernel<<<MROWS, blk>>>(x, ln1g, ln1b, ah, al);
    tconv_kernel<<<tg1024, tblk>>>(a1wq, bh + OW_QKV_Q, bl + OW_QKV_Q, DMODEL, DMODEL);
    tconv_kernel<<<tg1024, tblk>>>(a1wk, bh + OW_QKV_K, bl + OW_QKV_K, DMODEL, DMODEL);
    tconv_kernel<<<tg1024, tblk>>>(a1wv, bh + OW_QKV_V, bl + OW_QKV_V, DMODEL, DMODEL);
    gemm_mma_kernel<<<tcQKV, blk, GEMM_SMEM>>>(ah, al, bh, bl, nullptr,
        MROWS, QKVN, DMODEL, nullptr, nullptr, qkvh, qkvl);
    tconv_kernel<<<tg1024, tblk>>>(a1wo, bh + OW_O1, bl + OW_O1, DMODEL, DMODEL);
    attn_mma_kernel<<<attng, blk, ATT_SMEM>>>(qkvh, qkvl,
        qkvh + DMODEL, qkvl + DMODEL, qkvh + 2 * DMODEL, qkvl + 2 * DMODEL,
        oh, ol, SEQ, SEQ, QKVN, QKVN);
    gemm_mma_kernel<<<tc1024, blk, GEMM_SMEM>>>(oh, ol, bh + OW_O1, bl + OW_O1, xa,
        MROWS, DMODEL, DMODEL, a1bo, x, nullptr, nullptr);

    // --- cross attention ---
    ln_hilo_kernel<<<MROWS, blk>>>(xa, ln2g, ln2b, ah, al);
    tconv_kernel<<<tg1024, tblk>>>(a2wq, bh, bl, DMODEL, DMODEL);
    gemm_mma_kernel<<<tc1024, blk, GEMM_SMEM>>>(ah, al, bh, bl, nullptr,
        MROWS, DMODEL, DMODEL, nullptr, nullptr, qh, ql);
    gemm_kernel<<<gemmCtx, blk>>>(ctx, a2wk, ct1, CTXROWS, DMODEL, CTXDIM);
    hilo_kernel<<<CTXROWS, blk>>>(ct1, kh, kl);
    gemm_kernel<<<gemmCtx, blk>>>(ctx, a2wv, ct2, CTXROWS, DMODEL, CTXDIM);
    hilo_kernel<<<CTXROWS, blk>>>(ct2, vh, vl);
    attn_mma_kernel<<<attng, blk, ATT_SMEM>>>(qh, ql, kh, kl, vh, vl,
        oh, ol, SEQ, CTXLEN, DMODEL, DMODEL);
    tconv_kernel<<<tg1024, tblk>>>(a2wo, bh, bl, DMODEL, DMODEL);
    gemm_mma_kernel<<<tc1024, blk, GEMM_SMEM>>>(oh, ol, bh, bl, xa,
        MROWS, DMODEL, DMODEL, a2bo, xa, nullptr, nullptr);

    // --- GeGLU feed-forward ---
    ln_hilo_kernel<<<MROWS, blk>>>(xa, ln3g, ln3b, ah, al);
    tconv_kernel<<<tgFF1, tblk>>>(ffw1, bh, bl, DMODEL, FFH);
    gemm_mma_kernel<<<tcFF1, blk, GEMM_SMEM>>>(ah, al, bh, bl, nullptr,
        MROWS, FFH, DMODEL, ffb1, nullptr, hh, hl);
    geglu_hilo_kernel<<<dim3(FFHALF / 1024, MROWS), blk>>>(hh, hl, ah, al);
    tconv_kernel<<<tgFF2, tblk>>>(ffw2, bh, bl, FFHALF, DMODEL);
    gemm_mma_kernel<<<tc1024, blk, GEMM_SMEM>>>(ah, al, bh, bl, out,
        MROWS, DMODEL, FFHALF, ffb2, xa, nullptr, nullptr);
}